// round 9
// baseline (speedup 1.0000x reference)
#include <cuda_runtime.h>
#include <cuda_bf16.h>
#include <cstdint>
#include <cstddef>

#define NN 50000
#define NE 800000
#define HID 256

// smem stage layout (bytes, pitch 80/row of 32 bf16 + pad):
// Ah[128x80]=10240 | Al=10240 | Bh[128x80]=10240 | Bl=10240
#define STAGE_B 40960

// ---------------- scratch (device globals: no allocation allowed) ----------------
__device__ __nv_bfloat16 g_ah[(size_t)NN * HID], g_al[(size_t)NN * HID];
__device__ float g_t[(size_t)NN * HID];                          // fp32 t (agg-only consumer)
__device__ __nv_bfloat16 g_gh[(size_t)NN * HID], g_gl[(size_t)NN * HID];
__device__ __nv_bfloat16 g_uh[(size_t)NN * HID], g_ul[(size_t)NN * HID];
__device__ int g_cnt[NN];
__device__ int g_rowptr[NN + 1];
__device__ int g_fill[NN];
__device__ int g_col[NE];
__device__ float g_cbt[256];         // b2@Wc + conv_b
__device__ float g_cbu[256];         // b2@P1 + post_b1
__device__ __nv_bfloat16 g_wth[256 * 256], g_wtl[256 * 256];   // t-GEMM weights
__device__ __nv_bfloat16 g_wuh[256 * 512], g_wul[256 * 512];   // u-GEMM weights

// ---------------- helpers ----------------
__device__ __forceinline__ uint32_t s2u(const void* p) {
    uint32_t a;
    asm("{ .reg .u64 t; cvta.to.shared.u64 t, %1; cvt.u32.u64 %0, t; }" : "=r"(a) : "l"(p));
    return a;
}
__device__ __forceinline__ void cp16(uint32_t dst, const void* src, int srcsz) {
    asm volatile("cp.async.cg.shared.global [%0], [%1], 16, %2;"
                 :: "r"(dst), "l"(src), "r"(srcsz) : "memory");
}
#define CP_COMMIT() asm volatile("cp.async.commit_group;" ::: "memory")

__device__ __forceinline__ void ldsm4(uint32_t& r0, uint32_t& r1, uint32_t& r2, uint32_t& r3,
                                      uint32_t addr) {
    asm volatile("ldmatrix.sync.aligned.m8n8.x4.shared.b16 {%0,%1,%2,%3}, [%4];"
                 : "=r"(r0), "=r"(r1), "=r"(r2), "=r"(r3) : "r"(addr));
}

#define MMA_BF16(cc, aa, b0v, b1v)                                              \
    asm volatile(                                                               \
        "mma.sync.aligned.m16n8k16.row.col.f32.bf16.bf16.f32 "                  \
        "{%0,%1,%2,%3}, {%4,%5,%6,%7}, {%8,%9}, {%0,%1,%2,%3};"                 \
        : "+f"(cc[0]), "+f"(cc[1]), "+f"(cc[2]), "+f"(cc[3])                    \
        : "r"(aa[0]), "r"(aa[1]), "r"(aa[2]), "r"(aa[3]), "r"(b0v), "r"(b1v))

__device__ __forceinline__ uint32_t pack_bf16x2(float a, float b) {
    __nv_bfloat162 p = __float22bfloat162_rn(make_float2(a, b));
    return *reinterpret_cast<uint32_t*>(&p);
}
__device__ __forceinline__ void split_pair(float v0, float v1, uint32_t& hw, uint32_t& lw) {
    float h0 = __bfloat162float(__float2bfloat16_rn(v0));
    float h1 = __bfloat162float(__float2bfloat16_rn(v1));
    hw = pack_bf16x2(h0, h1);
    lw = pack_bf16x2(v0 - h0, v1 - h1);
}

// ---------------- device: compose+prep+bias tile (bx in 0..3, by in 0..4) ------------
__device__ void compose_tile(int bx, int by, const float* __restrict__ A,
                             const float* __restrict__ B,
                             __nv_bfloat16* __restrict__ hi, __nv_bfloat16* __restrict__ lo,
                             int kpitch, int koff,
                             const float* __restrict__ b2, const float* __restrict__ badd,
                             float* __restrict__ bout)
{
    __shared__ float As[16][64];
    __shared__ float Bs[16][64];
    __shared__ float red[4][64];
    const int t = threadIdx.x;
    if (by == 4) {
        int j = bx * 64 + (t & 63);
        int ks = t >> 6;
        float acc = 0.f;
#pragma unroll 8
        for (int k = ks * 64; k < ks * 64 + 64; k++)
            acc += b2[k] * B[(size_t)k * 256 + j];
        red[ks][t & 63] = acc;
        __syncthreads();
        if (t < 64) {
            int jj = bx * 64 + t;
            bout[jj] = red[0][t] + red[1][t] + red[2][t] + red[3][t] + badd[jj];
        }
        return;
    }

    const int tx = t & 15, ty = t >> 4;
    const int m0 = by * 64, n0 = bx * 64;
    float acc[4][4];
#pragma unroll
    for (int i = 0; i < 4; i++)
#pragma unroll
        for (int j = 0; j < 4; j++) acc[i][j] = 0.f;

    for (int k0 = 0; k0 < 256; k0 += 16) {
#pragma unroll
        for (int i = 0; i < 4; i++) {
            int idx = t + i * 256;
            int r = idx >> 4, c = idx & 15;
            As[c][r] = A[(size_t)(m0 + r) * 256 + k0 + c];
        }
#pragma unroll
        for (int i = 0; i < 4; i++) {
            int idx = t + i * 256;
            int r = idx >> 6, c = idx & 63;
            Bs[r][c] = B[(size_t)(k0 + r) * 256 + n0 + c];
        }
        __syncthreads();
#pragma unroll
        for (int k = 0; k < 16; k++) {
            float ra[4], rb[4];
#pragma unroll
            for (int i = 0; i < 4; i++) ra[i] = As[k][ty * 4 + i];
#pragma unroll
            for (int j = 0; j < 4; j++) rb[j] = Bs[k][tx * 4 + j];
#pragma unroll
            for (int i = 0; i < 4; i++)
#pragma unroll
                for (int j = 0; j < 4; j++) acc[i][j] += ra[i] * rb[j];
        }
        __syncthreads();
    }
#pragma unroll
    for (int i = 0; i < 4; i++) {
        int kk = m0 + ty * 4 + i;
#pragma unroll
        for (int j = 0; j < 4; j++) {
            int nn = n0 + tx * 4 + j;
            float v = acc[i][j];
            __nv_bfloat16 h = __float2bfloat16_rn(v);
            hi[(size_t)nn * kpitch + koff + kk] = h;
            lo[(size_t)nn * kpitch + koff + kk] =
                __float2bfloat16_rn(v - __bfloat162float(h));
        }
    }
}

// ---------------- L1: setup = compose_t | compose_u | prep2(P2) | count --------------
__global__ __launch_bounds__(256) void setup_kernel(
    const float* __restrict__ pre_w2, const float* __restrict__ conv_w,
    const float* __restrict__ post_w1,
    const float* __restrict__ pre_b2, const float* __restrict__ conv_b,
    const float* __restrict__ post_b1,
    __nv_bfloat16* __restrict__ wth, __nv_bfloat16* __restrict__ wtl,
    __nv_bfloat16* __restrict__ wuh, __nv_bfloat16* __restrict__ wul,
    float* __restrict__ cbt, float* __restrict__ cbu,
    const int* __restrict__ dst, int* __restrict__ cnt)
{
    const int bid = blockIdx.x;
    const float* P1 = post_w1;
    const float* P2 = post_w1 + 256 * 256;
    if (bid < 20) {
        compose_tile(bid & 3, bid >> 2, pre_w2, conv_w, wth, wtl, 256, 0,
                     pre_b2, conv_b, cbt);
    } else if (bid < 40) {
        int b = bid - 20;
        compose_tile(b & 3, b >> 2, pre_w2, P1, wuh, wul, 512, 0,
                     pre_b2, post_b1, cbu);
    } else if (bid < 104) {
        __shared__ float tile[32][33];
        int lb = bid - 40;
        int k0 = (lb >> 3) * 32, n0 = (lb & 7) * 32;
        int tx = threadIdx.x & 31, ty = threadIdx.x >> 5;  // 32 x 8
        for (int i = ty; i < 32; i += 8)
            tile[i][tx] = P2[(size_t)(k0 + i) * 256 + n0 + tx];
        __syncthreads();
        for (int i = ty; i < 32; i += 8) {
            float v = tile[tx][i];
            __nv_bfloat16 h = __float2bfloat16_rn(v);
            wuh[(size_t)(n0 + i) * 512 + 256 + k0 + tx] = h;
            wul[(size_t)(n0 + i) * 512 + 256 + k0 + tx] =
                __float2bfloat16_rn(v - __bfloat162float(h));
        }
    } else {
        int e = (bid - 104) * 256 + threadIdx.x;
        if (e < NE) atomicAdd(&cnt[dst[e]], 1);
    }
}

// ---------------- L2: pre (blocks 1..391) | scan (block 0), 1024 threads -------------
__global__ __launch_bounds__(1024) void pre_scan_kernel(
    const float* __restrict__ x, const float* __restrict__ w1, const float* __restrict__ b1,
    __nv_bfloat16* __restrict__ Ch, __nv_bfloat16* __restrict__ Cl,
    const int* __restrict__ cnt, int* __restrict__ rowptr, int* __restrict__ fill)
{
    const int tid = threadIdx.x, lane = tid & 31, warp = tid >> 5;
    if (blockIdx.x == 0) {
        __shared__ int wsum[32];
        __shared__ int s_carry;
        if (tid == 0) { s_carry = 0; rowptr[0] = 0; }
        __syncthreads();
        for (int base = 0; base < NN; base += 1024) {
            int i = base + tid;
            int v = (i < NN) ? cnt[i] : 0;
            int s = v;
#pragma unroll
            for (int d = 1; d < 32; d <<= 1) {
                int y = __shfl_up_sync(0xffffffffu, s, d);
                if (lane >= d) s += y;
            }
            if (lane == 31) wsum[warp] = s;
            int carry_in = s_carry;
            __syncthreads();
            if (warp == 0) {
                int ws = wsum[lane];
#pragma unroll
                for (int d = 1; d < 32; d <<= 1) {
                    int y = __shfl_up_sync(0xffffffffu, ws, d);
                    if (lane >= d) ws += y;
                }
                wsum[lane] = ws;
            }
            __syncthreads();
            int off = (warp ? wsum[warp - 1] : 0) + carry_in;
            int inc = s + off;
            if (i < NN) {
                rowptr[i + 1] = inc;
                fill[i] = inc - v;
            }
            __syncthreads();
            if (tid == 1023) s_carry = inc;
            __syncthreads();
        }
        return;
    }

    // pre-MLP layer 1: 128 rows per block, 32 warps x 4 rows
    __shared__ float ws[16 * 256];
    __shared__ float bs[256];
    ((float4*)ws)[tid] = ((const float4*)w1)[tid];
    if (tid < 256) bs[tid] = b1[tid];
    __syncthreads();

    const int rb = (blockIdx.x - 1) * 128;
#pragma unroll
    for (int r = 0; r < 4; r++) {
        int row = rb + warp * 4 + r;
        if (row >= NN) break;
        float xv[16];
        const float4* xp = (const float4*)(x + (size_t)row * 16);
#pragma unroll
        for (int q = 0; q < 4; q++) *(float4*)&xv[q * 4] = xp[q];
        float acc[8];
#pragma unroll
        for (int j = 0; j < 8; j++) acc[j] = bs[lane + 32 * j];
#pragma unroll
        for (int k = 0; k < 16; k++) {
            float xk = xv[k];
            const float* wr = &ws[k * 256 + lane];
#pragma unroll
            for (int j = 0; j < 8; j++) acc[j] += xk * wr[32 * j];
        }
#pragma unroll
        for (int j = 0; j < 8; j++) {
            float v = fmaxf(acc[j], 0.f);
            __nv_bfloat16 h = __float2bfloat16_rn(v);
            Ch[(size_t)row * 256 + lane + 32 * j] = h;
            Cl[(size_t)row * 256 + lane + 32 * j] =
                __float2bfloat16_rn(v - __bfloat162float(h));
        }
    }
}

// ---------------- device: tensor-core GEMM body ----------------
// OUTF32: write fp32 C (for t). Otherwise write hi/lo bf16 pair.
template <int ACT, int OUTF32>
__device__ void gemm_body(
    int nb, int mb, char* smc,
    const __nv_bfloat16* __restrict__ A1h, const __nv_bfloat16* __restrict__ A1l,
    const __nv_bfloat16* __restrict__ A2h, const __nv_bfloat16* __restrict__ A2l,
    const __nv_bfloat16* __restrict__ Wh,  const __nv_bfloat16* __restrict__ Wl,
    const float* __restrict__ bias,
    __nv_bfloat16* __restrict__ Ch, __nv_bfloat16* __restrict__ Cl,
    float* __restrict__ Cf,
    int M, int K, int K1)
{
    __shared__ float sbias[128];

    const int tid = threadIdx.x;
    const int wid = tid >> 5, lane = tid & 31;
    const int g = lane >> 2, tg = lane & 3;
    const int wm = wid >> 1, wn = wid & 1;
    const int m0 = mb * 128, n0 = nb * 128;
    const uint32_t smc_u = s2u(smc);

    if (tid < 128) sbias[tid] = bias[n0 + tid];

    const int arow = tid >> 1;
    const int aks  = (tid & 1) * 16;
    const int gm   = m0 + arow;
    const int okA  = (gm < M) ? 16 : 0;

    const int q = lane >> 3, rr = lane & 7;
    const uint32_t aoff0 = (uint32_t)((wm * 32 + (q & 1) * 8 + rr) * 80 + (q >> 1) * 16);
    const uint32_t boff0 = (uint32_t)(20480 + (wn * 64 + (q >> 1) * 8 + rr) * 80 + (q & 1) * 16);

    float acc[2][8][4];
#pragma unroll
    for (int i = 0; i < 2; i++)
#pragma unroll
        for (int j = 0; j < 8; j++)
#pragma unroll
            for (int p = 0; p < 4; p++) acc[i][j][p] = 0.f;

    const int NC = K >> 5;

    auto STAGE = [&](int c) {
        const int ck = c * 32;
        const __nv_bfloat16 *Ah, *Al; int lda, kof;
        if (ck < K1) { Ah = A1h; Al = A1l; lda = K1;     kof = ck; }
        else         { Ah = A2h; Al = A2l; lda = K - K1; kof = ck - K1; }
        const uint32_t sb = smc_u + (uint32_t)((c & 1) * STAGE_B);
        const uint32_t da = sb + (uint32_t)(arow * 80 + (tid & 1) * 32);
        const __nv_bfloat16* pah = Ah + (size_t)gm * lda + kof + aks;
        const __nv_bfloat16* pal = Al + (size_t)gm * lda + kof + aks;
        cp16(da, pah, okA);               cp16(da + 16, pah + 8, okA);
        cp16(da + 10240, pal, okA);       cp16(da + 10240 + 16, pal + 8, okA);
        const __nv_bfloat16* pbh = Wh + (size_t)(n0 + arow) * K + ck + aks;
        const __nv_bfloat16* pbl = Wl + (size_t)(n0 + arow) * K + ck + aks;
        cp16(da + 20480, pbh, 16);        cp16(da + 20480 + 16, pbh + 8, 16);
        cp16(da + 30720, pbl, 16);        cp16(da + 30720 + 16, pbl + 8, 16);
        CP_COMMIT();
    };

    STAGE(0);

    for (int c = 0; c < NC; c++) {
        if (c + 1 < NC) {
            STAGE(c + 1);
            asm volatile("cp.async.wait_group 1;" ::: "memory");
        } else {
            asm volatile("cp.async.wait_group 0;" ::: "memory");
        }
        __syncthreads();

        const uint32_t sb = smc_u + (uint32_t)((c & 1) * STAGE_B);
#pragma unroll
        for (int ks = 0; ks < 2; ks++) {
            const uint32_t ko = (uint32_t)(ks * 32);
            uint32_t ah[2][4], bb[8][2];
            ldsm4(ah[0][0], ah[0][1], ah[0][2], ah[0][3], sb + aoff0 + ko);
            ldsm4(ah[1][0], ah[1][1], ah[1][2], ah[1][3], sb + aoff0 + 1280 + ko);
#pragma unroll
            for (int jp = 0; jp < 4; jp++)
                ldsm4(bb[2 * jp][0], bb[2 * jp][1], bb[2 * jp + 1][0], bb[2 * jp + 1][1],
                      sb + boff0 + (uint32_t)(jp * 1280) + ko);
#pragma unroll
            for (int i = 0; i < 2; i++)
#pragma unroll
                for (int j = 0; j < 8; j++) MMA_BF16(acc[i][j], ah[i], bb[j][0], bb[j][1]);

            uint32_t al[2][4];
            ldsm4(al[0][0], al[0][1], al[0][2], al[0][3], sb + 10240 + aoff0 + ko);
            ldsm4(al[1][0], al[1][1], al[1][2], al[1][3], sb + 10240 + aoff0 + 1280 + ko);
#pragma unroll
            for (int i = 0; i < 2; i++)
#pragma unroll
                for (int j = 0; j < 8; j++) MMA_BF16(acc[i][j], al[i], bb[j][0], bb[j][1]);

#pragma unroll
            for (int jp = 0; jp < 4; jp++)
                ldsm4(bb[2 * jp][0], bb[2 * jp][1], bb[2 * jp + 1][0], bb[2 * jp + 1][1],
                      sb + 10240 + boff0 + (uint32_t)(jp * 1280) + ko);
#pragma unroll
            for (int i = 0; i < 2; i++)
#pragma unroll
                for (int j = 0; j < 8; j++) MMA_BF16(acc[i][j], ah[i], bb[j][0], bb[j][1]);
        }
        __syncthreads();
    }

    // epilogue: bias + activation + store
#pragma unroll
    for (int i = 0; i < 2; i++) {
        int r0 = m0 + wm * 32 + i * 16 + g;
#pragma unroll
        for (int j = 0; j < 8; j++) {
            int cl = wn * 64 + j * 8 + tg * 2;
            float b0 = sbias[cl], b1 = sbias[cl + 1];
            float v0 = acc[i][j][0] + b0, v1 = acc[i][j][1] + b1;
            float v2 = acc[i][j][2] + b0, v3 = acc[i][j][3] + b1;
            if (ACT == 1) {
                v0 = fmaxf(v0, 0.f); v1 = fmaxf(v1, 0.f);
                v2 = fmaxf(v2, 0.f); v3 = fmaxf(v3, 0.f);
            }
            if (OUTF32) {
                if (r0 < M)
                    *(float2*)(Cf + (size_t)r0 * 256 + n0 + cl) = make_float2(v0, v1);
                if (r0 + 8 < M)
                    *(float2*)(Cf + (size_t)(r0 + 8) * 256 + n0 + cl) = make_float2(v2, v3);
            } else {
                uint32_t hw, lw;
                if (r0 < M) {
                    split_pair(v0, v1, hw, lw);
                    *(uint32_t*)(Ch + (size_t)r0 * 256 + n0 + cl) = hw;
                    *(uint32_t*)(Cl + (size_t)r0 * 256 + n0 + cl) = lw;
                }
                if (r0 + 8 < M) {
                    split_pair(v2, v3, hw, lw);
                    *(uint32_t*)(Ch + (size_t)(r0 + 8) * 256 + n0 + cl) = hw;
                    *(uint32_t*)(Cl + (size_t)(r0 + 8) * 256 + n0 + cl) = lw;
                }
            }
        }
    }
}

#define GEMM_BLKS 782  // 2 x 391

// ---------------- L3: t-GEMM (fp32 out) ----------------
__global__ __launch_bounds__(256, 2) void tgemm_kernel(
    const __nv_bfloat16* __restrict__ ah, const __nv_bfloat16* __restrict__ al,
    const __nv_bfloat16* __restrict__ wth, const __nv_bfloat16* __restrict__ wtl,
    const float* __restrict__ cbt, float* __restrict__ t)
{
    extern __shared__ char smc[];
    const int bid = blockIdx.x;
    gemm_body<1, 1>(bid & 1, bid >> 1, smc, ah, al, nullptr, nullptr,
                    wth, wtl, cbt, nullptr, nullptr, t, NN, 256, 256);
}

// ---------------- L3b: scatter ----------------
__global__ void scatter_kernel(const int* __restrict__ src, const int* __restrict__ dst,
                               int* __restrict__ fill, int* __restrict__ col) {
    int e = blockIdx.x * blockDim.x + threadIdx.x;
    if (e < NE) {
        int slot = atomicAdd(&fill[dst[e]], 1);
        col[slot] = src[e];
    }
}

// ---------------- L5: u-GEMM (bf16 pair out) ----------------
__global__ __launch_bounds__(256, 2) void ugemm_kernel(
    const __nv_bfloat16* __restrict__ ah, const __nv_bfloat16* __restrict__ al,
    const __nv_bfloat16* __restrict__ gh, const __nv_bfloat16* __restrict__ gl,
    const __nv_bfloat16* __restrict__ wuh, const __nv_bfloat16* __restrict__ wul,
    const float* __restrict__ cbu,
    __nv_bfloat16* __restrict__ uh, __nv_bfloat16* __restrict__ ul)
{
    extern __shared__ char smc[];
    const int bid = blockIdx.x;
    gemm_body<1, 0>(bid & 1, bid >> 1, smc, ah, al, gh, gl,
                    wuh, wul, cbu, uh, ul, nullptr, NN, 512, 256);
}

// ---------------- L4: aggregation — fp32 t gather (4 nodes/block, 1 warp each) -------
__global__ __launch_bounds__(128) void agg_kernel(
    const float* __restrict__ t,
    const int* __restrict__ rowptr, const int* __restrict__ col,
    __nv_bfloat16* __restrict__ aggh, __nv_bfloat16* __restrict__ aggl)
{
    const int node = blockIdx.x * 4 + (threadIdx.x >> 5);
    if (node >= NN) return;
    const int tid = threadIdx.x & 31;
    const int s = rowptr[node];
    const int e = rowptr[node + 1];
    float4 a0 = make_float4(0.f, 0.f, 0.f, 0.f);
    float4 a1 = make_float4(0.f, 0.f, 0.f, 0.f);

    int i = s;
    for (; i + 4 <= e; i += 4) {
        int c0 = __ldg(&col[i]),     c1 = __ldg(&col[i + 1]);
        int c2 = __ldg(&col[i + 2]), c3 = __ldg(&col[i + 3]);
        const float4* p0 = (const float4*)(t + (size_t)c0 * HID + tid * 8);
        const float4* p1 = (const float4*)(t + (size_t)c1 * HID + tid * 8);
        const float4* p2 = (const float4*)(t + (size_t)c2 * HID + tid * 8);
        const float4* p3 = (const float4*)(t + (size_t)c3 * HID + tid * 8);
        float4 v00 = p0[0], v01 = p0[1];
        float4 v10 = p1[0], v11 = p1[1];
        float4 v20 = p2[0], v21 = p2[1];
        float4 v30 = p3[0], v31 = p3[1];
        a0.x += v00.x + v10.x + v20.x + v30.x;
        a0.y += v00.y + v10.y + v20.y + v30.y;
        a0.z += v00.z + v10.z + v20.z + v30.z;
        a0.w += v00.w + v10.w + v20.w + v30.w;
        a1.x += v01.x + v11.x + v21.x + v31.x;
        a1.y += v01.y + v11.y + v21.y + v31.y;
        a1.z += v01.z + v11.z + v21.z + v31.z;
        a1.w += v01.w + v11.w + v21.w + v31.w;
    }
    for (; i < e; i++) {
        int c0 = __ldg(&col[i]);
        const float4* p0 = (const float4*)(t + (size_t)c0 * HID + tid * 8);
        float4 v0 = p0[0], v1 = p0[1];
        a0.x += v0.x; a0.y += v0.y; a0.z += v0.z; a0.w += v0.w;
        a1.x += v1.x; a1.y += v1.y; a1.z += v1.z; a1.w += v1.w;
    }

    uint32_t hw[4], lw[4];
    split_pair(a0.x, a0.y, hw[0], lw[0]);
    split_pair(a0.z, a0.w, hw[1], lw[1]);
    split_pair(a1.x, a1.y, hw[2], lw[2]);
    split_pair(a1.z, a1.w, hw[3], lw[3]);
    *(uint4*)(aggh + (size_t)node * HID + tid * 8) = *(uint4*)hw;
    *(uint4*)(aggl + (size_t)node * HID + tid * 8) = *(uint4*)lw;
}

// ---------------- L6: output projection ----------------
__global__ __launch_bounds__(256) void out_kernel(
    const __nv_bfloat16* __restrict__ uh, const __nv_bfloat16* __restrict__ ul,
    const float* __restrict__ w, const float* __restrict__ b,
    float* __restrict__ out, int M)
{
    __shared__ float ws[256 * 16];
    __shared__ float bs[16];
    const int tid = threadIdx.x;
    for (int i = tid; i < 256 * 16 / 4; i += 256)
        ((float4*)ws)[i] = ((const float4*)w)[i];
    if (tid < 16) bs[tid] = b[tid];
    __syncthreads();

    const int mloc = tid >> 1;
    const int off  = (tid & 1) * 8;
    const int m = blockIdx.x * 128 + mloc;
    if (m >= M) return;

    float acc[8];
#pragma unroll
    for (int j = 0; j < 8; j++) acc[j] = bs[off + j];

    const uint4* ph = (const uint4*)(uh + (size_t)m * HID);
    const uint4* pl = (const uint4*)(ul + (size_t)m * HID);
#pragma unroll 4
    for (int kc = 0; kc < 32; kc++) {
        uint4 hv = ph[kc], lv = pl[kc];
        const uint32_t* hp = (const uint32_t*)&hv;
        const uint32_t* lp = (const uint32_t*)&lv;
        float f[8];
#pragma unroll
        for (int p = 0; p < 4; p++) {
            __nv_bfloat162 h2 = *reinterpret_cast<const __nv_bfloat162*>(&hp[p]);
            __nv_bfloat162 l2 = *reinterpret_cast<const __nv_bfloat162*>(&lp[p]);
            f[2 * p]     = __low2float(h2)  + __low2float(l2);
            f[2 * p + 1] = __high2float(h2) + __high2float(l2);
        }
#pragma unroll
        for (int qv = 0; qv < 8; qv++) {
            const float* wr = &ws[(kc * 8 + qv) * 16 + off];
#pragma unroll
            for (int j = 0; j < 8; j++) acc[j] += f[qv] * wr[j];
        }
    }
    float o[8];
#pragma unroll
    for (int j = 0; j < 8; j++) o[j] = tanhf(acc[j]);
    float* op = out + (size_t)m * 16 + off;
    *(float4*)(op)     = *(float4*)&o[0];
    *(float4*)(op + 4) = *(float4*)&o[4];
}

// ---------------- launcher ----------------
extern "C" void kernel_launch(void* const* d_in, const int* in_sizes, int n_in,
                              void* d_out, int out_size) {
    const float* x       = (const float*)d_in[0];
    const int*   ei      = (const int*)d_in[1];
    const float* pre_w1  = (const float*)d_in[2];
    const float* pre_b1  = (const float*)d_in[3];
    const float* pre_w2  = (const float*)d_in[4];
    const float* pre_b2  = (const float*)d_in[5];
    const float* conv_w  = (const float*)d_in[6];
    const float* conv_b  = (const float*)d_in[7];
    const float* post_w1 = (const float*)d_in[8];
    const float* post_b1 = (const float*)d_in[9];
    const float* post_w2 = (const float*)d_in[10];
    const float* post_b2 = (const float*)d_in[11];
    float* out = (float*)d_out;

    const int* src = ei;
    const int* dst = ei + NE;

    __nv_bfloat16 *ah, *al, *gh, *gl, *uh, *ul;
    float* t;
    int *cnt, *rowptr, *fill, *col;
    float *cbt, *cbu;
    __nv_bfloat16 *wth, *wtl, *wuh, *wul;
    cudaGetSymbolAddress((void**)&ah, g_ah);   cudaGetSymbolAddress((void**)&al, g_al);
    cudaGetSymbolAddress((void**)&t, g_t);
    cudaGetSymbolAddress((void**)&gh, g_gh);   cudaGetSymbolAddress((void**)&gl, g_gl);
    cudaGetSymbolAddress((void**)&uh, g_uh);   cudaGetSymbolAddress((void**)&ul, g_ul);
    cudaGetSymbolAddress((void**)&cnt, g_cnt);
    cudaGetSymbolAddress((void**)&rowptr, g_rowptr);
    cudaGetSymbolAddress((void**)&fill, g_fill);
    cudaGetSymbolAddress((void**)&col, g_col);
    cudaGetSymbolAddress((void**)&cbt, g_cbt); cudaGetSymbolAddress((void**)&cbu, g_cbu);
    cudaGetSymbolAddress((void**)&wth, g_wth); cudaGetSymbolAddress((void**)&wtl, g_wtl);
    cudaGetSymbolAddress((void**)&wuh, g_wuh); cudaGetSymbolAddress((void**)&wul, g_wul);

    const int DSMEM = 2 * STAGE_B;  // 80 KB
    cudaFuncSetAttribute(tgemm_kernel, cudaFuncAttributeMaxDynamicSharedMemorySize, DSMEM);
    cudaFuncSetAttribute(ugemm_kernel, cudaFuncAttributeMaxDynamicSharedMemorySize, DSMEM);

    cudaMemsetAsync(cnt, 0, NN * sizeof(int), 0);

    // L1: compose_t(20) | compose_u(20) | prep2(64) | count(3125)
    setup_kernel<<<104 + 3125, 256>>>(pre_w2, conv_w, post_w1, pre_b2, conv_b, post_b1,
                                      wth, wtl, wuh, wul, cbt, cbu, dst, cnt);
    // L2: scan(1) | pre-MLP(391)
    pre_scan_kernel<<<392, 1024>>>(x, pre_w1, pre_b1, ah, al, cnt, rowptr, fill);
    // L3: t = relu(a@Wt + bt) -> fp32
    tgemm_kernel<<<GEMM_BLKS, 256, DSMEM>>>(ah, al, wth, wtl, cbt, t);
    // L3b: scatter (own launch: full occupancy, no smem reservation)
    scatter_kernel<<<(NE + 255) / 256, 256>>>(src, dst, fill, col);
    // L4: aggregation (fp32 gather)
    agg_kernel<<<(NN + 3) / 4, 128>>>(t, rowptr, col, gh, gl);
    // L5: u = relu(a@Wp + agg@P2 + bu)
    ugemm_kernel<<<GEMM_BLKS, 256, DSMEM>>>(ah, al, gh, gl, wuh, wul, cbu, uh, ul);
    // L6: out = tanh(u@post_w2 + post_b2)
    out_kernel<<<(NN + 127) / 128, 256>>>(uh, ul, post_w2, post_b2, out, NN);
}

// round 10
// speedup vs baseline: 1.2143x; 1.2143x over previous
#include <cuda_runtime.h>
#include <cuda_bf16.h>
#include <cstdint>
#include <cstddef>

#define NN 50000
#define NE 800000
#define HID 256

// smem stage layout (bytes, pitch 80/row of 32 bf16 + pad):
// Ah[128x80]=10240 | Al=10240 | Bh[128x80]=10240 | Bl=10240
#define STAGE_B 40960

// ---------------- scratch (device globals: no allocation allowed) ----------------
__device__ __nv_bfloat16 g_ah[(size_t)NN * HID], g_al[(size_t)NN * HID];
__device__ float g_t[(size_t)NN * HID];                          // fp32 t (agg-only consumer)
__device__ __nv_bfloat16 g_gh[(size_t)NN * HID], g_gl[(size_t)NN * HID];
__device__ __nv_bfloat16 g_uh[(size_t)NN * HID], g_ul[(size_t)NN * HID];
__device__ int g_cnt[NN];
__device__ int g_rowptr[NN + 1];
__device__ int g_fill[NN];
__device__ int g_col[NE];
__device__ float g_cbt[256];         // b2@Wc + conv_b
__device__ float g_cbu[256];         // b2@P1 + post_b1
__device__ __nv_bfloat16 g_wth[256 * 256], g_wtl[256 * 256];   // t-GEMM weights
__device__ __nv_bfloat16 g_wuh[256 * 512], g_wul[256 * 512];   // u-GEMM weights

// ---------------- helpers ----------------
__device__ __forceinline__ uint32_t s2u(const void* p) {
    uint32_t a;
    asm("{ .reg .u64 t; cvta.to.shared.u64 t, %1; cvt.u32.u64 %0, t; }" : "=r"(a) : "l"(p));
    return a;
}
__device__ __forceinline__ void cp16(uint32_t dst, const void* src, int srcsz) {
    asm volatile("cp.async.cg.shared.global [%0], [%1], 16, %2;"
                 :: "r"(dst), "l"(src), "r"(srcsz) : "memory");
}
#define CP_COMMIT() asm volatile("cp.async.commit_group;" ::: "memory")

__device__ __forceinline__ void ldsm4(uint32_t& r0, uint32_t& r1, uint32_t& r2, uint32_t& r3,
                                      uint32_t addr) {
    asm volatile("ldmatrix.sync.aligned.m8n8.x4.shared.b16 {%0,%1,%2,%3}, [%4];"
                 : "=r"(r0), "=r"(r1), "=r"(r2), "=r"(r3) : "r"(addr));
}

#define MMA_BF16(cc, aa, b0v, b1v)                                              \
    asm volatile(                                                               \
        "mma.sync.aligned.m16n8k16.row.col.f32.bf16.bf16.f32 "                  \
        "{%0,%1,%2,%3}, {%4,%5,%6,%7}, {%8,%9}, {%0,%1,%2,%3};"                 \
        : "+f"(cc[0]), "+f"(cc[1]), "+f"(cc[2]), "+f"(cc[3])                    \
        : "r"(aa[0]), "r"(aa[1]), "r"(aa[2]), "r"(aa[3]), "r"(b0v), "r"(b1v))

__device__ __forceinline__ uint32_t pack_bf16x2(float a, float b) {
    __nv_bfloat162 p = __float22bfloat162_rn(make_float2(a, b));
    return *reinterpret_cast<uint32_t*>(&p);
}
__device__ __forceinline__ void split_pair(float v0, float v1, uint32_t& hw, uint32_t& lw) {
    float h0 = __bfloat162float(__float2bfloat16_rn(v0));
    float h1 = __bfloat162float(__float2bfloat16_rn(v1));
    hw = pack_bf16x2(h0, h1);
    lw = pack_bf16x2(v0 - h0, v1 - h1);
}

// ---------------- fused compose+prep+bias ----------------
// by<4: hi/lo[n][koff+k] = split((A@B)[k][n]).   by==4: bout = b2@B + badd.
__global__ __launch_bounds__(256) void compose_prep(
    const float* __restrict__ A, const float* __restrict__ B,
    __nv_bfloat16* __restrict__ hi, __nv_bfloat16* __restrict__ lo,
    int kpitch, int koff,
    const float* __restrict__ b2, const float* __restrict__ badd,
    float* __restrict__ bout)
{
    const int t = threadIdx.x;
    if (blockIdx.y == 4) {
        __shared__ float red[4][64];
        int j = blockIdx.x * 64 + (t & 63);
        int ks = t >> 6;
        float acc = 0.f;
#pragma unroll 8
        for (int k = ks * 64; k < ks * 64 + 64; k++)
            acc += b2[k] * B[(size_t)k * 256 + j];
        red[ks][t & 63] = acc;
        __syncthreads();
        if (t < 64) {
            int jj = blockIdx.x * 64 + t;
            bout[jj] = red[0][t] + red[1][t] + red[2][t] + red[3][t] + badd[jj];
        }
        return;
    }

    __shared__ float As[16][64];
    __shared__ float Bs[16][64];
    const int tx = t & 15, ty = t >> 4;
    const int m0 = blockIdx.y * 64, n0 = blockIdx.x * 64;
    float acc[4][4];
#pragma unroll
    for (int i = 0; i < 4; i++)
#pragma unroll
        for (int j = 0; j < 4; j++) acc[i][j] = 0.f;

    for (int k0 = 0; k0 < 256; k0 += 16) {
#pragma unroll
        for (int i = 0; i < 4; i++) {
            int idx = t + i * 256;
            int r = idx >> 4, c = idx & 15;
            As[c][r] = A[(size_t)(m0 + r) * 256 + k0 + c];
        }
#pragma unroll
        for (int i = 0; i < 4; i++) {
            int idx = t + i * 256;
            int r = idx >> 6, c = idx & 63;
            Bs[r][c] = B[(size_t)(k0 + r) * 256 + n0 + c];
        }
        __syncthreads();
#pragma unroll
        for (int k = 0; k < 16; k++) {
            float ra[4], rb[4];
#pragma unroll
            for (int i = 0; i < 4; i++) ra[i] = As[k][ty * 4 + i];
#pragma unroll
            for (int j = 0; j < 4; j++) rb[j] = Bs[k][tx * 4 + j];
#pragma unroll
            for (int i = 0; i < 4; i++)
#pragma unroll
                for (int j = 0; j < 4; j++) acc[i][j] += ra[i] * rb[j];
        }
        __syncthreads();
    }
#pragma unroll
    for (int i = 0; i < 4; i++) {
        int kk = m0 + ty * 4 + i;
#pragma unroll
        for (int j = 0; j < 4; j++) {
            int nn = n0 + tx * 4 + j;
            float v = acc[i][j];
            __nv_bfloat16 h = __float2bfloat16_rn(v);
            hi[(size_t)nn * kpitch + koff + kk] = h;
            lo[(size_t)nn * kpitch + koff + kk] =
                __float2bfloat16_rn(v - __bfloat162float(h));
        }
    }
}

// ---------------- prep (transpose + split only, for P2) ----------------
__global__ void prep2(const float* __restrict__ W, __nv_bfloat16* __restrict__ hi,
                      __nv_bfloat16* __restrict__ lo, int kpitch, int koff) {
    __shared__ float tile[32][33];
    int k0 = blockIdx.y * 32, n0 = blockIdx.x * 32;
    int tx = threadIdx.x, ty = threadIdx.y;  // 32 x 8
    for (int i = ty; i < 32; i += 8) tile[i][tx] = W[(size_t)(k0 + i) * 256 + n0 + tx];
    __syncthreads();
    for (int i = ty; i < 32; i += 8) {
        float v = tile[tx][i];
        __nv_bfloat16 h = __float2bfloat16_rn(v);
        hi[(size_t)(n0 + i) * kpitch + koff + k0 + tx] = h;
        lo[(size_t)(n0 + i) * kpitch + koff + k0 + tx] =
            __float2bfloat16_rn(v - __bfloat162float(h));
    }
}

// ---------------- pre-MLP layer 1: a = relu(x@w1+b1), K=16, hi/lo out ---------------
__global__ __launch_bounds__(256) void pre_kernel(
    const float* __restrict__ x, const float* __restrict__ w1, const float* __restrict__ b1,
    __nv_bfloat16* __restrict__ Ch, __nv_bfloat16* __restrict__ Cl)
{
    __shared__ float ws[16 * 256];
    __shared__ float bs[256];
    const int tid = threadIdx.x;
    for (int i = tid; i < 1024; i += 256) ((float4*)ws)[i] = ((const float4*)w1)[i];
    bs[tid] = b1[tid];
    __syncthreads();

    const int warp = tid >> 5, lane = tid & 31;
#pragma unroll
    for (int r = 0; r < 4; r++) {
        int row = blockIdx.x * 32 + warp * 4 + r;
        if (row >= NN) break;
        float xv[16];
        const float4* xp = (const float4*)(x + (size_t)row * 16);
#pragma unroll
        for (int q = 0; q < 4; q++) *(float4*)&xv[q * 4] = xp[q];
        float acc[8];
#pragma unroll
        for (int j = 0; j < 8; j++) acc[j] = bs[lane + 32 * j];
#pragma unroll
        for (int k = 0; k < 16; k++) {
            float xk = xv[k];
            const float* wr = &ws[k * 256 + lane];
#pragma unroll
            for (int j = 0; j < 8; j++) acc[j] += xk * wr[32 * j];
        }
#pragma unroll
        for (int j = 0; j < 8; j++) {
            float v = fmaxf(acc[j], 0.f);
            __nv_bfloat16 h = __float2bfloat16_rn(v);
            Ch[(size_t)row * 256 + lane + 32 * j] = h;
            Cl[(size_t)row * 256 + lane + 32 * j] =
                __float2bfloat16_rn(v - __bfloat162float(h));
        }
    }
}

// ---------------- tensor-core GEMM: C = act(concat(A1,A2) @ W + bias) ----------------
// OUTF32=1: write fp32 C. Otherwise hi/lo bf16 pair.
template <int ACT, int OUTF32>
__global__ __launch_bounds__(256, 2) void mma_gemm(
    const __nv_bfloat16* __restrict__ A1h, const __nv_bfloat16* __restrict__ A1l,
    const __nv_bfloat16* __restrict__ A2h, const __nv_bfloat16* __restrict__ A2l,
    const __nv_bfloat16* __restrict__ Wh,  const __nv_bfloat16* __restrict__ Wl,
    const float* __restrict__ bias,
    __nv_bfloat16* __restrict__ Ch, __nv_bfloat16* __restrict__ Cl,
    float* __restrict__ Cf,
    int M, int K, int K1)
{
    extern __shared__ char smc[];
    __shared__ float sbias[128];

    const int tid = threadIdx.x;
    const int wid = tid >> 5, lane = tid & 31;
    const int g = lane >> 2, tg = lane & 3;
    const int wm = wid >> 1, wn = wid & 1;
    const int m0 = blockIdx.y * 128, n0 = blockIdx.x * 128;
    const uint32_t smc_u = s2u(smc);

    if (tid < 128) sbias[tid] = bias[n0 + tid];

    const int arow = tid >> 1;
    const int aks  = (tid & 1) * 16;
    const int gm   = m0 + arow;
    const int okA  = (gm < M) ? 16 : 0;

    const int q = lane >> 3, rr = lane & 7;
    const uint32_t aoff0 = (uint32_t)((wm * 32 + (q & 1) * 8 + rr) * 80 + (q >> 1) * 16);
    const uint32_t boff0 = (uint32_t)(20480 + (wn * 64 + (q >> 1) * 8 + rr) * 80 + (q & 1) * 16);

    float acc[2][8][4];
#pragma unroll
    for (int i = 0; i < 2; i++)
#pragma unroll
        for (int j = 0; j < 8; j++)
#pragma unroll
            for (int p = 0; p < 4; p++) acc[i][j][p] = 0.f;

    const int NC = K >> 5;

    auto STAGE = [&](int c) {
        const int ck = c * 32;
        const __nv_bfloat16 *Ah, *Al; int lda, kof;
        if (ck < K1) { Ah = A1h; Al = A1l; lda = K1;     kof = ck; }
        else         { Ah = A2h; Al = A2l; lda = K - K1; kof = ck - K1; }
        const uint32_t sb = smc_u + (uint32_t)((c & 1) * STAGE_B);
        const uint32_t da = sb + (uint32_t)(arow * 80 + (tid & 1) * 32);
        const __nv_bfloat16* pah = Ah + (size_t)gm * lda + kof + aks;
        const __nv_bfloat16* pal = Al + (size_t)gm * lda + kof + aks;
        cp16(da, pah, okA);               cp16(da + 16, pah + 8, okA);
        cp16(da + 10240, pal, okA);       cp16(da + 10240 + 16, pal + 8, okA);
        const __nv_bfloat16* pbh = Wh + (size_t)(n0 + arow) * K + ck + aks;
        const __nv_bfloat16* pbl = Wl + (size_t)(n0 + arow) * K + ck + aks;
        cp16(da + 20480, pbh, 16);        cp16(da + 20480 + 16, pbh + 8, 16);
        cp16(da + 30720, pbl, 16);        cp16(da + 30720 + 16, pbl + 8, 16);
        CP_COMMIT();
    };

    STAGE(0);

    for (int c = 0; c < NC; c++) {
        if (c + 1 < NC) {
            STAGE(c + 1);
            asm volatile("cp.async.wait_group 1;" ::: "memory");
        } else {
            asm volatile("cp.async.wait_group 0;" ::: "memory");
        }
        __syncthreads();

        const uint32_t sb = smc_u + (uint32_t)((c & 1) * STAGE_B);
#pragma unroll
        for (int ks = 0; ks < 2; ks++) {
            const uint32_t ko = (uint32_t)(ks * 32);
            uint32_t ah[2][4], bb[8][2];
            ldsm4(ah[0][0], ah[0][1], ah[0][2], ah[0][3], sb + aoff0 + ko);
            ldsm4(ah[1][0], ah[1][1], ah[1][2], ah[1][3], sb + aoff0 + 1280 + ko);
#pragma unroll
            for (int jp = 0; jp < 4; jp++)
                ldsm4(bb[2 * jp][0], bb[2 * jp][1], bb[2 * jp + 1][0], bb[2 * jp + 1][1],
                      sb + boff0 + (uint32_t)(jp * 1280) + ko);
#pragma unroll
            for (int i = 0; i < 2; i++)
#pragma unroll
                for (int j = 0; j < 8; j++) MMA_BF16(acc[i][j], ah[i], bb[j][0], bb[j][1]);

            uint32_t al[2][4];
            ldsm4(al[0][0], al[0][1], al[0][2], al[0][3], sb + 10240 + aoff0 + ko);
            ldsm4(al[1][0], al[1][1], al[1][2], al[1][3], sb + 10240 + aoff0 + 1280 + ko);
#pragma unroll
            for (int i = 0; i < 2; i++)
#pragma unroll
                for (int j = 0; j < 8; j++) MMA_BF16(acc[i][j], al[i], bb[j][0], bb[j][1]);

#pragma unroll
            for (int jp = 0; jp < 4; jp++)
                ldsm4(bb[2 * jp][0], bb[2 * jp][1], bb[2 * jp + 1][0], bb[2 * jp + 1][1],
                      sb + 10240 + boff0 + (uint32_t)(jp * 1280) + ko);
#pragma unroll
            for (int i = 0; i < 2; i++)
#pragma unroll
                for (int j = 0; j < 8; j++) MMA_BF16(acc[i][j], ah[i], bb[j][0], bb[j][1]);
        }
        __syncthreads();
    }

    // epilogue: bias + activation + store
#pragma unroll
    for (int i = 0; i < 2; i++) {
        int r0 = m0 + wm * 32 + i * 16 + g;
#pragma unroll
        for (int j = 0; j < 8; j++) {
            int cl = wn * 64 + j * 8 + tg * 2;
            float b0 = sbias[cl], b1 = sbias[cl + 1];
            float v0 = acc[i][j][0] + b0, v1 = acc[i][j][1] + b1;
            float v2 = acc[i][j][2] + b0, v3 = acc[i][j][3] + b1;
            if (ACT == 1) {
                v0 = fmaxf(v0, 0.f); v1 = fmaxf(v1, 0.f);
                v2 = fmaxf(v2, 0.f); v3 = fmaxf(v3, 0.f);
            }
            if (OUTF32) {
                if (r0 < M)
                    *(float2*)(Cf + (size_t)r0 * 256 + n0 + cl) = make_float2(v0, v1);
                if (r0 + 8 < M)
                    *(float2*)(Cf + (size_t)(r0 + 8) * 256 + n0 + cl) = make_float2(v2, v3);
            } else {
                uint32_t hw, lw;
                if (r0 < M) {
                    split_pair(v0, v1, hw, lw);
                    *(uint32_t*)(Ch + (size_t)r0 * 256 + n0 + cl) = hw;
                    *(uint32_t*)(Cl + (size_t)r0 * 256 + n0 + cl) = lw;
                }
                if (r0 + 8 < M) {
                    split_pair(v2, v3, hw, lw);
                    *(uint32_t*)(Ch + (size_t)(r0 + 8) * 256 + n0 + cl) = hw;
                    *(uint32_t*)(Cl + (size_t)(r0 + 8) * 256 + n0 + cl) = lw;
                }
            }
        }
    }
}

// ---------------- CSR build ----------------
__global__ void count_kernel(const int* __restrict__ dst, int* __restrict__ cnt) {
    int e = blockIdx.x * blockDim.x + threadIdx.x;
    if (e < NE) atomicAdd(&cnt[dst[e]], 1);
}

__global__ __launch_bounds__(1024) void scan_kernel(const int* __restrict__ cnt,
                                                    int* __restrict__ rowptr,
                                                    int* __restrict__ fill) {
    __shared__ int wsum[32];
    __shared__ int s_carry;
    const int tid = threadIdx.x, lane = tid & 31, wid = tid >> 5;
    if (tid == 0) { s_carry = 0; rowptr[0] = 0; }
    __syncthreads();
    for (int base = 0; base < NN; base += 1024) {
        int i = base + tid;
        int v = (i < NN) ? cnt[i] : 0;
        int s = v;
#pragma unroll
        for (int d = 1; d < 32; d <<= 1) {
            int y = __shfl_up_sync(0xffffffffu, s, d);
            if (lane >= d) s += y;
        }
        if (lane == 31) wsum[wid] = s;
        int carry_in = s_carry;
        __syncthreads();
        if (wid == 0) {
            int ws = wsum[lane];
#pragma unroll
            for (int d = 1; d < 32; d <<= 1) {
                int y = __shfl_up_sync(0xffffffffu, ws, d);
                if (lane >= d) ws += y;
            }
            wsum[lane] = ws;
        }
        __syncthreads();
        int off = (wid ? wsum[wid - 1] : 0) + carry_in;
        int inc = s + off;
        if (i < NN) {
            rowptr[i + 1] = inc;
            fill[i] = inc - v;
        }
        __syncthreads();
        if (tid == 1023) s_carry = inc;
        __syncthreads();
    }
}

__global__ void scatter_kernel(const int* __restrict__ src, const int* __restrict__ dst,
                               int* __restrict__ fill, int* __restrict__ col) {
    int e = blockIdx.x * blockDim.x + threadIdx.x;
    if (e < NE) {
        int slot = atomicAdd(&fill[dst[e]], 1);
        col[slot] = src[e];
    }
}

// ---------------- aggregation — fp32 t gather (4 nodes/block, 1 warp each) -----------
__global__ __launch_bounds__(128) void agg_kernel(
    const float* __restrict__ t,
    const int* __restrict__ rowptr, const int* __restrict__ col,
    __nv_bfloat16* __restrict__ aggh, __nv_bfloat16* __restrict__ aggl)
{
    const int node = blockIdx.x * 4 + (threadIdx.x >> 5);
    if (node >= NN) return;
    const int tid = threadIdx.x & 31;
    const int s = rowptr[node];
    const int e = rowptr[node + 1];
    float4 a0 = make_float4(0.f, 0.f, 0.f, 0.f);
    float4 a1 = make_float4(0.f, 0.f, 0.f, 0.f);

    int i = s;
    for (; i + 4 <= e; i += 4) {
        int c0 = __ldg(&col[i]),     c1 = __ldg(&col[i + 1]);
        int c2 = __ldg(&col[i + 2]), c3 = __ldg(&col[i + 3]);
        const float4* p0 = (const float4*)(t + (size_t)c0 * HID + tid * 8);
        const float4* p1 = (const float4*)(t + (size_t)c1 * HID + tid * 8);
        const float4* p2 = (const float4*)(t + (size_t)c2 * HID + tid * 8);
        const float4* p3 = (const float4*)(t + (size_t)c3 * HID + tid * 8);
        float4 v00 = p0[0], v01 = p0[1];
        float4 v10 = p1[0], v11 = p1[1];
        float4 v20 = p2[0], v21 = p2[1];
        float4 v30 = p3[0], v31 = p3[1];
        a0.x += v00.x + v10.x + v20.x + v30.x;
        a0.y += v00.y + v10.y + v20.y + v30.y;
        a0.z += v00.z + v10.z + v20.z + v30.z;
        a0.w += v00.w + v10.w + v20.w + v30.w;
        a1.x += v01.x + v11.x + v21.x + v31.x;
        a1.y += v01.y + v11.y + v21.y + v31.y;
        a1.z += v01.z + v11.z + v21.z + v31.z;
        a1.w += v01.w + v11.w + v21.w + v31.w;
    }
    for (; i < e; i++) {
        int c0 = __ldg(&col[i]);
        const float4* p0 = (const float4*)(t + (size_t)c0 * HID + tid * 8);
        float4 v0 = p0[0], v1 = p0[1];
        a0.x += v0.x; a0.y += v0.y; a0.z += v0.z; a0.w += v0.w;
        a1.x += v1.x; a1.y += v1.y; a1.z += v1.z; a1.w += v1.w;
    }

    uint32_t hw[4], lw[4];
    split_pair(a0.x, a0.y, hw[0], lw[0]);
    split_pair(a0.z, a0.w, hw[1], lw[1]);
    split_pair(a1.x, a1.y, hw[2], lw[2]);
    split_pair(a1.z, a1.w, hw[3], lw[3]);
    *(uint4*)(aggh + (size_t)node * HID + tid * 8) = *(uint4*)hw;
    *(uint4*)(aggl + (size_t)node * HID + tid * 8) = *(uint4*)lw;
}

// ---------------- output projection: out = tanh(u @ W2 + b2) ----------------
__global__ __launch_bounds__(256) void out_kernel(
    const __nv_bfloat16* __restrict__ uh, const __nv_bfloat16* __restrict__ ul,
    const float* __restrict__ w, const float* __restrict__ b,
    float* __restrict__ out, int M)
{
    __shared__ float ws[256 * 16];
    __shared__ float bs[16];
    const int tid = threadIdx.x;
    for (int i = tid; i < 256 * 16 / 4; i += 256)
        ((float4*)ws)[i] = ((const float4*)w)[i];
    if (tid < 16) bs[tid] = b[tid];
    __syncthreads();

    const int mloc = tid >> 1;
    const int off  = (tid & 1) * 8;
    const int m = blockIdx.x * 128 + mloc;
    if (m >= M) return;

    float acc[8];
#pragma unroll
    for (int j = 0; j < 8; j++) acc[j] = bs[off + j];

    const uint4* ph = (const uint4*)(uh + (size_t)m * HID);
    const uint4* pl = (const uint4*)(ul + (size_t)m * HID);
#pragma unroll 4
    for (int kc = 0; kc < 32; kc++) {
        uint4 hv = ph[kc], lv = pl[kc];
        const uint32_t* hp = (const uint32_t*)&hv;
        const uint32_t* lp = (const uint32_t*)&lv;
        float f[8];
#pragma unroll
        for (int p = 0; p < 4; p++) {
            __nv_bfloat162 h2 = *reinterpret_cast<const __nv_bfloat162*>(&hp[p]);
            __nv_bfloat162 l2 = *reinterpret_cast<const __nv_bfloat162*>(&lp[p]);
            f[2 * p]     = __low2float(h2)  + __low2float(l2);
            f[2 * p + 1] = __high2float(h2) + __high2float(l2);
        }
#pragma unroll
        for (int qv = 0; qv < 8; qv++) {
            const float* wr = &ws[(kc * 8 + qv) * 16 + off];
#pragma unroll
            for (int j = 0; j < 8; j++) acc[j] += f[qv] * wr[j];
        }
    }
    float o[8];
#pragma unroll
    for (int j = 0; j < 8; j++) o[j] = tanhf(acc[j]);
    float* op = out + (size_t)m * 16 + off;
    *(float4*)(op)     = *(float4*)&o[0];
    *(float4*)(op + 4) = *(float4*)&o[4];
}

// ---------------- launcher (Round-7 structure: homogeneous kernels only) -------------
extern "C" void kernel_launch(void* const* d_in, const int* in_sizes, int n_in,
                              void* d_out, int out_size) {
    const float* x       = (const float*)d_in[0];
    const int*   ei      = (const int*)d_in[1];
    const float* pre_w1  = (const float*)d_in[2];
    const float* pre_b1  = (const float*)d_in[3];
    const float* pre_w2  = (const float*)d_in[4];
    const float* pre_b2  = (const float*)d_in[5];
    const float* conv_w  = (const float*)d_in[6];
    const float* conv_b  = (const float*)d_in[7];
    const float* post_w1 = (const float*)d_in[8];
    const float* post_b1 = (const float*)d_in[9];
    const float* post_w2 = (const float*)d_in[10];
    const float* post_b2 = (const float*)d_in[11];
    float* out = (float*)d_out;

    const int* src = ei;
    const int* dst = ei + NE;

    __nv_bfloat16 *ah, *al, *gh, *gl, *uh, *ul;
    float* t;
    int *cnt, *rowptr, *fill, *col;
    float *cbt, *cbu;
    __nv_bfloat16 *wth, *wtl, *wuh, *wul;
    cudaGetSymbolAddress((void**)&ah, g_ah);   cudaGetSymbolAddress((void**)&al, g_al);
    cudaGetSymbolAddress((void**)&t, g_t);
    cudaGetSymbolAddress((void**)&gh, g_gh);   cudaGetSymbolAddress((void**)&gl, g_gl);
    cudaGetSymbolAddress((void**)&uh, g_uh);   cudaGetSymbolAddress((void**)&ul, g_ul);
    cudaGetSymbolAddress((void**)&cnt, g_cnt);
    cudaGetSymbolAddress((void**)&rowptr, g_rowptr);
    cudaGetSymbolAddress((void**)&fill, g_fill);
    cudaGetSymbolAddress((void**)&col, g_col);
    cudaGetSymbolAddress((void**)&cbt, g_cbt); cudaGetSymbolAddress((void**)&cbu, g_cbu);
    cudaGetSymbolAddress((void**)&wth, g_wth); cudaGetSymbolAddress((void**)&wtl, g_wtl);
    cudaGetSymbolAddress((void**)&wuh, g_wuh); cudaGetSymbolAddress((void**)&wul, g_wul);

    const float* P1 = post_w1;                 // rows 0..255 of [512][256]
    const float* P2 = post_w1 + 256 * 256;     // rows 256..511

    const int DSMEM = 2 * STAGE_B;  // 80 KB
    cudaFuncSetAttribute(mma_gemm<1, 1>, cudaFuncAttributeMaxDynamicSharedMemorySize, DSMEM);
    cudaFuncSetAttribute(mma_gemm<1, 0>, cudaFuncAttributeMaxDynamicSharedMemorySize, DSMEM);

    const int MT = (NN + 127) / 128;  // 391
    dim3 gg(2, MT);

    // (1) t-weights + t-bias
    compose_prep<<<dim3(4, 5), 256>>>(pre_w2, conv_w, wth, wtl, 256, 0,
                                      pre_b2, conv_b, cbt);
    // (2) pre-MLP layer 1 -> a pair
    pre_kernel<<<(NN + 31) / 32, 256>>>(x, pre_w1, pre_b1, ah, al);
    // (3) u-weights a-part + u-bias
    compose_prep<<<dim3(4, 5), 256>>>(pre_w2, P1, wuh, wul, 512, 0,
                                      pre_b2, post_b1, cbu);
    // (4) u-weights agg-part
    prep2<<<dim3(8, 8), dim3(32, 8)>>>(P2, wuh, wul, 512, 256);
    // (5) t = relu(a@Wt + bt) -> fp32
    mma_gemm<1, 1><<<gg, 256, DSMEM>>>(ah, al, nullptr, nullptr, wth, wtl, cbt,
                                       nullptr, nullptr, t, NN, 256, 256);

    // ---- CSR build + atomic-free segment sum ----
    cudaMemsetAsync(cnt, 0, NN * sizeof(int), 0);
    count_kernel<<<(NE + 255) / 256, 256>>>(dst, cnt);
    scan_kernel<<<1, 1024>>>(cnt, rowptr, fill);
    scatter_kernel<<<(NE + 255) / 256, 256>>>(src, dst, fill, col);
    agg_kernel<<<(NN + 3) / 4, 128>>>(t, rowptr, col, gh, gl);

    // ---- u = relu(a@Wp + agg@P2 + bu)  (K=512 concat) ----
    mma_gemm<1, 0><<<gg, 256, DSMEM>>>(ah, al, gh, gl, wuh, wul, cbu,
                                       uh, ul, nullptr, NN, 512, 256);
    // ---- out = tanh(u@post_w2 + post_b2) ----
    out_kernel<<<(NN + 127) / 128, 256>>>(uh, ul, post_w2, post_b2, out, NN);
}

// round 11
// speedup vs baseline: 1.3258x; 1.0918x over previous
#include <cuda_runtime.h>
#include <cuda_bf16.h>
#include <cstdint>
#include <cstddef>

#define NN 50000
#define NE 800000
#define HID 256

// smem stage layout (bytes, pitch 80/row of 32 bf16 + pad):
// Ah[128x80]=10240 | Al=10240 | Bh[128x80]=10240 | Bl=10240
#define STAGE_B 40960

// ---------------- scratch (device globals: no allocation allowed) ----------------
__device__ __nv_bfloat16 g_ah[(size_t)NN * HID], g_al[(size_t)NN * HID];
__device__ __nv_bfloat16 g_t[(size_t)NN * HID];                 // SINGLE bf16 t (agg-only)
__device__ __nv_bfloat16 g_gh[(size_t)NN * HID], g_gl[(size_t)NN * HID];
__device__ __nv_bfloat16 g_uh[(size_t)NN * HID], g_ul[(size_t)NN * HID];
__device__ int g_cnt[NN];
__device__ int g_rowptr[NN + 1];
__device__ int g_fill[NN];
__device__ int g_col[NE];
__device__ float g_cbt[256];         // b2@Wc + conv_b
__device__ float g_cbu[256];         // b2@P1 + post_b1
__device__ __nv_bfloat16 g_wth[256 * 256], g_wtl[256 * 256];   // t-GEMM weights
__device__ __nv_bfloat16 g_wuh[256 * 512], g_wul[256 * 512];   // u-GEMM weights

// ---------------- helpers ----------------
__device__ __forceinline__ uint32_t s2u(const void* p) {
    uint32_t a;
    asm("{ .reg .u64 t; cvta.to.shared.u64 t, %1; cvt.u32.u64 %0, t; }" : "=r"(a) : "l"(p));
    return a;
}
__device__ __forceinline__ void cp16(uint32_t dst, const void* src, int srcsz) {
    asm volatile("cp.async.cg.shared.global [%0], [%1], 16, %2;"
                 :: "r"(dst), "l"(src), "r"(srcsz) : "memory");
}
#define CP_COMMIT() asm volatile("cp.async.commit_group;" ::: "memory")

__device__ __forceinline__ void ldsm4(uint32_t& r0, uint32_t& r1, uint32_t& r2, uint32_t& r3,
                                      uint32_t addr) {
    asm volatile("ldmatrix.sync.aligned.m8n8.x4.shared.b16 {%0,%1,%2,%3}, [%4];"
                 : "=r"(r0), "=r"(r1), "=r"(r2), "=r"(r3) : "r"(addr));
}

#define MMA_BF16(cc, aa, b0v, b1v)                                              \
    asm volatile(                                                               \
        "mma.sync.aligned.m16n8k16.row.col.f32.bf16.bf16.f32 "                  \
        "{%0,%1,%2,%3}, {%4,%5,%6,%7}, {%8,%9}, {%0,%1,%2,%3};"                 \
        : "+f"(cc[0]), "+f"(cc[1]), "+f"(cc[2]), "+f"(cc[3])                    \
        : "r"(aa[0]), "r"(aa[1]), "r"(aa[2]), "r"(aa[3]), "r"(b0v), "r"(b1v))

__device__ __forceinline__ uint32_t pack_bf16x2(float a, float b) {
    __nv_bfloat162 p = __float22bfloat162_rn(make_float2(a, b));
    return *reinterpret_cast<uint32_t*>(&p);
}
__device__ __forceinline__ void split_pair(float v0, float v1, uint32_t& hw, uint32_t& lw) {
    float h0 = __bfloat162float(__float2bfloat16_rn(v0));
    float h1 = __bfloat162float(__float2bfloat16_rn(v1));
    hw = pack_bf16x2(h0, h1);
    lw = pack_bf16x2(v0 - h0, v1 - h1);
}

// ---------------- fused compose+prep+bias ----------------
__global__ __launch_bounds__(256) void compose_prep(
    const float* __restrict__ A, const float* __restrict__ B,
    __nv_bfloat16* __restrict__ hi, __nv_bfloat16* __restrict__ lo,
    int kpitch, int koff,
    const float* __restrict__ b2, const float* __restrict__ badd,
    float* __restrict__ bout)
{
    const int t = threadIdx.x;
    if (blockIdx.y == 4) {
        __shared__ float red[4][64];
        int j = blockIdx.x * 64 + (t & 63);
        int ks = t >> 6;
        float acc = 0.f;
#pragma unroll 8
        for (int k = ks * 64; k < ks * 64 + 64; k++)
            acc += b2[k] * B[(size_t)k * 256 + j];
        red[ks][t & 63] = acc;
        __syncthreads();
        if (t < 64) {
            int jj = blockIdx.x * 64 + t;
            bout[jj] = red[0][t] + red[1][t] + red[2][t] + red[3][t] + badd[jj];
        }
        return;
    }

    __shared__ float As[16][64];
    __shared__ float Bs[16][64];
    const int tx = t & 15, ty = t >> 4;
    const int m0 = blockIdx.y * 64, n0 = blockIdx.x * 64;
    float acc[4][4];
#pragma unroll
    for (int i = 0; i < 4; i++)
#pragma unroll
        for (int j = 0; j < 4; j++) acc[i][j] = 0.f;

    for (int k0 = 0; k0 < 256; k0 += 16) {
#pragma unroll
        for (int i = 0; i < 4; i++) {
            int idx = t + i * 256;
            int r = idx >> 4, c = idx & 15;
            As[c][r] = A[(size_t)(m0 + r) * 256 + k0 + c];
        }
#pragma unroll
        for (int i = 0; i < 4; i++) {
            int idx = t + i * 256;
            int r = idx >> 6, c = idx & 63;
            Bs[r][c] = B[(size_t)(k0 + r) * 256 + n0 + c];
        }
        __syncthreads();
#pragma unroll
        for (int k = 0; k < 16; k++) {
            float ra[4], rb[4];
#pragma unroll
            for (int i = 0; i < 4; i++) ra[i] = As[k][ty * 4 + i];
#pragma unroll
            for (int j = 0; j < 4; j++) rb[j] = Bs[k][tx * 4 + j];
#pragma unroll
            for (int i = 0; i < 4; i++)
#pragma unroll
                for (int j = 0; j < 4; j++) acc[i][j] += ra[i] * rb[j];
        }
        __syncthreads();
    }
#pragma unroll
    for (int i = 0; i < 4; i++) {
        int kk = m0 + ty * 4 + i;
#pragma unroll
        for (int j = 0; j < 4; j++) {
            int nn = n0 + tx * 4 + j;
            float v = acc[i][j];
            __nv_bfloat16 h = __float2bfloat16_rn(v);
            hi[(size_t)nn * kpitch + koff + kk] = h;
            lo[(size_t)nn * kpitch + koff + kk] =
                __float2bfloat16_rn(v - __bfloat162float(h));
        }
    }
}

// ---------------- prep (transpose + split only, for P2) ----------------
__global__ void prep2(const float* __restrict__ W, __nv_bfloat16* __restrict__ hi,
                      __nv_bfloat16* __restrict__ lo, int kpitch, int koff) {
    __shared__ float tile[32][33];
    int k0 = blockIdx.y * 32, n0 = blockIdx.x * 32;
    int tx = threadIdx.x, ty = threadIdx.y;  // 32 x 8
    for (int i = ty; i < 32; i += 8) tile[i][tx] = W[(size_t)(k0 + i) * 256 + n0 + tx];
    __syncthreads();
    for (int i = ty; i < 32; i += 8) {
        float v = tile[tx][i];
        __nv_bfloat16 h = __float2bfloat16_rn(v);
        hi[(size_t)(n0 + i) * kpitch + koff + k0 + tx] = h;
        lo[(size_t)(n0 + i) * kpitch + koff + k0 + tx] =
            __float2bfloat16_rn(v - __bfloat162float(h));
    }
}

// ---------------- pre-MLP layer 1: a = relu(x@w1+b1), K=16, hi/lo out ---------------
__global__ __launch_bounds__(256) void pre_kernel(
    const float* __restrict__ x, const float* __restrict__ w1, const float* __restrict__ b1,
    __nv_bfloat16* __restrict__ Ch, __nv_bfloat16* __restrict__ Cl)
{
    __shared__ float ws[16 * 256];
    __shared__ float bs[256];
    const int tid = threadIdx.x;
    for (int i = tid; i < 1024; i += 256) ((float4*)ws)[i] = ((const float4*)w1)[i];
    bs[tid] = b1[tid];
    __syncthreads();

    const int warp = tid >> 5, lane = tid & 31;
#pragma unroll
    for (int r = 0; r < 4; r++) {
        int row = blockIdx.x * 32 + warp * 4 + r;
        if (row >= NN) break;
        float xv[16];
        const float4* xp = (const float4*)(x + (size_t)row * 16);
#pragma unroll
        for (int q = 0; q < 4; q++) *(float4*)&xv[q * 4] = xp[q];
        float acc[8];
#pragma unroll
        for (int j = 0; j < 8; j++) acc[j] = bs[lane + 32 * j];
#pragma unroll
        for (int k = 0; k < 16; k++) {
            float xk = xv[k];
            const float* wr = &ws[k * 256 + lane];
#pragma unroll
            for (int j = 0; j < 8; j++) acc[j] += xk * wr[32 * j];
        }
#pragma unroll
        for (int j = 0; j < 8; j++) {
            float v = fmaxf(acc[j], 0.f);
            __nv_bfloat16 h = __float2bfloat16_rn(v);
            Ch[(size_t)row * 256 + lane + 32 * j] = h;
            Cl[(size_t)row * 256 + lane + 32 * j] =
                __float2bfloat16_rn(v - __bfloat162float(h));
        }
    }
}

// ---------------- tensor-core GEMM: C = act(concat(A1,A2) @ W + bias) ----------------
// OUTMODE 0: hi/lo bf16 pair.  OUTMODE 2: single bf16 (for t).
template <int ACT, int OUTMODE>
__global__ __launch_bounds__(256, 2) void mma_gemm(
    const __nv_bfloat16* __restrict__ A1h, const __nv_bfloat16* __restrict__ A1l,
    const __nv_bfloat16* __restrict__ A2h, const __nv_bfloat16* __restrict__ A2l,
    const __nv_bfloat16* __restrict__ Wh,  const __nv_bfloat16* __restrict__ Wl,
    const float* __restrict__ bias,
    __nv_bfloat16* __restrict__ Ch, __nv_bfloat16* __restrict__ Cl,
    int M, int K, int K1)
{
    extern __shared__ char smc[];
    __shared__ float sbias[128];

    const int tid = threadIdx.x;
    const int wid = tid >> 5, lane = tid & 31;
    const int g = lane >> 2, tg = lane & 3;
    const int wm = wid >> 1, wn = wid & 1;
    const int m0 = blockIdx.y * 128, n0 = blockIdx.x * 128;
    const uint32_t smc_u = s2u(smc);

    if (tid < 128) sbias[tid] = bias[n0 + tid];

    const int arow = tid >> 1;
    const int aks  = (tid & 1) * 16;
    const int gm   = m0 + arow;
    const int okA  = (gm < M) ? 16 : 0;

    const int q = lane >> 3, rr = lane & 7;
    const uint32_t aoff0 = (uint32_t)((wm * 32 + (q & 1) * 8 + rr) * 80 + (q >> 1) * 16);
    const uint32_t boff0 = (uint32_t)(20480 + (wn * 64 + (q >> 1) * 8 + rr) * 80 + (q & 1) * 16);

    float acc[2][8][4];
#pragma unroll
    for (int i = 0; i < 2; i++)
#pragma unroll
        for (int j = 0; j < 8; j++)
#pragma unroll
            for (int p = 0; p < 4; p++) acc[i][j][p] = 0.f;

    const int NC = K >> 5;

    auto STAGE = [&](int c) {
        const int ck = c * 32;
        const __nv_bfloat16 *Ah, *Al; int lda, kof;
        if (ck < K1) { Ah = A1h; Al = A1l; lda = K1;     kof = ck; }
        else         { Ah = A2h; Al = A2l; lda = K - K1; kof = ck - K1; }
        const uint32_t sb = smc_u + (uint32_t)((c & 1) * STAGE_B);
        const uint32_t da = sb + (uint32_t)(arow * 80 + (tid & 1) * 32);
        const __nv_bfloat16* pah = Ah + (size_t)gm * lda + kof + aks;
        const __nv_bfloat16* pal = Al + (size_t)gm * lda + kof + aks;
        cp16(da, pah, okA);               cp16(da + 16, pah + 8, okA);
        cp16(da + 10240, pal, okA);       cp16(da + 10240 + 16, pal + 8, okA);
        const __nv_bfloat16* pbh = Wh + (size_t)(n0 + arow) * K + ck + aks;
        const __nv_bfloat16* pbl = Wl + (size_t)(n0 + arow) * K + ck + aks;
        cp16(da + 20480, pbh, 16);        cp16(da + 20480 + 16, pbh + 8, 16);
        cp16(da + 30720, pbl, 16);        cp16(da + 30720 + 16, pbl + 8, 16);
        CP_COMMIT();
    };

    STAGE(0);

    for (int c = 0; c < NC; c++) {
        if (c + 1 < NC) {
            STAGE(c + 1);
            asm volatile("cp.async.wait_group 1;" ::: "memory");
        } else {
            asm volatile("cp.async.wait_group 0;" ::: "memory");
        }
        __syncthreads();

        const uint32_t sb = smc_u + (uint32_t)((c & 1) * STAGE_B);
#pragma unroll
        for (int ks = 0; ks < 2; ks++) {
            const uint32_t ko = (uint32_t)(ks * 32);
            uint32_t ah[2][4], bb[8][2];
            ldsm4(ah[0][0], ah[0][1], ah[0][2], ah[0][3], sb + aoff0 + ko);
            ldsm4(ah[1][0], ah[1][1], ah[1][2], ah[1][3], sb + aoff0 + 1280 + ko);
#pragma unroll
            for (int jp = 0; jp < 4; jp++)
                ldsm4(bb[2 * jp][0], bb[2 * jp][1], bb[2 * jp + 1][0], bb[2 * jp + 1][1],
                      sb + boff0 + (uint32_t)(jp * 1280) + ko);
#pragma unroll
            for (int i = 0; i < 2; i++)
#pragma unroll
                for (int j = 0; j < 8; j++) MMA_BF16(acc[i][j], ah[i], bb[j][0], bb[j][1]);

            uint32_t al[2][4];
            ldsm4(al[0][0], al[0][1], al[0][2], al[0][3], sb + 10240 + aoff0 + ko);
            ldsm4(al[1][0], al[1][1], al[1][2], al[1][3], sb + 10240 + aoff0 + 1280 + ko);
#pragma unroll
            for (int i = 0; i < 2; i++)
#pragma unroll
                for (int j = 0; j < 8; j++) MMA_BF16(acc[i][j], al[i], bb[j][0], bb[j][1]);

#pragma unroll
            for (int jp = 0; jp < 4; jp++)
                ldsm4(bb[2 * jp][0], bb[2 * jp][1], bb[2 * jp + 1][0], bb[2 * jp + 1][1],
                      sb + 10240 + boff0 + (uint32_t)(jp * 1280) + ko);
#pragma unroll
            for (int i = 0; i < 2; i++)
#pragma unroll
                for (int j = 0; j < 8; j++) MMA_BF16(acc[i][j], ah[i], bb[j][0], bb[j][1]);
        }
        __syncthreads();
    }

    // epilogue
#pragma unroll
    for (int i = 0; i < 2; i++) {
        int r0 = m0 + wm * 32 + i * 16 + g;
#pragma unroll
        for (int j = 0; j < 8; j++) {
            int cl = wn * 64 + j * 8 + tg * 2;
            float b0 = sbias[cl], b1 = sbias[cl + 1];
            float v0 = acc[i][j][0] + b0, v1 = acc[i][j][1] + b1;
            float v2 = acc[i][j][2] + b0, v3 = acc[i][j][3] + b1;
            if (ACT == 1) {
                v0 = fmaxf(v0, 0.f); v1 = fmaxf(v1, 0.f);
                v2 = fmaxf(v2, 0.f); v3 = fmaxf(v3, 0.f);
            }
            if (OUTMODE == 2) {
                if (r0 < M)
                    *(uint32_t*)(Ch + (size_t)r0 * 256 + n0 + cl) = pack_bf16x2(v0, v1);
                if (r0 + 8 < M)
                    *(uint32_t*)(Ch + (size_t)(r0 + 8) * 256 + n0 + cl) = pack_bf16x2(v2, v3);
            } else {
                uint32_t hw, lw;
                if (r0 < M) {
                    split_pair(v0, v1, hw, lw);
                    *(uint32_t*)(Ch + (size_t)r0 * 256 + n0 + cl) = hw;
                    *(uint32_t*)(Cl + (size_t)r0 * 256 + n0 + cl) = lw;
                }
                if (r0 + 8 < M) {
                    split_pair(v2, v3, hw, lw);
                    *(uint32_t*)(Ch + (size_t)(r0 + 8) * 256 + n0 + cl) = hw;
                    *(uint32_t*)(Cl + (size_t)(r0 + 8) * 256 + n0 + cl) = lw;
                }
            }
        }
    }
}

// ---------------- CSR build ----------------
__global__ void count_kernel(const int* __restrict__ dst, int* __restrict__ cnt) {
    int e = blockIdx.x * blockDim.x + threadIdx.x;
    if (e < NE) atomicAdd(&cnt[dst[e]], 1);
}

__global__ __launch_bounds__(1024) void scan_kernel(const int* __restrict__ cnt,
                                                    int* __restrict__ rowptr,
                                                    int* __restrict__ fill) {
    __shared__ int wsum[32];
    __shared__ int s_carry;
    const int tid = threadIdx.x, lane = tid & 31, wid = tid >> 5;
    if (tid == 0) { s_carry = 0; rowptr[0] = 0; }
    __syncthreads();
    for (int base = 0; base < NN; base += 1024) {
        int i = base + tid;
        int v = (i < NN) ? cnt[i] : 0;
        int s = v;
#pragma unroll
        for (int d = 1; d < 32; d <<= 1) {
            int y = __shfl_up_sync(0xffffffffu, s, d);
            if (lane >= d) s += y;
        }
        if (lane == 31) wsum[wid] = s;
        int carry_in = s_carry;
        __syncthreads();
        if (wid == 0) {
            int ws = wsum[lane];
#pragma unroll
            for (int d = 1; d < 32; d <<= 1) {
                int y = __shfl_up_sync(0xffffffffu, ws, d);
                if (lane >= d) ws += y;
            }
            wsum[lane] = ws;
        }
        __syncthreads();
        int off = (wid ? wsum[wid - 1] : 0) + carry_in;
        int inc = s + off;
        if (i < NN) {
            rowptr[i + 1] = inc;
            fill[i] = inc - v;
        }
        __syncthreads();
        if (tid == 1023) s_carry = inc;
        __syncthreads();
    }
}

__global__ void scatter_kernel(const int* __restrict__ src, const int* __restrict__ dst,
                               int* __restrict__ fill, int* __restrict__ col) {
    int e = blockIdx.x * blockDim.x + threadIdx.x;
    if (e < NE) {
        int slot = atomicAdd(&fill[dst[e]], 1);
        col[slot] = src[e];
    }
}

// ---------------- aggregation — single-bf16 t gather (4 nodes/block, 1 warp each) ----
__device__ __forceinline__ void acc8s(float* acc, uint4 hv) {
    const uint32_t* h = (const uint32_t*)&hv;
#pragma unroll
    for (int p = 0; p < 4; p++) {
        __nv_bfloat162 h2 = *reinterpret_cast<const __nv_bfloat162*>(&h[p]);
        acc[2 * p]     += __low2float(h2);
        acc[2 * p + 1] += __high2float(h2);
    }
}

__global__ __launch_bounds__(128) void agg_kernel(
    const __nv_bfloat16* __restrict__ t,
    const int* __restrict__ rowptr, const int* __restrict__ col,
    __nv_bfloat16* __restrict__ aggh, __nv_bfloat16* __restrict__ aggl)
{
    const int node = blockIdx.x * 4 + (threadIdx.x >> 5);
    if (node >= NN) return;
    const int tid = threadIdx.x & 31;
    const int s = rowptr[node];
    const int e = rowptr[node + 1];
    float acc[8];
#pragma unroll
    for (int p = 0; p < 8; p++) acc[p] = 0.f;

    int i = s;
    for (; i + 4 <= e; i += 4) {
        int c0 = __ldg(&col[i]),     c1 = __ldg(&col[i + 1]);
        int c2 = __ldg(&col[i + 2]), c3 = __ldg(&col[i + 3]);
        uint4 h0 = *(const uint4*)(t + (size_t)c0 * HID + tid * 8);
        uint4 h1 = *(const uint4*)(t + (size_t)c1 * HID + tid * 8);
        uint4 h2 = *(const uint4*)(t + (size_t)c2 * HID + tid * 8);
        uint4 h3 = *(const uint4*)(t + (size_t)c3 * HID + tid * 8);
        acc8s(acc, h0); acc8s(acc, h1);
        acc8s(acc, h2); acc8s(acc, h3);
    }
    for (; i < e; i++) {
        int c0 = __ldg(&col[i]);
        uint4 h0 = *(const uint4*)(t + (size_t)c0 * HID + tid * 8);
        acc8s(acc, h0);
    }

    uint32_t hw[4], lw[4];
#pragma unroll
    for (int p = 0; p < 4; p++) split_pair(acc[2 * p], acc[2 * p + 1], hw[p], lw[p]);
    *(uint4*)(aggh + (size_t)node * HID + tid * 8) = *(uint4*)hw;
    *(uint4*)(aggl + (size_t)node * HID + tid * 8) = *(uint4*)lw;
}

// ---------------- output projection: out = tanh(u @ W2 + b2) ----------------
__global__ __launch_bounds__(256) void out_kernel(
    const __nv_bfloat16* __restrict__ uh, const __nv_bfloat16* __restrict__ ul,
    const float* __restrict__ w, const float* __restrict__ b,
    float* __restrict__ out, int M)
{
    __shared__ float ws[256 * 16];
    __shared__ float bs[16];
    const int tid = threadIdx.x;
    for (int i = tid; i < 256 * 16 / 4; i += 256)
        ((float4*)ws)[i] = ((const float4*)w)[i];
    if (tid < 16) bs[tid] = b[tid];
    __syncthreads();

    const int mloc = tid >> 1;
    const int off  = (tid & 1) * 8;
    const int m = blockIdx.x * 128 + mloc;
    if (m >= M) return;

    float acc[8];
#pragma unroll
    for (int j = 0; j < 8; j++) acc[j] = bs[off + j];

    const uint4* ph = (const uint4*)(uh + (size_t)m * HID);
    const uint4* pl = (const uint4*)(ul + (size_t)m * HID);
#pragma unroll 4
    for (int kc = 0; kc < 32; kc++) {
        uint4 hv = ph[kc], lv = pl[kc];
        const uint32_t* hp = (const uint32_t*)&hv;
        const uint32_t* lp = (const uint32_t*)&lv;
        float f[8];
#pragma unroll
        for (int p = 0; p < 4; p++) {
            __nv_bfloat162 h2 = *reinterpret_cast<const __nv_bfloat162*>(&hp[p]);
            __nv_bfloat162 l2 = *reinterpret_cast<const __nv_bfloat162*>(&lp[p]);
            f[2 * p]     = __low2float(h2)  + __low2float(l2);
            f[2 * p + 1] = __high2float(h2) + __high2float(l2);
        }
#pragma unroll
        for (int qv = 0; qv < 8; qv++) {
            const float* wr = &ws[(kc * 8 + qv) * 16 + off];
#pragma unroll
            for (int j = 0; j < 8; j++) acc[j] += f[qv] * wr[j];
        }
    }
    float o[8];
#pragma unroll
    for (int j = 0; j < 8; j++) o[j] = tanhf(acc[j]);
    float* op = out + (size_t)m * 16 + off;
    *(float4*)(op)     = *(float4*)&o[0];
    *(float4*)(op + 4) = *(float4*)&o[4];
}

// ---------------- launcher ----------------
extern "C" void kernel_launch(void* const* d_in, const int* in_sizes, int n_in,
                              void* d_out, int out_size) {
    const float* x       = (const float*)d_in[0];
    const int*   ei      = (const int*)d_in[1];
    const float* pre_w1  = (const float*)d_in[2];
    const float* pre_b1  = (const float*)d_in[3];
    const float* pre_w2  = (const float*)d_in[4];
    const float* pre_b2  = (const float*)d_in[5];
    const float* conv_w  = (const float*)d_in[6];
    const float* conv_b  = (const float*)d_in[7];
    const float* post_w1 = (const float*)d_in[8];
    const float* post_b1 = (const float*)d_in[9];
    const float* post_w2 = (const float*)d_in[10];
    const float* post_b2 = (const float*)d_in[11];
    float* out = (float*)d_out;

    const int* src = ei;
    const int* dst = ei + NE;

    __nv_bfloat16 *ah, *al, *t, *gh, *gl, *uh, *ul;
    int *cnt, *rowptr, *fill, *col;
    float *cbt, *cbu;
    __nv_bfloat16 *wth, *wtl, *wuh, *wul;
    cudaGetSymbolAddress((void**)&ah, g_ah);   cudaGetSymbolAddress((void**)&al, g_al);
    cudaGetSymbolAddress((void**)&t, g_t);
    cudaGetSymbolAddress((void**)&gh, g_gh);   cudaGetSymbolAddress((void**)&gl, g_gl);
    cudaGetSymbolAddress((void**)&uh, g_uh);   cudaGetSymbolAddress((void**)&ul, g_ul);
    cudaGetSymbolAddress((void**)&cnt, g_cnt);
    cudaGetSymbolAddress((void**)&rowptr, g_rowptr);
    cudaGetSymbolAddress((void**)&fill, g_fill);
    cudaGetSymbolAddress((void**)&col, g_col);
    cudaGetSymbolAddress((void**)&cbt, g_cbt); cudaGetSymbolAddress((void**)&cbu, g_cbu);
    cudaGetSymbolAddress((void**)&wth, g_wth); cudaGetSymbolAddress((void**)&wtl, g_wtl);
    cudaGetSymbolAddress((void**)&wuh, g_wuh); cudaGetSymbolAddress((void**)&wul, g_wul);

    const float* P1 = post_w1;                 // rows 0..255 of [512][256]
    const float* P2 = post_w1 + 256 * 256;     // rows 256..511

    const int DSMEM = 2 * STAGE_B;  // 80 KB
    cudaFuncSetAttribute(mma_gemm<1, 2>, cudaFuncAttributeMaxDynamicSharedMemorySize, DSMEM);
    cudaFuncSetAttribute(mma_gemm<1, 0>, cudaFuncAttributeMaxDynamicSharedMemorySize, DSMEM);

    const int MT = (NN + 127) / 128;  // 391
    dim3 gg(2, MT);

    // (1) t-weights + t-bias
    compose_prep<<<dim3(4, 5), 256>>>(pre_w2, conv_w, wth, wtl, 256, 0,
                                      pre_b2, conv_b, cbt);
    // (2) pre-MLP layer 1 -> a pair
    pre_kernel<<<(NN + 31) / 32, 256>>>(x, pre_w1, pre_b1, ah, al);
    // (3) u-weights a-part + u-bias
    compose_prep<<<dim3(4, 5), 256>>>(pre_w2, P1, wuh, wul, 512, 0,
                                      pre_b2, post_b1, cbu);
    // (4) u-weights agg-part
    prep2<<<dim3(8, 8), dim3(32, 8)>>>(P2, wuh, wul, 512, 256);
    // (5) t = relu(a@Wt + bt) -> single bf16
    mma_gemm<1, 2><<<gg, 256, DSMEM>>>(ah, al, nullptr, nullptr, wth, wtl, cbt,
                                       t, nullptr, NN, 256, 256);

    // ---- CSR build + atomic-free segment sum ----
    cudaMemsetAsync(cnt, 0, NN * sizeof(int), 0);
    count_kernel<<<(NE + 255) / 256, 256>>>(dst, cnt);
    scan_kernel<<<1, 1024>>>(cnt, rowptr, fill);
    scatter_kernel<<<(NE + 255) / 256, 256>>>(src, dst, fill, col);
    agg_kernel<<<(NN + 3) / 4, 128>>>(t, rowptr, col, gh, gl);

    // ---- u = relu(a@Wp + agg@P2 + bu)  (K=512 concat) ----
    mma_gemm<1, 0><<<gg, 256, DSMEM>>>(ah, al, gh, gl, wuh, wul, cbu,
                                       uh, ul, NN, 512, 256);
    // ---- out = tanh(u@post_w2 + post_b2) ----
    out_kernel<<<(NN + 127) / 128, 256>>>(uh, ul, post_w2, post_b2, out, NN);
}

// round 12
// speedup vs baseline: 1.3300x; 1.0032x over previous
#include <cuda_runtime.h>
#include <cuda_bf16.h>
#include <cuda_fp16.h>
#include <cstdint>
#include <cstddef>

#define NN 50000
#define NE 800000
#define HID 256

// smem stage layout (bytes, pitch 80/row of 32 bf16 + pad):
// Ah[128x80]=10240 | Al=10240 | Bh[128x80]=10240 | Bl=10240
#define STAGE_B 40960

// ---------------- scratch (device globals: no allocation allowed) ----------------
__device__ __nv_bfloat16 g_ah[(size_t)NN * HID], g_al[(size_t)NN * HID];
__device__ __half g_t[(size_t)NN * HID];                        // SINGLE fp16 t (agg-only)
__device__ __nv_bfloat16 g_gh[(size_t)NN * HID], g_gl[(size_t)NN * HID];
__device__ __nv_bfloat16 g_uh[(size_t)NN * HID], g_ul[(size_t)NN * HID];
__device__ int g_cnt[NN];
__device__ int g_rowptr[NN + 1];
__device__ int g_fill[NN];
__device__ int g_col[NE];
__device__ float g_cbt[256];         // b2@Wc + conv_b
__device__ float g_cbu[256];         // b2@P1 + post_b1
__device__ __nv_bfloat16 g_wth[256 * 256], g_wtl[256 * 256];   // t-GEMM weights
__device__ __nv_bfloat16 g_wuh[256 * 512], g_wul[256 * 512];   // u-GEMM weights

// ---------------- helpers ----------------
__device__ __forceinline__ uint32_t s2u(const void* p) {
    uint32_t a;
    asm("{ .reg .u64 t; cvta.to.shared.u64 t, %1; cvt.u32.u64 %0, t; }" : "=r"(a) : "l"(p));
    return a;
}
__device__ __forceinline__ void cp16(uint32_t dst, const void* src, int srcsz) {
    asm volatile("cp.async.cg.shared.global [%0], [%1], 16, %2;"
                 :: "r"(dst), "l"(src), "r"(srcsz) : "memory");
}
#define CP_COMMIT() asm volatile("cp.async.commit_group;" ::: "memory")

__device__ __forceinline__ void ldsm4(uint32_t& r0, uint32_t& r1, uint32_t& r2, uint32_t& r3,
                                      uint32_t addr) {
    asm volatile("ldmatrix.sync.aligned.m8n8.x4.shared.b16 {%0,%1,%2,%3}, [%4];"
                 : "=r"(r0), "=r"(r1), "=r"(r2), "=r"(r3) : "r"(addr));
}

#define MMA_BF16(cc, aa, b0v, b1v)                                              \
    asm volatile(                                                               \
        "mma.sync.aligned.m16n8k16.row.col.f32.bf16.bf16.f32 "                  \
        "{%0,%1,%2,%3}, {%4,%5,%6,%7}, {%8,%9}, {%0,%1,%2,%3};"                 \
        : "+f"(cc[0]), "+f"(cc[1]), "+f"(cc[2]), "+f"(cc[3])                    \
        : "r"(aa[0]), "r"(aa[1]), "r"(aa[2]), "r"(aa[3]), "r"(b0v), "r"(b1v))

__device__ __forceinline__ uint32_t pack_bf16x2(float a, float b) {
    __nv_bfloat162 p = __float22bfloat162_rn(make_float2(a, b));
    return *reinterpret_cast<uint32_t*>(&p);
}
__device__ __forceinline__ uint32_t pack_f16x2(float a, float b) {
    __half2 p = __float22half2_rn(make_float2(a, b));
    return *reinterpret_cast<uint32_t*>(&p);
}
__device__ __forceinline__ void split_pair(float v0, float v1, uint32_t& hw, uint32_t& lw) {
    float h0 = __bfloat162float(__float2bfloat16_rn(v0));
    float h1 = __bfloat162float(__float2bfloat16_rn(v1));
    hw = pack_bf16x2(h0, h1);
    lw = pack_bf16x2(v0 - h0, v1 - h1);
}

// ---------------- fused compose+prep+bias ----------------
__global__ __launch_bounds__(256) void compose_prep(
    const float* __restrict__ A, const float* __restrict__ B,
    __nv_bfloat16* __restrict__ hi, __nv_bfloat16* __restrict__ lo,
    int kpitch, int koff,
    const float* __restrict__ b2, const float* __restrict__ badd,
    float* __restrict__ bout)
{
    const int t = threadIdx.x;
    if (blockIdx.y == 4) {
        __shared__ float red[4][64];
        int j = blockIdx.x * 64 + (t & 63);
        int ks = t >> 6;
        float acc = 0.f;
#pragma unroll 8
        for (int k = ks * 64; k < ks * 64 + 64; k++)
            acc += b2[k] * B[(size_t)k * 256 + j];
        red[ks][t & 63] = acc;
        __syncthreads();
        if (t < 64) {
            int jj = blockIdx.x * 64 + t;
            bout[jj] = red[0][t] + red[1][t] + red[2][t] + red[3][t] + badd[jj];
        }
        return;
    }

    __shared__ float As[16][64];
    __shared__ float Bs[16][64];
    const int tx = t & 15, ty = t >> 4;
    const int m0 = blockIdx.y * 64, n0 = blockIdx.x * 64;
    float acc[4][4];
#pragma unroll
    for (int i = 0; i < 4; i++)
#pragma unroll
        for (int j = 0; j < 4; j++) acc[i][j] = 0.f;

    for (int k0 = 0; k0 < 256; k0 += 16) {
#pragma unroll
        for (int i = 0; i < 4; i++) {
            int idx = t + i * 256;
            int r = idx >> 4, c = idx & 15;
            As[c][r] = A[(size_t)(m0 + r) * 256 + k0 + c];
        }
#pragma unroll
        for (int i = 0; i < 4; i++) {
            int idx = t + i * 256;
            int r = idx >> 6, c = idx & 63;
            Bs[r][c] = B[(size_t)(k0 + r) * 256 + n0 + c];
        }
        __syncthreads();
#pragma unroll
        for (int k = 0; k < 16; k++) {
            float ra[4], rb[4];
#pragma unroll
            for (int i = 0; i < 4; i++) ra[i] = As[k][ty * 4 + i];
#pragma unroll
            for (int j = 0; j < 4; j++) rb[j] = Bs[k][tx * 4 + j];
#pragma unroll
            for (int i = 0; i < 4; i++)
#pragma unroll
                for (int j = 0; j < 4; j++) acc[i][j] += ra[i] * rb[j];
        }
        __syncthreads();
    }
#pragma unroll
    for (int i = 0; i < 4; i++) {
        int kk = m0 + ty * 4 + i;
#pragma unroll
        for (int j = 0; j < 4; j++) {
            int nn = n0 + tx * 4 + j;
            float v = acc[i][j];
            __nv_bfloat16 h = __float2bfloat16_rn(v);
            hi[(size_t)nn * kpitch + koff + kk] = h;
            lo[(size_t)nn * kpitch + koff + kk] =
                __float2bfloat16_rn(v - __bfloat162float(h));
        }
    }
}

// ---------------- prep (transpose + split only, for P2) ----------------
__global__ void prep2(const float* __restrict__ W, __nv_bfloat16* __restrict__ hi,
                      __nv_bfloat16* __restrict__ lo, int kpitch, int koff) {
    __shared__ float tile[32][33];
    int k0 = blockIdx.y * 32, n0 = blockIdx.x * 32;
    int tx = threadIdx.x, ty = threadIdx.y;  // 32 x 8
    for (int i = ty; i < 32; i += 8) tile[i][tx] = W[(size_t)(k0 + i) * 256 + n0 + tx];
    __syncthreads();
    for (int i = ty; i < 32; i += 8) {
        float v = tile[tx][i];
        __nv_bfloat16 h = __float2bfloat16_rn(v);
        hi[(size_t)(n0 + i) * kpitch + koff + k0 + tx] = h;
        lo[(size_t)(n0 + i) * kpitch + koff + k0 + tx] =
            __float2bfloat16_rn(v - __bfloat162float(h));
    }
}

// ---------------- pre-MLP layer 1: a = relu(x@w1+b1), K=16, hi/lo out ---------------
__global__ __launch_bounds__(256) void pre_kernel(
    const float* __restrict__ x, const float* __restrict__ w1, const float* __restrict__ b1,
    __nv_bfloat16* __restrict__ Ch, __nv_bfloat16* __restrict__ Cl)
{
    __shared__ float ws[16 * 256];
    __shared__ float bs[256];
    const int tid = threadIdx.x;
    for (int i = tid; i < 1024; i += 256) ((float4*)ws)[i] = ((const float4*)w1)[i];
    bs[tid] = b1[tid];
    __syncthreads();

    const int warp = tid >> 5, lane = tid & 31;
#pragma unroll
    for (int r = 0; r < 4; r++) {
        int row = blockIdx.x * 32 + warp * 4 + r;
        if (row >= NN) break;
        float xv[16];
        const float4* xp = (const float4*)(x + (size_t)row * 16);
#pragma unroll
        for (int q = 0; q < 4; q++) *(float4*)&xv[q * 4] = xp[q];
        float acc[8];
#pragma unroll
        for (int j = 0; j < 8; j++) acc[j] = bs[lane + 32 * j];
#pragma unroll
        for (int k = 0; k < 16; k++) {
            float xk = xv[k];
            const float* wr = &ws[k * 256 + lane];
#pragma unroll
            for (int j = 0; j < 8; j++) acc[j] += xk * wr[32 * j];
        }
#pragma unroll
        for (int j = 0; j < 8; j++) {
            float v = fmaxf(acc[j], 0.f);
            __nv_bfloat16 h = __float2bfloat16_rn(v);
            Ch[(size_t)row * 256 + lane + 32 * j] = h;
            Cl[(size_t)row * 256 + lane + 32 * j] =
                __float2bfloat16_rn(v - __bfloat162float(h));
        }
    }
}

// ---------------- tensor-core GEMM: C = act(concat(A1,A2) @ W + bias) ----------------
// OUTMODE 0: hi/lo bf16 pair.  OUTMODE 2: single fp16 (for t).
template <int ACT, int OUTMODE>
__global__ __launch_bounds__(256, 2) void mma_gemm(
    const __nv_bfloat16* __restrict__ A1h, const __nv_bfloat16* __restrict__ A1l,
    const __nv_bfloat16* __restrict__ A2h, const __nv_bfloat16* __restrict__ A2l,
    const __nv_bfloat16* __restrict__ Wh,  const __nv_bfloat16* __restrict__ Wl,
    const float* __restrict__ bias,
    __nv_bfloat16* __restrict__ Ch, __nv_bfloat16* __restrict__ Cl,
    __half* __restrict__ Chf,
    int M, int K, int K1)
{
    extern __shared__ char smc[];
    __shared__ float sbias[128];

    const int tid = threadIdx.x;
    const int wid = tid >> 5, lane = tid & 31;
    const int g = lane >> 2, tg = lane & 3;
    const int wm = wid >> 1, wn = wid & 1;
    const int m0 = blockIdx.y * 128, n0 = blockIdx.x * 128;
    const uint32_t smc_u = s2u(smc);

    if (tid < 128) sbias[tid] = bias[n0 + tid];

    const int arow = tid >> 1;
    const int aks  = (tid & 1) * 16;
    const int gm   = m0 + arow;
    const int okA  = (gm < M) ? 16 : 0;

    const int q = lane >> 3, rr = lane & 7;
    const uint32_t aoff0 = (uint32_t)((wm * 32 + (q & 1) * 8 + rr) * 80 + (q >> 1) * 16);
    const uint32_t boff0 = (uint32_t)(20480 + (wn * 64 + (q >> 1) * 8 + rr) * 80 + (q & 1) * 16);

    float acc[2][8][4];
#pragma unroll
    for (int i = 0; i < 2; i++)
#pragma unroll
        for (int j = 0; j < 8; j++)
#pragma unroll
            for (int p = 0; p < 4; p++) acc[i][j][p] = 0.f;

    const int NC = K >> 5;

    auto STAGE = [&](int c) {
        const int ck = c * 32;
        const __nv_bfloat16 *Ah, *Al; int lda, kof;
        if (ck < K1) { Ah = A1h; Al = A1l; lda = K1;     kof = ck; }
        else         { Ah = A2h; Al = A2l; lda = K - K1; kof = ck - K1; }
        const uint32_t sb = smc_u + (uint32_t)((c & 1) * STAGE_B);
        const uint32_t da = sb + (uint32_t)(arow * 80 + (tid & 1) * 32);
        const __nv_bfloat16* pah = Ah + (size_t)gm * lda + kof + aks;
        const __nv_bfloat16* pal = Al + (size_t)gm * lda + kof + aks;
        cp16(da, pah, okA);               cp16(da + 16, pah + 8, okA);
        cp16(da + 10240, pal, okA);       cp16(da + 10240 + 16, pal + 8, okA);
        const __nv_bfloat16* pbh = Wh + (size_t)(n0 + arow) * K + ck + aks;
        const __nv_bfloat16* pbl = Wl + (size_t)(n0 + arow) * K + ck + aks;
        cp16(da + 20480, pbh, 16);        cp16(da + 20480 + 16, pbh + 8, 16);
        cp16(da + 30720, pbl, 16);        cp16(da + 30720 + 16, pbl + 8, 16);
        CP_COMMIT();
    };

    STAGE(0);

    for (int c = 0; c < NC; c++) {
        if (c + 1 < NC) {
            STAGE(c + 1);
            asm volatile("cp.async.wait_group 1;" ::: "memory");
        } else {
            asm volatile("cp.async.wait_group 0;" ::: "memory");
        }
        __syncthreads();

        const uint32_t sb = smc_u + (uint32_t)((c & 1) * STAGE_B);
#pragma unroll
        for (int ks = 0; ks < 2; ks++) {
            const uint32_t ko = (uint32_t)(ks * 32);
            uint32_t ah[2][4], bb[8][2];
            ldsm4(ah[0][0], ah[0][1], ah[0][2], ah[0][3], sb + aoff0 + ko);
            ldsm4(ah[1][0], ah[1][1], ah[1][2], ah[1][3], sb + aoff0 + 1280 + ko);
#pragma unroll
            for (int jp = 0; jp < 4; jp++)
                ldsm4(bb[2 * jp][0], bb[2 * jp][1], bb[2 * jp + 1][0], bb[2 * jp + 1][1],
                      sb + boff0 + (uint32_t)(jp * 1280) + ko);
#pragma unroll
            for (int i = 0; i < 2; i++)
#pragma unroll
                for (int j = 0; j < 8; j++) MMA_BF16(acc[i][j], ah[i], bb[j][0], bb[j][1]);

            uint32_t al[2][4];
            ldsm4(al[0][0], al[0][1], al[0][2], al[0][3], sb + 10240 + aoff0 + ko);
            ldsm4(al[1][0], al[1][1], al[1][2], al[1][3], sb + 10240 + aoff0 + 1280 + ko);
#pragma unroll
            for (int i = 0; i < 2; i++)
#pragma unroll
                for (int j = 0; j < 8; j++) MMA_BF16(acc[i][j], al[i], bb[j][0], bb[j][1]);

#pragma unroll
            for (int jp = 0; jp < 4; jp++)
                ldsm4(bb[2 * jp][0], bb[2 * jp][1], bb[2 * jp + 1][0], bb[2 * jp + 1][1],
                      sb + 10240 + boff0 + (uint32_t)(jp * 1280) + ko);
#pragma unroll
            for (int i = 0; i < 2; i++)
#pragma unroll
                for (int j = 0; j < 8; j++) MMA_BF16(acc[i][j], ah[i], bb[j][0], bb[j][1]);
        }
        __syncthreads();
    }

    // epilogue
#pragma unroll
    for (int i = 0; i < 2; i++) {
        int r0 = m0 + wm * 32 + i * 16 + g;
#pragma unroll
        for (int j = 0; j < 8; j++) {
            int cl = wn * 64 + j * 8 + tg * 2;
            float b0 = sbias[cl], b1 = sbias[cl + 1];
            float v0 = acc[i][j][0] + b0, v1 = acc[i][j][1] + b1;
            float v2 = acc[i][j][2] + b0, v3 = acc[i][j][3] + b1;
            if (ACT == 1) {
                v0 = fmaxf(v0, 0.f); v1 = fmaxf(v1, 0.f);
                v2 = fmaxf(v2, 0.f); v3 = fmaxf(v3, 0.f);
            }
            if (OUTMODE == 2) {
                if (r0 < M)
                    *(uint32_t*)(Chf + (size_t)r0 * 256 + n0 + cl) = pack_f16x2(v0, v1);
                if (r0 + 8 < M)
                    *(uint32_t*)(Chf + (size_t)(r0 + 8) * 256 + n0 + cl) = pack_f16x2(v2, v3);
            } else {
                uint32_t hw, lw;
                if (r0 < M) {
                    split_pair(v0, v1, hw, lw);
                    *(uint32_t*)(Ch + (size_t)r0 * 256 + n0 + cl) = hw;
                    *(uint32_t*)(Cl + (size_t)r0 * 256 + n0 + cl) = lw;
                }
                if (r0 + 8 < M) {
                    split_pair(v2, v3, hw, lw);
                    *(uint32_t*)(Ch + (size_t)(r0 + 8) * 256 + n0 + cl) = hw;
                    *(uint32_t*)(Cl + (size_t)(r0 + 8) * 256 + n0 + cl) = lw;
                }
            }
        }
    }
}

// ---------------- CSR build ----------------
__global__ void count_kernel(const int* __restrict__ dst, int* __restrict__ cnt) {
    int e = blockIdx.x * blockDim.x + threadIdx.x;
    if (e < NE) atomicAdd(&cnt[dst[e]], 1);
}

__global__ __launch_bounds__(1024) void scan_kernel(const int* __restrict__ cnt,
                                                    int* __restrict__ rowptr,
                                                    int* __restrict__ fill) {
    __shared__ int wsum[32];
    __shared__ int s_carry;
    const int tid = threadIdx.x, lane = tid & 31, wid = tid >> 5;
    if (tid == 0) { s_carry = 0; rowptr[0] = 0; }
    __syncthreads();
    for (int base = 0; base < NN; base += 1024) {
        int i = base + tid;
        int v = (i < NN) ? cnt[i] : 0;
        int s = v;
#pragma unroll
        for (int d = 1; d < 32; d <<= 1) {
            int y = __shfl_up_sync(0xffffffffu, s, d);
            if (lane >= d) s += y;
        }
        if (lane == 31) wsum[wid] = s;
        int carry_in = s_carry;
        __syncthreads();
        if (wid == 0) {
            int ws = wsum[lane];
#pragma unroll
            for (int d = 1; d < 32; d <<= 1) {
                int y = __shfl_up_sync(0xffffffffu, ws, d);
                if (lane >= d) ws += y;
            }
            wsum[lane] = ws;
        }
        __syncthreads();
        int off = (wid ? wsum[wid - 1] : 0) + carry_in;
        int inc = s + off;
        if (i < NN) {
            rowptr[i + 1] = inc;
            fill[i] = inc - v;
        }
        __syncthreads();
        if (tid == 1023) s_carry = inc;
        __syncthreads();
    }
}

__global__ void scatter_kernel(const int* __restrict__ src, const int* __restrict__ dst,
                               int* __restrict__ fill, int* __restrict__ col) {
    int e = blockIdx.x * blockDim.x + threadIdx.x;
    if (e < NE) {
        int slot = atomicAdd(&fill[dst[e]], 1);
        col[slot] = src[e];
    }
}

// ---------------- aggregation — single-fp16 t gather (4 nodes/block, 1 warp each) ----
__device__ __forceinline__ void acc8h(float* acc, uint4 hv) {
    const uint32_t* h = (const uint32_t*)&hv;
#pragma unroll
    for (int p = 0; p < 4; p++) {
        float2 f = __half22float2(*reinterpret_cast<const __half2*>(&h[p]));
        acc[2 * p]     += f.x;
        acc[2 * p + 1] += f.y;
    }
}

__global__ __launch_bounds__(128) void agg_kernel(
    const __half* __restrict__ t,
    const int* __restrict__ rowptr, const int* __restrict__ col,
    __nv_bfloat16* __restrict__ aggh, __nv_bfloat16* __restrict__ aggl)
{
    const int node = blockIdx.x * 4 + (threadIdx.x >> 5);
    if (node >= NN) return;
    const int tid = threadIdx.x & 31;
    const int s = rowptr[node];
    const int e = rowptr[node + 1];
    float acc[8];
#pragma unroll
    for (int p = 0; p < 8; p++) acc[p] = 0.f;

    int i = s;
    for (; i + 4 <= e; i += 4) {
        int c0 = __ldg(&col[i]),     c1 = __ldg(&col[i + 1]);
        int c2 = __ldg(&col[i + 2]), c3 = __ldg(&col[i + 3]);
        uint4 h0 = *(const uint4*)(t + (size_t)c0 * HID + tid * 8);
        uint4 h1 = *(const uint4*)(t + (size_t)c1 * HID + tid * 8);
        uint4 h2 = *(const uint4*)(t + (size_t)c2 * HID + tid * 8);
        uint4 h3 = *(const uint4*)(t + (size_t)c3 * HID + tid * 8);
        acc8h(acc, h0); acc8h(acc, h1);
        acc8h(acc, h2); acc8h(acc, h3);
    }
    for (; i < e; i++) {
        int c0 = __ldg(&col[i]);
        uint4 h0 = *(const uint4*)(t + (size_t)c0 * HID + tid * 8);
        acc8h(acc, h0);
    }

    uint32_t hw[4], lw[4];
#pragma unroll
    for (int p = 0; p < 4; p++) split_pair(acc[2 * p], acc[2 * p + 1], hw[p], lw[p]);
    *(uint4*)(aggh + (size_t)node * HID + tid * 8) = *(uint4*)hw;
    *(uint4*)(aggl + (size_t)node * HID + tid * 8) = *(uint4*)lw;
}

// ---------------- output projection: out = tanh(u @ W2 + b2) ----------------
__global__ __launch_bounds__(256) void out_kernel(
    const __nv_bfloat16* __restrict__ uh, const __nv_bfloat16* __restrict__ ul,
    const float* __restrict__ w, const float* __restrict__ b,
    float* __restrict__ out, int M)
{
    __shared__ float ws[256 * 16];
    __shared__ float bs[16];
    const int tid = threadIdx.x;
    for (int i = tid; i < 256 * 16 / 4; i += 256)
        ((float4*)ws)[i] = ((const float4*)w)[i];
    if (tid < 16) bs[tid] = b[tid];
    __syncthreads();

    const int mloc = tid >> 1;
    const int off  = (tid & 1) * 8;
    const int m = blockIdx.x * 128 + mloc;
    if (m >= M) return;

    float acc[8];
#pragma unroll
    for (int j = 0; j < 8; j++) acc[j] = bs[off + j];

    const uint4* ph = (const uint4*)(uh + (size_t)m * HID);
    const uint4* pl = (const uint4*)(ul + (size_t)m * HID);
#pragma unroll 4
    for (int kc = 0; kc < 32; kc++) {
        uint4 hv = ph[kc], lv = pl[kc];
        const uint32_t* hp = (const uint32_t*)&hv;
        const uint32_t* lp = (const uint32_t*)&lv;
        float f[8];
#pragma unroll
        for (int p = 0; p < 4; p++) {
            __nv_bfloat162 h2 = *reinterpret_cast<const __nv_bfloat162*>(&hp[p]);
            __nv_bfloat162 l2 = *reinterpret_cast<const __nv_bfloat162*>(&lp[p]);
            f[2 * p]     = __low2float(h2)  + __low2float(l2);
            f[2 * p + 1] = __high2float(h2) + __high2float(l2);
        }
#pragma unroll
        for (int qv = 0; qv < 8; qv++) {
            const float* wr = &ws[(kc * 8 + qv) * 16 + off];
#pragma unroll
            for (int j = 0; j < 8; j++) acc[j] += f[qv] * wr[j];
        }
    }
    float o[8];
#pragma unroll
    for (int j = 0; j < 8; j++) o[j] = tanhf(acc[j]);
    float* op = out + (size_t)m * 16 + off;
    *(float4*)(op)     = *(float4*)&o[0];
    *(float4*)(op + 4) = *(float4*)&o[4];
}

// ---------------- launcher ----------------
extern "C" void kernel_launch(void* const* d_in, const int* in_sizes, int n_in,
                              void* d_out, int out_size) {
    const float* x       = (const float*)d_in[0];
    const int*   ei      = (const int*)d_in[1];
    const float* pre_w1  = (const float*)d_in[2];
    const float* pre_b1  = (const float*)d_in[3];
    const float* pre_w2  = (const float*)d_in[4];
    const float* pre_b2  = (const float*)d_in[5];
    const float* conv_w  = (const float*)d_in[6];
    const float* conv_b  = (const float*)d_in[7];
    const float* post_w1 = (const float*)d_in[8];
    const float* post_b1 = (const float*)d_in[9];
    const float* post_w2 = (const float*)d_in[10];
    const float* post_b2 = (const float*)d_in[11];
    float* out = (float*)d_out;

    const int* src = ei;
    const int* dst = ei + NE;

    __nv_bfloat16 *ah, *al, *gh, *gl, *uh, *ul;
    __half* t;
    int *cnt, *rowptr, *fill, *col;
    float *cbt, *cbu;
    __nv_bfloat16 *wth, *wtl, *wuh, *wul;
    cudaGetSymbolAddress((void**)&ah, g_ah);   cudaGetSymbolAddress((void**)&al, g_al);
    cudaGetSymbolAddress((void**)&t, g_t);
    cudaGetSymbolAddress((void**)&gh, g_gh);   cudaGetSymbolAddress((void**)&gl, g_gl);
    cudaGetSymbolAddress((void**)&uh, g_uh);   cudaGetSymbolAddress((void**)&ul, g_ul);
    cudaGetSymbolAddress((void**)&cnt, g_cnt);
    cudaGetSymbolAddress((void**)&rowptr, g_rowptr);
    cudaGetSymbolAddress((void**)&fill, g_fill);
    cudaGetSymbolAddress((void**)&col, g_col);
    cudaGetSymbolAddress((void**)&cbt, g_cbt); cudaGetSymbolAddress((void**)&cbu, g_cbu);
    cudaGetSymbolAddress((void**)&wth, g_wth); cudaGetSymbolAddress((void**)&wtl, g_wtl);
    cudaGetSymbolAddress((void**)&wuh, g_wuh); cudaGetSymbolAddress((void**)&wul, g_wul);

    const float* P1 = post_w1;                 // rows 0..255 of [512][256]
    const float* P2 = post_w1 + 256 * 256;     // rows 256..511

    const int DSMEM = 2 * STAGE_B;  // 80 KB
    cudaFuncSetAttribute(mma_gemm<1, 2>, cudaFuncAttributeMaxDynamicSharedMemorySize, DSMEM);
    cudaFuncSetAttribute(mma_gemm<1, 0>, cudaFuncAttributeMaxDynamicSharedMemorySize, DSMEM);

    const int MT = (NN + 127) / 128;  // 391
    dim3 gg(2, MT);

    // (1) t-weights + t-bias
    compose_prep<<<dim3(4, 5), 256>>>(pre_w2, conv_w, wth, wtl, 256, 0,
                                      pre_b2, conv_b, cbt);
    // (2) pre-MLP layer 1 -> a pair
    pre_kernel<<<(NN + 31) / 32, 256>>>(x, pre_w1, pre_b1, ah, al);
    // (3) u-weights a-part + u-bias
    compose_prep<<<dim3(4, 5), 256>>>(pre_w2, P1, wuh, wul, 512, 0,
                                      pre_b2, post_b1, cbu);
    // (4) u-weights agg-part
    prep2<<<dim3(8, 8), dim3(32, 8)>>>(P2, wuh, wul, 512, 256);
    // (5) t = relu(a@Wt + bt) -> single fp16
    mma_gemm<1, 2><<<gg, 256, DSMEM>>>(ah, al, nullptr, nullptr, wth, wtl, cbt,
                                       nullptr, nullptr, t, NN, 256, 256);

    // ---- CSR build + atomic-free segment sum ----
    cudaMemsetAsync(cnt, 0, NN * sizeof(int), 0);
    count_kernel<<<(NE + 255) / 256, 256>>>(dst, cnt);
    scan_kernel<<<1, 1024>>>(cnt, rowptr, fill);
    scatter_kernel<<<(NE + 255) / 256, 256>>>(src, dst, fill, col);
    agg_kernel<<<(NN + 3) / 4, 128>>>(t, rowptr, col, gh, gl);

    // ---- u = relu(a@Wp + agg@P2 + bu)  (K=512 concat) ----
    mma_gemm<1, 0><<<gg, 256, DSMEM>>>(ah, al, gh, gl, wuh, wul, cbu,
                                       uh, ul, nullptr, NN, 512, 256);
    // ---- out = tanh(u@post_w2 + post_b2) ----
    out_kernel<<<(NN + 127) / 128, 256>>>(uh, ul, post_w2, post_b2, out, NN);
}

// round 13
// speedup vs baseline: 1.3822x; 1.0392x over previous
#include <cuda_runtime.h>
#include <cuda_bf16.h>
#include <cuda_fp16.h>
#include <cstdint>
#include <cstddef>

#define NN 50000
#define NE 800000
#define HID 256

// smem stage layout (bytes, pitch 80/row of 32 bf16 + pad):
// Ah[128x80]=10240 | Al=10240 | Bh[128x80]=10240 | Bl=10240
#define STAGE_B 40960

// ---------------- scratch (device globals: no allocation allowed) ----------------
__device__ __nv_bfloat16 g_ah[(size_t)NN * HID], g_al[(size_t)NN * HID];
__device__ __half g_t[(size_t)NN * HID];                        // SINGLE fp16 t (agg-only)
__device__ __nv_bfloat16 g_gh[(size_t)NN * HID], g_gl[(size_t)NN * HID];
__device__ float g_pout[(size_t)NN * 16];                       // fp32 out partials
__device__ int g_cnt[NN];
__device__ int g_rowptr[NN + 1];
__device__ int g_fill[NN];
__device__ int g_col[NE];
__device__ float g_cbt[256];         // b2@Wc + conv_b
__device__ float g_cbu[256];         // b2@P1 + post_b1
__device__ __nv_bfloat16 g_wth[256 * 256], g_wtl[256 * 256];   // t-GEMM weights
__device__ __nv_bfloat16 g_wuh[256 * 512], g_wul[256 * 512];   // u-GEMM weights

// ---------------- helpers ----------------
__device__ __forceinline__ uint32_t s2u(const void* p) {
    uint32_t a;
    asm("{ .reg .u64 t; cvta.to.shared.u64 t, %1; cvt.u32.u64 %0, t; }" : "=r"(a) : "l"(p));
    return a;
}
__device__ __forceinline__ void cp16(uint32_t dst, const void* src, int srcsz) {
    asm volatile("cp.async.cg.shared.global [%0], [%1], 16, %2;"
                 :: "r"(dst), "l"(src), "r"(srcsz) : "memory");
}
#define CP_COMMIT() asm volatile("cp.async.commit_group;" ::: "memory")

__device__ __forceinline__ void ldsm4(uint32_t& r0, uint32_t& r1, uint32_t& r2, uint32_t& r3,
                                      uint32_t addr) {
    asm volatile("ldmatrix.sync.aligned.m8n8.x4.shared.b16 {%0,%1,%2,%3}, [%4];"
                 : "=r"(r0), "=r"(r1), "=r"(r2), "=r"(r3) : "r"(addr));
}

#define MMA_BF16(cc, aa, b0v, b1v)                                              \
    asm volatile(                                                               \
        "mma.sync.aligned.m16n8k16.row.col.f32.bf16.bf16.f32 "                  \
        "{%0,%1,%2,%3}, {%4,%5,%6,%7}, {%8,%9}, {%0,%1,%2,%3};"                 \
        : "+f"(cc[0]), "+f"(cc[1]), "+f"(cc[2]), "+f"(cc[3])                    \
        : "r"(aa[0]), "r"(aa[1]), "r"(aa[2]), "r"(aa[3]), "r"(b0v), "r"(b1v))

__device__ __forceinline__ uint32_t pack_bf16x2(float a, float b) {
    __nv_bfloat162 p = __float22bfloat162_rn(make_float2(a, b));
    return *reinterpret_cast<uint32_t*>(&p);
}
__device__ __forceinline__ uint32_t pack_f16x2(float a, float b) {
    __half2 p = __float22half2_rn(make_float2(a, b));
    return *reinterpret_cast<uint32_t*>(&p);
}
__device__ __forceinline__ void split_pair(float v0, float v1, uint32_t& hw, uint32_t& lw) {
    float h0 = __bfloat162float(__float2bfloat16_rn(v0));
    float h1 = __bfloat162float(__float2bfloat16_rn(v1));
    hw = pack_bf16x2(h0, h1);
    lw = pack_bf16x2(v0 - h0, v1 - h1);
}

// ---------------- fused compose+prep+bias ----------------
__global__ __launch_bounds__(256) void compose_prep(
    const float* __restrict__ A, const float* __restrict__ B,
    __nv_bfloat16* __restrict__ hi, __nv_bfloat16* __restrict__ lo,
    int kpitch, int koff,
    const float* __restrict__ b2, const float* __restrict__ badd,
    float* __restrict__ bout)
{
    const int t = threadIdx.x;
    if (blockIdx.y == 4) {
        __shared__ float red[4][64];
        int j = blockIdx.x * 64 + (t & 63);
        int ks = t >> 6;
        float acc = 0.f;
#pragma unroll 8
        for (int k = ks * 64; k < ks * 64 + 64; k++)
            acc += b2[k] * B[(size_t)k * 256 + j];
        red[ks][t & 63] = acc;
        __syncthreads();
        if (t < 64) {
            int jj = blockIdx.x * 64 + t;
            bout[jj] = red[0][t] + red[1][t] + red[2][t] + red[3][t] + badd[jj];
        }
        return;
    }

    __shared__ float As[16][64];
    __shared__ float Bs[16][64];
    const int tx = t & 15, ty = t >> 4;
    const int m0 = blockIdx.y * 64, n0 = blockIdx.x * 64;
    float acc[4][4];
#pragma unroll
    for (int i = 0; i < 4; i++)
#pragma unroll
        for (int j = 0; j < 4; j++) acc[i][j] = 0.f;

    for (int k0 = 0; k0 < 256; k0 += 16) {
#pragma unroll
        for (int i = 0; i < 4; i++) {
            int idx = t + i * 256;
            int r = idx >> 4, c = idx & 15;
            As[c][r] = A[(size_t)(m0 + r) * 256 + k0 + c];
        }
#pragma unroll
        for (int i = 0; i < 4; i++) {
            int idx = t + i * 256;
            int r = idx >> 6, c = idx & 63;
            Bs[r][c] = B[(size_t)(k0 + r) * 256 + n0 + c];
        }
        __syncthreads();
#pragma unroll
        for (int k = 0; k < 16; k++) {
            float ra[4], rb[4];
#pragma unroll
            for (int i = 0; i < 4; i++) ra[i] = As[k][ty * 4 + i];
#pragma unroll
            for (int j = 0; j < 4; j++) rb[j] = Bs[k][tx * 4 + j];
#pragma unroll
            for (int i = 0; i < 4; i++)
#pragma unroll
                for (int j = 0; j < 4; j++) acc[i][j] += ra[i] * rb[j];
        }
        __syncthreads();
    }
#pragma unroll
    for (int i = 0; i < 4; i++) {
        int kk = m0 + ty * 4 + i;
#pragma unroll
        for (int j = 0; j < 4; j++) {
            int nn = n0 + tx * 4 + j;
            float v = acc[i][j];
            __nv_bfloat16 h = __float2bfloat16_rn(v);
            hi[(size_t)nn * kpitch + koff + kk] = h;
            lo[(size_t)nn * kpitch + koff + kk] =
                __float2bfloat16_rn(v - __bfloat162float(h));
        }
    }
}

// ---------------- prep (transpose + split only, for P2) ----------------
__global__ void prep2(const float* __restrict__ W, __nv_bfloat16* __restrict__ hi,
                      __nv_bfloat16* __restrict__ lo, int kpitch, int koff) {
    __shared__ float tile[32][33];
    int k0 = blockIdx.y * 32, n0 = blockIdx.x * 32;
    int tx = threadIdx.x, ty = threadIdx.y;  // 32 x 8
    for (int i = ty; i < 32; i += 8) tile[i][tx] = W[(size_t)(k0 + i) * 256 + n0 + tx];
    __syncthreads();
    for (int i = ty; i < 32; i += 8) {
        float v = tile[tx][i];
        __nv_bfloat16 h = __float2bfloat16_rn(v);
        hi[(size_t)(n0 + i) * kpitch + koff + k0 + tx] = h;
        lo[(size_t)(n0 + i) * kpitch + koff + k0 + tx] =
            __float2bfloat16_rn(v - __bfloat162float(h));
    }
}

// ---------------- pre-MLP layer 1: a = relu(x@w1+b1), K=16, hi/lo out ---------------
__global__ __launch_bounds__(256) void pre_kernel(
    const float* __restrict__ x, const float* __restrict__ w1, const float* __restrict__ b1,
    __nv_bfloat16* __restrict__ Ch, __nv_bfloat16* __restrict__ Cl)
{
    __shared__ float ws[16 * 256];
    __shared__ float bs[256];
    const int tid = threadIdx.x;
    for (int i = tid; i < 1024; i += 256) ((float4*)ws)[i] = ((const float4*)w1)[i];
    bs[tid] = b1[tid];
    __syncthreads();

    const int warp = tid >> 5, lane = tid & 31;
#pragma unroll
    for (int r = 0; r < 4; r++) {
        int row = blockIdx.x * 32 + warp * 4 + r;
        if (row >= NN) break;
        float xv[16];
        const float4* xp = (const float4*)(x + (size_t)row * 16);
#pragma unroll
        for (int q = 0; q < 4; q++) *(float4*)&xv[q * 4] = xp[q];
        float acc[8];
#pragma unroll
        for (int j = 0; j < 8; j++) acc[j] = bs[lane + 32 * j];
#pragma unroll
        for (int k = 0; k < 16; k++) {
            float xk = xv[k];
            const float* wr = &ws[k * 256 + lane];
#pragma unroll
            for (int j = 0; j < 8; j++) acc[j] += xk * wr[32 * j];
        }
#pragma unroll
        for (int j = 0; j < 8; j++) {
            float v = fmaxf(acc[j], 0.f);
            __nv_bfloat16 h = __float2bfloat16_rn(v);
            Ch[(size_t)row * 256 + lane + 32 * j] = h;
            Cl[(size_t)row * 256 + lane + 32 * j] =
                __float2bfloat16_rn(v - __bfloat162float(h));
        }
    }
}

// ---------------- tensor-core GEMM: C = act(concat(A1,A2) @ W + bias) ----------------
// OUTMODE 2: single fp16 (t).  OUTMODE 3: fused out-projection -> atomic fp32 partials.
template <int ACT, int OUTMODE>
__global__ __launch_bounds__(256, 2) void mma_gemm(
    const __nv_bfloat16* __restrict__ A1h, const __nv_bfloat16* __restrict__ A1l,
    const __nv_bfloat16* __restrict__ A2h, const __nv_bfloat16* __restrict__ A2l,
    const __nv_bfloat16* __restrict__ Wh,  const __nv_bfloat16* __restrict__ Wl,
    const float* __restrict__ bias,
    __half* __restrict__ Chf,
    const float* __restrict__ W2, float* __restrict__ Pout,
    int M, int K, int K1)
{
    extern __shared__ char smc[];
    __shared__ float sbias[128];

    const int tid = threadIdx.x;
    const int wid = tid >> 5, lane = tid & 31;
    const int g = lane >> 2, tg = lane & 3;
    const int wm = wid >> 1, wn = wid & 1;
    const int m0 = blockIdx.y * 128, n0 = blockIdx.x * 128;
    const uint32_t smc_u = s2u(smc);

    if (tid < 128) sbias[tid] = bias[n0 + tid];

    const int arow = tid >> 1;
    const int aks  = (tid & 1) * 16;
    const int gm   = m0 + arow;
    const int okA  = (gm < M) ? 16 : 0;

    const int q = lane >> 3, rr = lane & 7;
    const uint32_t aoff0 = (uint32_t)((wm * 32 + (q & 1) * 8 + rr) * 80 + (q >> 1) * 16);
    const uint32_t boff0 = (uint32_t)(20480 + (wn * 64 + (q >> 1) * 8 + rr) * 80 + (q & 1) * 16);

    float acc[2][8][4];
#pragma unroll
    for (int i = 0; i < 2; i++)
#pragma unroll
        for (int j = 0; j < 8; j++)
#pragma unroll
            for (int p = 0; p < 4; p++) acc[i][j][p] = 0.f;

    const int NC = K >> 5;

    auto STAGE = [&](int c) {
        const int ck = c * 32;
        const __nv_bfloat16 *Ah, *Al; int lda, kof;
        if (ck < K1) { Ah = A1h; Al = A1l; lda = K1;     kof = ck; }
        else         { Ah = A2h; Al = A2l; lda = K - K1; kof = ck - K1; }
        const uint32_t sb = smc_u + (uint32_t)((c & 1) * STAGE_B);
        const uint32_t da = sb + (uint32_t)(arow * 80 + (tid & 1) * 32);
        const __nv_bfloat16* pah = Ah + (size_t)gm * lda + kof + aks;
        const __nv_bfloat16* pal = Al + (size_t)gm * lda + kof + aks;
        cp16(da, pah, okA);               cp16(da + 16, pah + 8, okA);
        cp16(da + 10240, pal, okA);       cp16(da + 10240 + 16, pal + 8, okA);
        const __nv_bfloat16* pbh = Wh + (size_t)(n0 + arow) * K + ck + aks;
        const __nv_bfloat16* pbl = Wl + (size_t)(n0 + arow) * K + ck + aks;
        cp16(da + 20480, pbh, 16);        cp16(da + 20480 + 16, pbh + 8, 16);
        cp16(da + 30720, pbl, 16);        cp16(da + 30720 + 16, pbl + 8, 16);
        CP_COMMIT();
    };

    STAGE(0);

    for (int c = 0; c < NC; c++) {
        if (c + 1 < NC) {
            STAGE(c + 1);
            asm volatile("cp.async.wait_group 1;" ::: "memory");
        } else {
            asm volatile("cp.async.wait_group 0;" ::: "memory");
        }
        __syncthreads();

        const uint32_t sb = smc_u + (uint32_t)((c & 1) * STAGE_B);
#pragma unroll
        for (int ks = 0; ks < 2; ks++) {
            const uint32_t ko = (uint32_t)(ks * 32);
            uint32_t ah[2][4], bb[8][2];
            ldsm4(ah[0][0], ah[0][1], ah[0][2], ah[0][3], sb + aoff0 + ko);
            ldsm4(ah[1][0], ah[1][1], ah[1][2], ah[1][3], sb + aoff0 + 1280 + ko);
#pragma unroll
            for (int jp = 0; jp < 4; jp++)
                ldsm4(bb[2 * jp][0], bb[2 * jp][1], bb[2 * jp + 1][0], bb[2 * jp + 1][1],
                      sb + boff0 + (uint32_t)(jp * 1280) + ko);
#pragma unroll
            for (int i = 0; i < 2; i++)
#pragma unroll
                for (int j = 0; j < 8; j++) MMA_BF16(acc[i][j], ah[i], bb[j][0], bb[j][1]);

            uint32_t al[2][4];
            ldsm4(al[0][0], al[0][1], al[0][2], al[0][3], sb + 10240 + aoff0 + ko);
            ldsm4(al[1][0], al[1][1], al[1][2], al[1][3], sb + 10240 + aoff0 + 1280 + ko);
#pragma unroll
            for (int i = 0; i < 2; i++)
#pragma unroll
                for (int j = 0; j < 8; j++) MMA_BF16(acc[i][j], al[i], bb[j][0], bb[j][1]);

#pragma unroll
            for (int jp = 0; jp < 4; jp++)
                ldsm4(bb[2 * jp][0], bb[2 * jp][1], bb[2 * jp + 1][0], bb[2 * jp + 1][1],
                      sb + 10240 + boff0 + (uint32_t)(jp * 1280) + ko);
#pragma unroll
            for (int i = 0; i < 2; i++)
#pragma unroll
                for (int j = 0; j < 8; j++) MMA_BF16(acc[i][j], ah[i], bb[j][0], bb[j][1]);
        }
        __syncthreads();
    }

    if (OUTMODE == 2) {
        // t path: bias + relu + single fp16 store
#pragma unroll
        for (int i = 0; i < 2; i++) {
            int r0 = m0 + wm * 32 + i * 16 + g;
#pragma unroll
            for (int j = 0; j < 8; j++) {
                int cl = wn * 64 + j * 8 + tg * 2;
                float b0 = sbias[cl], b1 = sbias[cl + 1];
                float v0 = acc[i][j][0] + b0, v1 = acc[i][j][1] + b1;
                float v2 = acc[i][j][2] + b0, v3 = acc[i][j][3] + b1;
                if (ACT == 1) {
                    v0 = fmaxf(v0, 0.f); v1 = fmaxf(v1, 0.f);
                    v2 = fmaxf(v2, 0.f); v3 = fmaxf(v3, 0.f);
                }
                if (r0 < M)
                    *(uint32_t*)(Chf + (size_t)r0 * 256 + n0 + cl) = pack_f16x2(v0, v1);
                if (r0 + 8 < M)
                    *(uint32_t*)(Chf + (size_t)(r0 + 8) * 256 + n0 + cl) = pack_f16x2(v2, v3);
            }
        }
    } else {
        // u path: park u-tile in smem (fp32, pitch 129), then fused out-projection
        float* ut = (float*)smc;
#pragma unroll
        for (int i = 0; i < 2; i++) {
            int rl = wm * 32 + i * 16 + g;
#pragma unroll
            for (int j = 0; j < 8; j++) {
                int cl = wn * 64 + j * 8 + tg * 2;
                float b0 = sbias[cl], b1 = sbias[cl + 1];
                float v0 = acc[i][j][0] + b0, v1 = acc[i][j][1] + b1;
                float v2 = acc[i][j][2] + b0, v3 = acc[i][j][3] + b1;
                if (ACT == 1) {
                    v0 = fmaxf(v0, 0.f); v1 = fmaxf(v1, 0.f);
                    v2 = fmaxf(v2, 0.f); v3 = fmaxf(v3, 0.f);
                }
                ut[rl * 129 + cl]       = v0;
                ut[rl * 129 + cl + 1]   = v1;
                ut[(rl + 8) * 129 + cl]     = v2;
                ut[(rl + 8) * 129 + cl + 1] = v3;
            }
        }
        __shared__ float w2s[128 * 16];
        for (int i = tid; i < 128 * 16 / 4; i += 256)
            ((float4*)w2s)[i] = ((const float4*)(W2 + (size_t)n0 * 16))[i];
        __syncthreads();

        const int row = tid >> 1;
        const int off = (tid & 1) * 8;
        const int gr = m0 + row;
        if (gr < M) {
            float o[8];
#pragma unroll
            for (int j = 0; j < 8; j++) o[j] = 0.f;
#pragma unroll 4
            for (int c = 0; c < 128; c++) {
                float uv = ut[row * 129 + c];
                const float* wr = &w2s[c * 16 + off];
#pragma unroll
                for (int j = 0; j < 8; j++) o[j] += uv * wr[j];
            }
            float* pp = Pout + (size_t)gr * 16 + off;
#pragma unroll
            for (int j = 0; j < 8; j++) atomicAdd(&pp[j], o[j]);
        }
    }
}

// ---------------- final: out = tanh(partial + b2) ----------------
__global__ __launch_bounds__(256) void tanh_kernel(const float* __restrict__ pout,
                                                   const float* __restrict__ b2,
                                                   float* __restrict__ out) {
    __shared__ float bs[16];
    if (threadIdx.x < 16) bs[threadIdx.x] = b2[threadIdx.x];
    __syncthreads();
    int idx = blockIdx.x * 256 + threadIdx.x;   // float4 index
    if (idx < NN * 4) {
        float4 v = ((const float4*)pout)[idx];
        int jb = (idx & 3) * 4;
        v.x = tanhf(v.x + bs[jb]);
        v.y = tanhf(v.y + bs[jb + 1]);
        v.z = tanhf(v.z + bs[jb + 2]);
        v.w = tanhf(v.w + bs[jb + 3]);
        ((float4*)out)[idx] = v;
    }
}

// ---------------- CSR build ----------------
__global__ void count_kernel(const int* __restrict__ dst, int* __restrict__ cnt) {
    int e = blockIdx.x * blockDim.x + threadIdx.x;
    if (e < NE) atomicAdd(&cnt[dst[e]], 1);
}

__global__ __launch_bounds__(1024) void scan_kernel(const int* __restrict__ cnt,
                                                    int* __restrict__ rowptr,
                                                    int* __restrict__ fill) {
    __shared__ int wsum[32];
    __shared__ int s_carry;
    const int tid = threadIdx.x, lane = tid & 31, wid = tid >> 5;
    if (tid == 0) { s_carry = 0; rowptr[0] = 0; }
    __syncthreads();
    for (int base = 0; base < NN; base += 1024) {
        int i = base + tid;
        int v = (i < NN) ? cnt[i] : 0;
        int s = v;
#pragma unroll
        for (int d = 1; d < 32; d <<= 1) {
            int y = __shfl_up_sync(0xffffffffu, s, d);
            if (lane >= d) s += y;
        }
        if (lane == 31) wsum[wid] = s;
        int carry_in = s_carry;
        __syncthreads();
        if (wid == 0) {
            int ws = wsum[lane];
#pragma unroll
            for (int d = 1; d < 32; d <<= 1) {
                int y = __shfl_up_sync(0xffffffffu, ws, d);
                if (lane >= d) ws += y;
            }
            wsum[lane] = ws;
        }
        __syncthreads();
        int off = (wid ? wsum[wid - 1] : 0) + carry_in;
        int inc = s + off;
        if (i < NN) {
            rowptr[i + 1] = inc;
            fill[i] = inc - v;
        }
        __syncthreads();
        if (tid == 1023) s_carry = inc;
        __syncthreads();
    }
}

__global__ void scatter_kernel(const int* __restrict__ src, const int* __restrict__ dst,
                               int* __restrict__ fill, int* __restrict__ col) {
    int e = blockIdx.x * blockDim.x + threadIdx.x;
    if (e < NE) {
        int slot = atomicAdd(&fill[dst[e]], 1);
        col[slot] = src[e];
    }
}

// ---------------- aggregation — single-fp16 t gather (4 nodes/block, 1 warp each) ----
__device__ __forceinline__ void acc8h(float* acc, uint4 hv) {
    const uint32_t* h = (const uint32_t*)&hv;
#pragma unroll
    for (int p = 0; p < 4; p++) {
        float2 f = __half22float2(*reinterpret_cast<const __half2*>(&h[p]));
        acc[2 * p]     += f.x;
        acc[2 * p + 1] += f.y;
    }
}

__global__ __launch_bounds__(128) void agg_kernel(
    const __half* __restrict__ t,
    const int* __restrict__ rowptr, const int* __restrict__ col,
    __nv_bfloat16* __restrict__ aggh, __nv_bfloat16* __restrict__ aggl)
{
    const int node = blockIdx.x * 4 + (threadIdx.x >> 5);
    if (node >= NN) return;
    const int tid = threadIdx.x & 31;
    const int s = rowptr[node];
    const int e = rowptr[node + 1];
    float acc[8];
#pragma unroll
    for (int p = 0; p < 8; p++) acc[p] = 0.f;

    int i = s;
    for (; i + 4 <= e; i += 4) {
        int c0 = __ldg(&col[i]),     c1 = __ldg(&col[i + 1]);
        int c2 = __ldg(&col[i + 2]), c3 = __ldg(&col[i + 3]);
        uint4 h0 = *(const uint4*)(t + (size_t)c0 * HID + tid * 8);
        uint4 h1 = *(const uint4*)(t + (size_t)c1 * HID + tid * 8);
        uint4 h2 = *(const uint4*)(t + (size_t)c2 * HID + tid * 8);
        uint4 h3 = *(const uint4*)(t + (size_t)c3 * HID + tid * 8);
        acc8h(acc, h0); acc8h(acc, h1);
        acc8h(acc, h2); acc8h(acc, h3);
    }
    for (; i < e; i++) {
        int c0 = __ldg(&col[i]);
        uint4 h0 = *(const uint4*)(t + (size_t)c0 * HID + tid * 8);
        acc8h(acc, h0);
    }

    uint32_t hw[4], lw[4];
#pragma unroll
    for (int p = 0; p < 4; p++) split_pair(acc[2 * p], acc[2 * p + 1], hw[p], lw[p]);
    *(uint4*)(aggh + (size_t)node * HID + tid * 8) = *(uint4*)hw;
    *(uint4*)(aggl + (size_t)node * HID + tid * 8) = *(uint4*)lw;
}

// ---------------- launcher ----------------
extern "C" void kernel_launch(void* const* d_in, const int* in_sizes, int n_in,
                              void* d_out, int out_size) {
    const float* x       = (const float*)d_in[0];
    const int*   ei      = (const int*)d_in[1];
    const float* pre_w1  = (const float*)d_in[2];
    const float* pre_b1  = (const float*)d_in[3];
    const float* pre_w2  = (const float*)d_in[4];
    const float* pre_b2  = (const float*)d_in[5];
    const float* conv_w  = (const float*)d_in[6];
    const float* conv_b  = (const float*)d_in[7];
    const float* post_w1 = (const float*)d_in[8];
    const float* post_b1 = (const float*)d_in[9];
    const float* post_w2 = (const float*)d_in[10];
    const float* post_b2 = (const float*)d_in[11];
    float* out = (float*)d_out;

    const int* src = ei;
    const int* dst = ei + NE;

    __nv_bfloat16 *ah, *al, *gh, *gl;
    __half* t;
    float* pout;
    int *cnt, *rowptr, *fill, *col;
    float *cbt, *cbu;
    __nv_bfloat16 *wth, *wtl, *wuh, *wul;
    cudaGetSymbolAddress((void**)&ah, g_ah);   cudaGetSymbolAddress((void**)&al, g_al);
    cudaGetSymbolAddress((void**)&t, g_t);
    cudaGetSymbolAddress((void**)&gh, g_gh);   cudaGetSymbolAddress((void**)&gl, g_gl);
    cudaGetSymbolAddress((void**)&pout, g_pout);
    cudaGetSymbolAddress((void**)&cnt, g_cnt);
    cudaGetSymbolAddress((void**)&rowptr, g_rowptr);
    cudaGetSymbolAddress((void**)&fill, g_fill);
    cudaGetSymbolAddress((void**)&col, g_col);
    cudaGetSymbolAddress((void**)&cbt, g_cbt); cudaGetSymbolAddress((void**)&cbu, g_cbu);
    cudaGetSymbolAddress((void**)&wth, g_wth); cudaGetSymbolAddress((void**)&wtl, g_wtl);
    cudaGetSymbolAddress((void**)&wuh, g_wuh); cudaGetSymbolAddress((void**)&wul, g_wul);

    const float* P1 = post_w1;                 // rows 0..255 of [512][256]
    const float* P2 = post_w1 + 256 * 256;     // rows 256..511

    const int DSMEM = 2 * STAGE_B;  // 80 KB (>= 128*129*4 = 66048 for u-tile park)
    cudaFuncSetAttribute(mma_gemm<1, 2>, cudaFuncAttributeMaxDynamicSharedMemorySize, DSMEM);
    cudaFuncSetAttribute(mma_gemm<1, 3>, cudaFuncAttributeMaxDynamicSharedMemorySize, DSMEM);

    const int MT = (NN + 127) / 128;  // 391
    dim3 gg(2, MT);

    // (1) t-weights + t-bias
    compose_prep<<<dim3(4, 5), 256>>>(pre_w2, conv_w, wth, wtl, 256, 0,
                                      pre_b2, conv_b, cbt);
    // (2) pre-MLP layer 1 -> a pair
    pre_kernel<<<(NN + 31) / 32, 256>>>(x, pre_w1, pre_b1, ah, al);
    // (3) u-weights a-part + u-bias
    compose_prep<<<dim3(4, 5), 256>>>(pre_w2, P1, wuh, wul, 512, 0,
                                      pre_b2, post_b1, cbu);
    // (4) u-weights agg-part
    prep2<<<dim3(8, 8), dim3(32, 8)>>>(P2, wuh, wul, 512, 256);
    // (5) t = relu(a@Wt + bt) -> single fp16
    mma_gemm<1, 2><<<gg, 256, DSMEM>>>(ah, al, nullptr, nullptr, wth, wtl, cbt,
                                       t, nullptr, nullptr, NN, 256, 256);

    // ---- CSR build + atomic-free segment sum ----
    cudaMemsetAsync(cnt, 0, NN * sizeof(int), 0);
    cudaMemsetAsync(pout, 0, (size_t)NN * 16 * sizeof(float), 0);
    count_kernel<<<(NE + 255) / 256, 256>>>(dst, cnt);
    scan_kernel<<<1, 1024>>>(cnt, rowptr, fill);
    scatter_kernel<<<(NE + 255) / 256, 256>>>(src, dst, fill, col);
    agg_kernel<<<(NN + 3) / 4, 128>>>(t, rowptr, col, gh, gl);

    // ---- u = relu(a@Wp + agg@P2 + bu), fused out-projection -> pout partials ----
    mma_gemm<1, 3><<<gg, 256, DSMEM>>>(ah, al, gh, gl, wuh, wul, cbu,
                                       nullptr, post_w2, pout, NN, 512, 256);
    // ---- out = tanh(pout + b2) ----
    tanh_kernel<<<(NN * 4 + 255) / 256, 256>>>(pout, post_b2, out);
}

// round 14
// speedup vs baseline: 1.4626x; 1.0582x over previous
#include <cuda_runtime.h>
#include <cuda_bf16.h>
#include <cuda_fp16.h>
#include <cstdint>
#include <cstddef>

#define NN 50000
#define NE 800000
#define HID 256

// smem stage layout (bytes, pitch 80/row of 32 halfwords + pad):
// A_hi[128x80]=10240 | A_lo=10240 | B_hi[128x80]=10240 | B_lo=10240
#define STAGE_B 40960

// ---------------- scratch (device globals: no allocation allowed) ----------------
__device__ __nv_bfloat16 g_ah[(size_t)NN * HID], g_al[(size_t)NN * HID];
__device__ __half g_t[(size_t)NN * HID];                        // single fp16 t
__device__ __half g_g[(size_t)NN * HID];                        // single fp16 agg
__device__ float g_pout[(size_t)NN * 16];                       // fp32 out partials
__device__ int g_cnt[NN];
__device__ int g_rowptr[NN + 1];
__device__ int g_fill[NN];
__device__ int g_col[NE];
__device__ float g_cbt[256];         // b2@Wc + conv_b
__device__ float g_cbu[256];         // b2@P1 + post_b1
__device__ __nv_bfloat16 g_wth[256 * 256], g_wtl[256 * 256];   // t-GEMM weights (bf16)
// u-GEMM weights: k<256 bf16 hi/lo (W2@P1), k>=256 fp16 hi/lo (P2) — same 16-bit storage
__device__ __nv_bfloat16 g_wuh[256 * 512], g_wul[256 * 512];

// ---------------- helpers ----------------
__device__ __forceinline__ uint32_t s2u(const void* p) {
    uint32_t a;
    asm("{ .reg .u64 t; cvta.to.shared.u64 t, %1; cvt.u32.u64 %0, t; }" : "=r"(a) : "l"(p));
    return a;
}
__device__ __forceinline__ void cp16(uint32_t dst, const void* src, int srcsz) {
    asm volatile("cp.async.cg.shared.global [%0], [%1], 16, %2;"
                 :: "r"(dst), "l"(src), "r"(srcsz) : "memory");
}
#define CP_COMMIT() asm volatile("cp.async.commit_group;" ::: "memory")

__device__ __forceinline__ void ldsm4(uint32_t& r0, uint32_t& r1, uint32_t& r2, uint32_t& r3,
                                      uint32_t addr) {
    asm volatile("ldmatrix.sync.aligned.m8n8.x4.shared.b16 {%0,%1,%2,%3}, [%4];"
                 : "=r"(r0), "=r"(r1), "=r"(r2), "=r"(r3) : "r"(addr));
}

#define MMA_BF16(cc, aa, b0v, b1v)                                              \
    asm volatile(                                                               \
        "mma.sync.aligned.m16n8k16.row.col.f32.bf16.bf16.f32 "                  \
        "{%0,%1,%2,%3}, {%4,%5,%6,%7}, {%8,%9}, {%0,%1,%2,%3};"                 \
        : "+f"(cc[0]), "+f"(cc[1]), "+f"(cc[2]), "+f"(cc[3])                    \
        : "r"(aa[0]), "r"(aa[1]), "r"(aa[2]), "r"(aa[3]), "r"(b0v), "r"(b1v))

#define MMA_F16(cc, aa, b0v, b1v)                                               \
    asm volatile(                                                               \
        "mma.sync.aligned.m16n8k16.row.col.f32.f16.f16.f32 "                    \
        "{%0,%1,%2,%3}, {%4,%5,%6,%7}, {%8,%9}, {%0,%1,%2,%3};"                 \
        : "+f"(cc[0]), "+f"(cc[1]), "+f"(cc[2]), "+f"(cc[3])                    \
        : "r"(aa[0]), "r"(aa[1]), "r"(aa[2]), "r"(aa[3]), "r"(b0v), "r"(b1v))

__device__ __forceinline__ uint32_t pack_bf16x2(float a, float b) {
    __nv_bfloat162 p = __float22bfloat162_rn(make_float2(a, b));
    return *reinterpret_cast<uint32_t*>(&p);
}
__device__ __forceinline__ uint32_t pack_f16x2(float a, float b) {
    __half2 p = __float22half2_rn(make_float2(a, b));
    return *reinterpret_cast<uint32_t*>(&p);
}
__device__ __forceinline__ void split_pair(float v0, float v1, uint32_t& hw, uint32_t& lw) {
    float h0 = __bfloat162float(__float2bfloat16_rn(v0));
    float h1 = __bfloat162float(__float2bfloat16_rn(v1));
    hw = pack_bf16x2(h0, h1);
    lw = pack_bf16x2(v0 - h0, v1 - h1);
}

// ---------------- fused compose+prep+bias (bf16 hi/lo out) ----------------
__global__ __launch_bounds__(256) void compose_prep(
    const float* __restrict__ A, const float* __restrict__ B,
    __nv_bfloat16* __restrict__ hi, __nv_bfloat16* __restrict__ lo,
    int kpitch, int koff,
    const float* __restrict__ b2, const float* __restrict__ badd,
    float* __restrict__ bout)
{
    const int t = threadIdx.x;
    if (blockIdx.y == 4) {
        __shared__ float red[4][64];
        int j = blockIdx.x * 64 + (t & 63);
        int ks = t >> 6;
        float acc = 0.f;
#pragma unroll 8
        for (int k = ks * 64; k < ks * 64 + 64; k++)
            acc += b2[k] * B[(size_t)k * 256 + j];
        red[ks][t & 63] = acc;
        __syncthreads();
        if (t < 64) {
            int jj = blockIdx.x * 64 + t;
            bout[jj] = red[0][t] + red[1][t] + red[2][t] + red[3][t] + badd[jj];
        }
        return;
    }

    __shared__ float As[16][64];
    __shared__ float Bs[16][64];
    const int tx = t & 15, ty = t >> 4;
    const int m0 = blockIdx.y * 64, n0 = blockIdx.x * 64;
    float acc[4][4];
#pragma unroll
    for (int i = 0; i < 4; i++)
#pragma unroll
        for (int j = 0; j < 4; j++) acc[i][j] = 0.f;

    for (int k0 = 0; k0 < 256; k0 += 16) {
#pragma unroll
        for (int i = 0; i < 4; i++) {
            int idx = t + i * 256;
            int r = idx >> 4, c = idx & 15;
            As[c][r] = A[(size_t)(m0 + r) * 256 + k0 + c];
        }
#pragma unroll
        for (int i = 0; i < 4; i++) {
            int idx = t + i * 256;
            int r = idx >> 6, c = idx & 63;
            Bs[r][c] = B[(size_t)(k0 + r) * 256 + n0 + c];
        }
        __syncthreads();
#pragma unroll
        for (int k = 0; k < 16; k++) {
            float ra[4], rb[4];
#pragma unroll
            for (int i = 0; i < 4; i++) ra[i] = As[k][ty * 4 + i];
#pragma unroll
            for (int j = 0; j < 4; j++) rb[j] = Bs[k][tx * 4 + j];
#pragma unroll
            for (int i = 0; i < 4; i++)
#pragma unroll
                for (int j = 0; j < 4; j++) acc[i][j] += ra[i] * rb[j];
        }
        __syncthreads();
    }
#pragma unroll
    for (int i = 0; i < 4; i++) {
        int kk = m0 + ty * 4 + i;
#pragma unroll
        for (int j = 0; j < 4; j++) {
            int nn = n0 + tx * 4 + j;
            float v = acc[i][j];
            __nv_bfloat16 h = __float2bfloat16_rn(v);
            hi[(size_t)nn * kpitch + koff + kk] = h;
            lo[(size_t)nn * kpitch + koff + kk] =
                __float2bfloat16_rn(v - __bfloat162float(h));
        }
    }
}

// ---------------- prep for P2: transpose + fp16 hi/lo split ----------------
__global__ void prep2h(const float* __restrict__ W, __half* __restrict__ hi,
                       __half* __restrict__ lo, int kpitch, int koff) {
    __shared__ float tile[32][33];
    int k0 = blockIdx.y * 32, n0 = blockIdx.x * 32;
    int tx = threadIdx.x, ty = threadIdx.y;  // 32 x 8
    for (int i = ty; i < 32; i += 8) tile[i][tx] = W[(size_t)(k0 + i) * 256 + n0 + tx];
    __syncthreads();
    for (int i = ty; i < 32; i += 8) {
        float v = tile[tx][i];
        __half h = __float2half_rn(v);
        hi[(size_t)(n0 + i) * kpitch + koff + k0 + tx] = h;
        lo[(size_t)(n0 + i) * kpitch + koff + k0 + tx] =
            __float2half_rn(v - __half2float(h));
    }
}

// ---------------- pre-MLP layer 1: a = relu(x@w1+b1), K=16, bf16 hi/lo out -----------
__global__ __launch_bounds__(256) void pre_kernel(
    const float* __restrict__ x, const float* __restrict__ w1, const float* __restrict__ b1,
    __nv_bfloat16* __restrict__ Ch, __nv_bfloat16* __restrict__ Cl)
{
    __shared__ float ws[16 * 256];
    __shared__ float bs[256];
    const int tid = threadIdx.x;
    for (int i = tid; i < 1024; i += 256) ((float4*)ws)[i] = ((const float4*)w1)[i];
    bs[tid] = b1[tid];
    __syncthreads();

    const int warp = tid >> 5, lane = tid & 31;
#pragma unroll
    for (int r = 0; r < 4; r++) {
        int row = blockIdx.x * 32 + warp * 4 + r;
        if (row >= NN) break;
        float xv[16];
        const float4* xp = (const float4*)(x + (size_t)row * 16);
#pragma unroll
        for (int q = 0; q < 4; q++) *(float4*)&xv[q * 4] = xp[q];
        float acc[8];
#pragma unroll
        for (int j = 0; j < 8; j++) acc[j] = bs[lane + 32 * j];
#pragma unroll
        for (int k = 0; k < 16; k++) {
            float xk = xv[k];
            const float* wr = &ws[k * 256 + lane];
#pragma unroll
            for (int j = 0; j < 8; j++) acc[j] += xk * wr[32 * j];
        }
#pragma unroll
        for (int j = 0; j < 8; j++) {
            float v = fmaxf(acc[j], 0.f);
            __nv_bfloat16 h = __float2bfloat16_rn(v);
            Ch[(size_t)row * 256 + lane + 32 * j] = h;
            Cl[(size_t)row * 256 + lane + 32 * j] =
                __float2bfloat16_rn(v - __bfloat162float(h));
        }
    }
}

// ---------------- tensor-core GEMM ----------------
// A1: bf16 hi/lo pair (k < K1, 3 passes).  A2: single fp16 (k >= K1, 2 passes, f16 MMA
// with fp16 hi/lo weights).  OUTMODE 2: single fp16 out (t).  OUTMODE 3: fused
// out-projection -> atomic fp32 partials.
template <int ACT, int OUTMODE>
__global__ __launch_bounds__(256, 2) void mma_gemm(
    const __nv_bfloat16* __restrict__ A1h, const __nv_bfloat16* __restrict__ A1l,
    const __half* __restrict__ A2,
    const __nv_bfloat16* __restrict__ Wh,  const __nv_bfloat16* __restrict__ Wl,
    const float* __restrict__ bias,
    __half* __restrict__ Chf,
    const float* __restrict__ W2, float* __restrict__ Pout,
    int M, int K, int K1)
{
    extern __shared__ char smc[];
    __shared__ float sbias[128];

    const int tid = threadIdx.x;
    const int wid = tid >> 5, lane = tid & 31;
    const int g = lane >> 2, tg = lane & 3;
    const int wm = wid >> 1, wn = wid & 1;
    const int m0 = blockIdx.y * 128, n0 = blockIdx.x * 128;
    const uint32_t smc_u = s2u(smc);

    if (tid < 128) sbias[tid] = bias[n0 + tid];

    const int arow = tid >> 1;
    const int aks  = (tid & 1) * 16;
    const int gm   = m0 + arow;
    const int okA  = (gm < M) ? 16 : 0;

    const int q = lane >> 3, rr = lane & 7;
    const uint32_t aoff0 = (uint32_t)((wm * 32 + (q & 1) * 8 + rr) * 80 + (q >> 1) * 16);
    const uint32_t boff0 = (uint32_t)(20480 + (wn * 64 + (q >> 1) * 8 + rr) * 80 + (q & 1) * 16);

    float acc[2][8][4];
#pragma unroll
    for (int i = 0; i < 2; i++)
#pragma unroll
        for (int j = 0; j < 8; j++)
#pragma unroll
            for (int p = 0; p < 4; p++) acc[i][j][p] = 0.f;

    const int NC = K >> 5;

    auto STAGE = [&](int c) {
        const int ck = c * 32;
        const uint32_t sb = smc_u + (uint32_t)((c & 1) * STAGE_B);
        const uint32_t da = sb + (uint32_t)(arow * 80 + (tid & 1) * 32);
        if (ck < K1) {
            const __nv_bfloat16* pah = A1h + (size_t)gm * K1 + ck + aks;
            const __nv_bfloat16* pal = A1l + (size_t)gm * K1 + ck + aks;
            cp16(da, pah, okA);               cp16(da + 16, pah + 8, okA);
            cp16(da + 10240, pal, okA);       cp16(da + 10240 + 16, pal + 8, okA);
        } else {
            const __half* pa = A2 + (size_t)gm * (K - K1) + (ck - K1) + aks;
            cp16(da, pa, okA);                cp16(da + 16, pa + 8, okA);
        }
        const __nv_bfloat16* pbh = Wh + (size_t)(n0 + arow) * K + ck + aks;
        const __nv_bfloat16* pbl = Wl + (size_t)(n0 + arow) * K + ck + aks;
        cp16(da + 20480, pbh, 16);        cp16(da + 20480 + 16, pbh + 8, 16);
        cp16(da + 30720, pbl, 16);        cp16(da + 30720 + 16, pbl + 8, 16);
        CP_COMMIT();
    };

    STAGE(0);

    for (int c = 0; c < NC; c++) {
        if (c + 1 < NC) {
            STAGE(c + 1);
            asm volatile("cp.async.wait_group 1;" ::: "memory");
        } else {
            asm volatile("cp.async.wait_group 0;" ::: "memory");
        }
        __syncthreads();

        const uint32_t sb = smc_u + (uint32_t)((c & 1) * STAGE_B);
        const bool f16path = (c * 32 >= K1);
#pragma unroll
        for (int ks = 0; ks < 2; ks++) {
            const uint32_t ko = (uint32_t)(ks * 32);
            uint32_t ah[2][4], bb[8][2];
            ldsm4(ah[0][0], ah[0][1], ah[0][2], ah[0][3], sb + aoff0 + ko);
            ldsm4(ah[1][0], ah[1][1], ah[1][2], ah[1][3], sb + aoff0 + 1280 + ko);
#pragma unroll
            for (int jp = 0; jp < 4; jp++)
                ldsm4(bb[2 * jp][0], bb[2 * jp][1], bb[2 * jp + 1][0], bb[2 * jp + 1][1],
                      sb + boff0 + (uint32_t)(jp * 1280) + ko);

            if (!f16path) {
#pragma unroll
                for (int i = 0; i < 2; i++)
#pragma unroll
                    for (int j = 0; j < 8; j++) MMA_BF16(acc[i][j], ah[i], bb[j][0], bb[j][1]);

                uint32_t al[2][4];
                ldsm4(al[0][0], al[0][1], al[0][2], al[0][3], sb + 10240 + aoff0 + ko);
                ldsm4(al[1][0], al[1][1], al[1][2], al[1][3], sb + 10240 + aoff0 + 1280 + ko);
#pragma unroll
                for (int i = 0; i < 2; i++)
#pragma unroll
                    for (int j = 0; j < 8; j++) MMA_BF16(acc[i][j], al[i], bb[j][0], bb[j][1]);

#pragma unroll
                for (int jp = 0; jp < 4; jp++)
                    ldsm4(bb[2 * jp][0], bb[2 * jp][1], bb[2 * jp + 1][0], bb[2 * jp + 1][1],
                          sb + 10240 + boff0 + (uint32_t)(jp * 1280) + ko);
#pragma unroll
                for (int i = 0; i < 2; i++)
#pragma unroll
                    for (int j = 0; j < 8; j++) MMA_BF16(acc[i][j], ah[i], bb[j][0], bb[j][1]);
            } else {
#pragma unroll
                for (int i = 0; i < 2; i++)
#pragma unroll
                    for (int j = 0; j < 8; j++) MMA_F16(acc[i][j], ah[i], bb[j][0], bb[j][1]);

#pragma unroll
                for (int jp = 0; jp < 4; jp++)
                    ldsm4(bb[2 * jp][0], bb[2 * jp][1], bb[2 * jp + 1][0], bb[2 * jp + 1][1],
                          sb + 10240 + boff0 + (uint32_t)(jp * 1280) + ko);
#pragma unroll
                for (int i = 0; i < 2; i++)
#pragma unroll
                    for (int j = 0; j < 8; j++) MMA_F16(acc[i][j], ah[i], bb[j][0], bb[j][1]);
            }
        }
        __syncthreads();
    }

    if (OUTMODE == 2) {
#pragma unroll
        for (int i = 0; i < 2; i++) {
            int r0 = m0 + wm * 32 + i * 16 + g;
#pragma unroll
            for (int j = 0; j < 8; j++) {
                int cl = wn * 64 + j * 8 + tg * 2;
                float b0 = sbias[cl], b1 = sbias[cl + 1];
                float v0 = acc[i][j][0] + b0, v1 = acc[i][j][1] + b1;
                float v2 = acc[i][j][2] + b0, v3 = acc[i][j][3] + b1;
                if (ACT == 1) {
                    v0 = fmaxf(v0, 0.f); v1 = fmaxf(v1, 0.f);
                    v2 = fmaxf(v2, 0.f); v3 = fmaxf(v3, 0.f);
                }
                if (r0 < M)
                    *(uint32_t*)(Chf + (size_t)r0 * 256 + n0 + cl) = pack_f16x2(v0, v1);
                if (r0 + 8 < M)
                    *(uint32_t*)(Chf + (size_t)(r0 + 8) * 256 + n0 + cl) = pack_f16x2(v2, v3);
            }
        }
    } else {
        // u path: park u-tile in smem (fp32, pitch 129), then fused out-projection
        float* ut = (float*)smc;
#pragma unroll
        for (int i = 0; i < 2; i++) {
            int rl = wm * 32 + i * 16 + g;
#pragma unroll
            for (int j = 0; j < 8; j++) {
                int cl = wn * 64 + j * 8 + tg * 2;
                float b0 = sbias[cl], b1 = sbias[cl + 1];
                float v0 = acc[i][j][0] + b0, v1 = acc[i][j][1] + b1;
                float v2 = acc[i][j][2] + b0, v3 = acc[i][j][3] + b1;
                if (ACT == 1) {
                    v0 = fmaxf(v0, 0.f); v1 = fmaxf(v1, 0.f);
                    v2 = fmaxf(v2, 0.f); v3 = fmaxf(v3, 0.f);
                }
                ut[rl * 129 + cl]       = v0;
                ut[rl * 129 + cl + 1]   = v1;
                ut[(rl + 8) * 129 + cl]     = v2;
                ut[(rl + 8) * 129 + cl + 1] = v3;
            }
        }
        __shared__ float w2s[128 * 16];
        for (int i = tid; i < 128 * 16 / 4; i += 256)
            ((float4*)w2s)[i] = ((const float4*)(W2 + (size_t)n0 * 16))[i];
        __syncthreads();

        const int row = tid >> 1;
        const int off = (tid & 1) * 8;
        const int gr = m0 + row;
        if (gr < M) {
            float o[8];
#pragma unroll
            for (int j = 0; j < 8; j++) o[j] = 0.f;
#pragma unroll 4
            for (int c = 0; c < 128; c++) {
                float uv = ut[row * 129 + c];
                const float* wr = &w2s[c * 16 + off];
#pragma unroll
                for (int j = 0; j < 8; j++) o[j] += uv * wr[j];
            }
            float* pp = Pout + (size_t)gr * 16 + off;
#pragma unroll
            for (int j = 0; j < 8; j++) atomicAdd(&pp[j], o[j]);
        }
    }
}

// ---------------- final: out = tanh(partial + b2) ----------------
__global__ __launch_bounds__(256) void tanh_kernel(const float* __restrict__ pout,
                                                   const float* __restrict__ b2,
                                                   float* __restrict__ out) {
    __shared__ float bs[16];
    if (threadIdx.x < 16) bs[threadIdx.x] = b2[threadIdx.x];
    __syncthreads();
    int idx = blockIdx.x * 256 + threadIdx.x;   // float4 index
    if (idx < NN * 4) {
        float4 v = ((const float4*)pout)[idx];
        int jb = (idx & 3) * 4;
        v.x = tanhf(v.x + bs[jb]);
        v.y = tanhf(v.y + bs[jb + 1]);
        v.z = tanhf(v.z + bs[jb + 2]);
        v.w = tanhf(v.w + bs[jb + 3]);
        ((float4*)out)[idx] = v;
    }
}

// ---------------- CSR build ----------------
__global__ void count_kernel(const int* __restrict__ dst, int* __restrict__ cnt) {
    int e = blockIdx.x * blockDim.x + threadIdx.x;
    if (e < NE) atomicAdd(&cnt[dst[e]], 1);
}

__global__ __launch_bounds__(1024) void scan_kernel(const int* __restrict__ cnt,
                                                    int* __restrict__ rowptr,
                                                    int* __restrict__ fill) {
    __shared__ int wsum[32];
    __shared__ int s_carry;
    const int tid = threadIdx.x, lane = tid & 31, wid = tid >> 5;
    if (tid == 0) { s_carry = 0; rowptr[0] = 0; }
    __syncthreads();
    for (int base = 0; base < NN; base += 1024) {
        int i = base + tid;
        int v = (i < NN) ? cnt[i] : 0;
        int s = v;
#pragma unroll
        for (int d = 1; d < 32; d <<= 1) {
            int y = __shfl_up_sync(0xffffffffu, s, d);
            if (lane >= d) s += y;
        }
        if (lane == 31) wsum[wid] = s;
        int carry_in = s_carry;
        __syncthreads();
        if (wid == 0) {
            int ws = wsum[lane];
#pragma unroll
            for (int d = 1; d < 32; d <<= 1) {
                int y = __shfl_up_sync(0xffffffffu, ws, d);
                if (lane >= d) ws += y;
            }
            wsum[lane] = ws;
        }
        __syncthreads();
        int off = (wid ? wsum[wid - 1] : 0) + carry_in;
        int inc = s + off;
        if (i < NN) {
            rowptr[i + 1] = inc;
            fill[i] = inc - v;
        }
        __syncthreads();
        if (tid == 1023) s_carry = inc;
        __syncthreads();
    }
}

__global__ void scatter_kernel(const int* __restrict__ src, const int* __restrict__ dst,
                               int* __restrict__ fill, int* __restrict__ col) {
    int e = blockIdx.x * blockDim.x + threadIdx.x;
    if (e < NE) {
        int slot = atomicAdd(&fill[dst[e]], 1);
        col[slot] = src[e];
    }
}

// ---------------- aggregation — fp16 in, fp16 out (4 nodes/block, 1 warp each) -------
__device__ __forceinline__ void acc8h(float* acc, uint4 hv) {
    const uint32_t* h = (const uint32_t*)&hv;
#pragma unroll
    for (int p = 0; p < 4; p++) {
        float2 f = __half22float2(*reinterpret_cast<const __half2*>(&h[p]));
        acc[2 * p]     += f.x;
        acc[2 * p + 1] += f.y;
    }
}

__global__ __launch_bounds__(128) void agg_kernel(
    const __half* __restrict__ t,
    const int* __restrict__ rowptr, const int* __restrict__ col,
    __half* __restrict__ agg)
{
    const int node = blockIdx.x * 4 + (threadIdx.x >> 5);
    if (node >= NN) return;
    const int tid = threadIdx.x & 31;
    const int s = rowptr[node];
    const int e = rowptr[node + 1];
    float acc[8];
#pragma unroll
    for (int p = 0; p < 8; p++) acc[p] = 0.f;

    int i = s;
    for (; i + 4 <= e; i += 4) {
        int c0 = __ldg(&col[i]),     c1 = __ldg(&col[i + 1]);
        int c2 = __ldg(&col[i + 2]), c3 = __ldg(&col[i + 3]);
        uint4 h0 = *(const uint4*)(t + (size_t)c0 * HID + tid * 8);
        uint4 h1 = *(const uint4*)(t + (size_t)c1 * HID + tid * 8);
        uint4 h2 = *(const uint4*)(t + (size_t)c2 * HID + tid * 8);
        uint4 h3 = *(const uint4*)(t + (size_t)c3 * HID + tid * 8);
        acc8h(acc, h0); acc8h(acc, h1);
        acc8h(acc, h2); acc8h(acc, h3);
    }
    for (; i < e; i++) {
        int c0 = __ldg(&col[i]);
        uint4 h0 = *(const uint4*)(t + (size_t)c0 * HID + tid * 8);
        acc8h(acc, h0);
    }

    uint32_t hw[4];
#pragma unroll
    for (int p = 0; p < 4; p++) hw[p] = pack_f16x2(acc[2 * p], acc[2 * p + 1]);
    *(uint4*)(agg + (size_t)node * HID + tid * 8) = *(uint4*)hw;
}

// ---------------- launcher ----------------
extern "C" void kernel_launch(void* const* d_in, const int* in_sizes, int n_in,
                              void* d_out, int out_size) {
    const float* x       = (const float*)d_in[0];
    const int*   ei      = (const int*)d_in[1];
    const float* pre_w1  = (const float*)d_in[2];
    const float* pre_b1  = (const float*)d_in[3];
    const float* pre_w2  = (const float*)d_in[4];
    const float* pre_b2  = (const float*)d_in[5];
    const float* conv_w  = (const float*)d_in[6];
    const float* conv_b  = (const float*)d_in[7];
    const float* post_w1 = (const float*)d_in[8];
    const float* post_b1 = (const float*)d_in[9];
    const float* post_w2 = (const float*)d_in[10];
    const float* post_b2 = (const float*)d_in[11];
    float* out = (float*)d_out;

    const int* src = ei;
    const int* dst = ei + NE;

    __nv_bfloat16 *ah, *al;
    __half *t, *gg;
    float* pout;
    int *cnt, *rowptr, *fill, *col;
    float *cbt, *cbu;
    __nv_bfloat16 *wth, *wtl, *wuh, *wul;
    cudaGetSymbolAddress((void**)&ah, g_ah);   cudaGetSymbolAddress((void**)&al, g_al);
    cudaGetSymbolAddress((void**)&t, g_t);     cudaGetSymbolAddress((void**)&gg, g_g);
    cudaGetSymbolAddress((void**)&pout, g_pout);
    cudaGetSymbolAddress((void**)&cnt, g_cnt);
    cudaGetSymbolAddress((void**)&rowptr, g_rowptr);
    cudaGetSymbolAddress((void**)&fill, g_fill);
    cudaGetSymbolAddress((void**)&col, g_col);
    cudaGetSymbolAddress((void**)&cbt, g_cbt); cudaGetSymbolAddress((void**)&cbu, g_cbu);
    cudaGetSymbolAddress((void**)&wth, g_wth); cudaGetSymbolAddress((void**)&wtl, g_wtl);
    cudaGetSymbolAddress((void**)&wuh, g_wuh); cudaGetSymbolAddress((void**)&wul, g_wul);

    const float* P1 = post_w1;                 // rows 0..255 of [512][256]
    const float* P2 = post_w1 + 256 * 256;     // rows 256..511

    const int DSMEM = 2 * STAGE_B;  // 80 KB (>= 128*129*4 = 66048 for u-tile park)
    cudaFuncSetAttribute(mma_gemm<1, 2>, cudaFuncAttributeMaxDynamicSharedMemorySize, DSMEM);
    cudaFuncSetAttribute(mma_gemm<1, 3>, cudaFuncAttributeMaxDynamicSharedMemorySize, DSMEM);

    const int MT = (NN + 127) / 128;  // 391
    dim3 gg2(2, MT);

    // (1) t-weights + t-bias
    compose_prep<<<dim3(4, 5), 256>>>(pre_w2, conv_w, wth, wtl, 256, 0,
                                      pre_b2, conv_b, cbt);
    // (2) pre-MLP layer 1 -> a pair (bf16 hi/lo)
    pre_kernel<<<(NN + 31) / 32, 256>>>(x, pre_w1, pre_b1, ah, al);
    // (3) u-weights a-part (bf16 hi/lo) + u-bias
    compose_prep<<<dim3(4, 5), 256>>>(pre_w2, P1, wuh, wul, 512, 0,
                                      pre_b2, post_b1, cbu);
    // (4) u-weights agg-part: P2 as fp16 hi/lo (same 16-bit storage, reinterpreted)
    prep2h<<<dim3(8, 8), dim3(32, 8)>>>(P2, (__half*)wuh, (__half*)wul, 512, 256);
    // (5) t = relu(a@Wt + bt) -> single fp16
    mma_gemm<1, 2><<<gg2, 256, DSMEM>>>(ah, al, nullptr, wth, wtl, cbt,
                                        t, nullptr, nullptr, NN, 256, 256);

    // ---- CSR build + atomic-free segment sum ----
    cudaMemsetAsync(cnt, 0, NN * sizeof(int), 0);
    cudaMemsetAsync(pout, 0, (size_t)NN * 16 * sizeof(float), 0);
    count_kernel<<<(NE + 255) / 256, 256>>>(dst, cnt);
    scan_kernel<<<1, 1024>>>(cnt, rowptr, fill);
    scatter_kernel<<<(NE + 255) / 256, 256>>>(src, dst, fill, col);
    agg_kernel<<<(NN + 3) / 4, 128>>>(t, rowptr, col, gg);

    // ---- u = relu(a@Wp + agg@P2 + bu), fused out-projection -> pout partials ----
    mma_gemm<1, 3><<<gg2, 256, DSMEM>>>(ah, al, gg, wuh, wul, cbu,
                                        nullptr, post_w2, pout, NN, 512, 256);
    // ---- out = tanh(pout + b2) ----
    tanh_kernel<<<(NN * 4 + 255) / 256, 256>>>(pout, post_b2, out);
}

// round 15
// speedup vs baseline: 1.6232x; 1.1098x over previous
#include <cuda_runtime.h>
#include <cuda_bf16.h>
#include <cuda_fp16.h>
#include <cstdint>
#include <cstddef>

#define NN 50000
#define NE 800000
#define HID 256

// smem stage layout (bytes, pitch 80/row of 32 halfwords + pad):
// A[128x80]=10240 | B_hi[128x80]=10240 | B_lo[128x80]=10240
#define STAGE_B 30720

// ---------------- scratch (device globals: no allocation allowed) ----------------
__device__ __half g_a[(size_t)NN * HID];                        // single fp16 a
__device__ __half g_t[(size_t)NN * HID];                        // single fp16 t
__device__ __half g_g[(size_t)NN * HID];                        // single fp16 agg
__device__ float g_pout[(size_t)NN * 16];                       // fp32 out partials
__device__ int g_cnt[NN];
__device__ int g_rowptr[NN + 1];
__device__ int g_fill[NN];
__device__ int g_col[NE];
__device__ float g_cbt[256];         // b2@Wc + conv_b
__device__ float g_cbu[256];         // b2@P1 + post_b1
__device__ __half g_wth[256 * 256], g_wtl[256 * 256];           // t-GEMM weights fp16 hi/lo
__device__ __half g_wuh[256 * 512], g_wul[256 * 512];           // u-GEMM weights fp16 hi/lo

// ---------------- helpers ----------------
__device__ __forceinline__ uint32_t s2u(const void* p) {
    uint32_t a;
    asm("{ .reg .u64 t; cvta.to.shared.u64 t, %1; cvt.u32.u64 %0, t; }" : "=r"(a) : "l"(p));
    return a;
}
__device__ __forceinline__ void cp16(uint32_t dst, const void* src, int srcsz) {
    asm volatile("cp.async.cg.shared.global [%0], [%1], 16, %2;"
                 :: "r"(dst), "l"(src), "r"(srcsz) : "memory");
}
#define CP_COMMIT() asm volatile("cp.async.commit_group;" ::: "memory")

__device__ __forceinline__ void ldsm4(uint32_t& r0, uint32_t& r1, uint32_t& r2, uint32_t& r3,
                                      uint32_t addr) {
    asm volatile("ldmatrix.sync.aligned.m8n8.x4.shared.b16 {%0,%1,%2,%3}, [%4];"
                 : "=r"(r0), "=r"(r1), "=r"(r2), "=r"(r3) : "r"(addr));
}

#define MMA_F16(cc, aa, b0v, b1v)                                               \
    asm volatile(                                                               \
        "mma.sync.aligned.m16n8k16.row.col.f32.f16.f16.f32 "                    \
        "{%0,%1,%2,%3}, {%4,%5,%6,%7}, {%8,%9}, {%0,%1,%2,%3};"                 \
        : "+f"(cc[0]), "+f"(cc[1]), "+f"(cc[2]), "+f"(cc[3])                    \
        : "r"(aa[0]), "r"(aa[1]), "r"(aa[2]), "r"(aa[3]), "r"(b0v), "r"(b1v))

__device__ __forceinline__ uint32_t pack_f16x2(float a, float b) {
    __half2 p = __float22half2_rn(make_float2(a, b));
    return *reinterpret_cast<uint32_t*>(&p);
}

// ---------------- fused compose+prep+bias (fp16 hi/lo out) ----------------
__global__ __launch_bounds__(256) void compose_prep(
    const float* __restrict__ A, const float* __restrict__ B,
    __half* __restrict__ hi, __half* __restrict__ lo,
    int kpitch, int koff,
    const float* __restrict__ b2, const float* __restrict__ badd,
    float* __restrict__ bout)
{
    const int t = threadIdx.x;
    if (blockIdx.y == 4) {
        __shared__ float red[4][64];
        int j = blockIdx.x * 64 + (t & 63);
        int ks = t >> 6;
        float acc = 0.f;
#pragma unroll 8
        for (int k = ks * 64; k < ks * 64 + 64; k++)
            acc += b2[k] * B[(size_t)k * 256 + j];
        red[ks][t & 63] = acc;
        __syncthreads();
        if (t < 64) {
            int jj = blockIdx.x * 64 + t;
            bout[jj] = red[0][t] + red[1][t] + red[2][t] + red[3][t] + badd[jj];
        }
        return;
    }

    __shared__ float As[16][64];
    __shared__ float Bs[16][64];
    const int tx = t & 15, ty = t >> 4;
    const int m0 = blockIdx.y * 64, n0 = blockIdx.x * 64;
    float acc[4][4];
#pragma unroll
    for (int i = 0; i < 4; i++)
#pragma unroll
        for (int j = 0; j < 4; j++) acc[i][j] = 0.f;

    for (int k0 = 0; k0 < 256; k0 += 16) {
#pragma unroll
        for (int i = 0; i < 4; i++) {
            int idx = t + i * 256;
            int r = idx >> 4, c = idx & 15;
            As[c][r] = A[(size_t)(m0 + r) * 256 + k0 + c];
        }
#pragma unroll
        for (int i = 0; i < 4; i++) {
            int idx = t + i * 256;
            int r = idx >> 6, c = idx & 63;
            Bs[r][c] = B[(size_t)(k0 + r) * 256 + n0 + c];
        }
        __syncthreads();
#pragma unroll
        for (int k = 0; k < 16; k++) {
            float ra[4], rb[4];
#pragma unroll
            for (int i = 0; i < 4; i++) ra[i] = As[k][ty * 4 + i];
#pragma unroll
            for (int j = 0; j < 4; j++) rb[j] = Bs[k][tx * 4 + j];
#pragma unroll
            for (int i = 0; i < 4; i++)
#pragma unroll
                for (int j = 0; j < 4; j++) acc[i][j] += ra[i] * rb[j];
        }
        __syncthreads();
    }
#pragma unroll
    for (int i = 0; i < 4; i++) {
        int kk = m0 + ty * 4 + i;
#pragma unroll
        for (int j = 0; j < 4; j++) {
            int nn = n0 + tx * 4 + j;
            float v = acc[i][j];
            __half h = __float2half_rn(v);
            hi[(size_t)nn * kpitch + koff + kk] = h;
            lo[(size_t)nn * kpitch + koff + kk] = __float2half_rn(v - __half2float(h));
        }
    }
}

// ---------------- prep for P2: transpose + fp16 hi/lo split ----------------
__global__ void prep2h(const float* __restrict__ W, __half* __restrict__ hi,
                       __half* __restrict__ lo, int kpitch, int koff) {
    __shared__ float tile[32][33];
    int k0 = blockIdx.y * 32, n0 = blockIdx.x * 32;
    int tx = threadIdx.x, ty = threadIdx.y;  // 32 x 8
    for (int i = ty; i < 32; i += 8) tile[i][tx] = W[(size_t)(k0 + i) * 256 + n0 + tx];
    __syncthreads();
    for (int i = ty; i < 32; i += 8) {
        float v = tile[tx][i];
        __half h = __float2half_rn(v);
        hi[(size_t)(n0 + i) * kpitch + koff + k0 + tx] = h;
        lo[(size_t)(n0 + i) * kpitch + koff + k0 + tx] =
            __float2half_rn(v - __half2float(h));
    }
}

// ---------------- pre-MLP layer 1: a = relu(x@w1+b1), K=16, single fp16 out ----------
__global__ __launch_bounds__(256) void pre_kernel(
    const float* __restrict__ x, const float* __restrict__ w1, const float* __restrict__ b1,
    __half* __restrict__ C)
{
    __shared__ float ws[16 * 256];
    __shared__ float bs[256];
    const int tid = threadIdx.x;
    for (int i = tid; i < 1024; i += 256) ((float4*)ws)[i] = ((const float4*)w1)[i];
    bs[tid] = b1[tid];
    __syncthreads();

    const int warp = tid >> 5, lane = tid & 31;
#pragma unroll
    for (int r = 0; r < 4; r++) {
        int row = blockIdx.x * 32 + warp * 4 + r;
        if (row >= NN) break;
        float xv[16];
        const float4* xp = (const float4*)(x + (size_t)row * 16);
#pragma unroll
        for (int q = 0; q < 4; q++) *(float4*)&xv[q * 4] = xp[q];
        float acc[8];
#pragma unroll
        for (int j = 0; j < 8; j++) acc[j] = bs[lane + 32 * j];
#pragma unroll
        for (int k = 0; k < 16; k++) {
            float xk = xv[k];
            const float* wr = &ws[k * 256 + lane];
#pragma unroll
            for (int j = 0; j < 8; j++) acc[j] += xk * wr[32 * j];
        }
#pragma unroll
        for (int j = 0; j < 8; j++) {
            float v = fmaxf(acc[j], 0.f);
            C[(size_t)row * 256 + lane + 32 * j] = __float2half_rn(v);
        }
    }
}

// ---------------- tensor-core GEMM: all-fp16, 2-pass (W hi + W lo) ------------------
// A = concat(A1, A2), both single fp16.  OUTMODE 2: fp16 out (t).  OUTMODE 3:
// fused out-projection -> atomic fp32 partials.
template <int ACT, int OUTMODE>
__global__ __launch_bounds__(256, 2) void mma_gemm(
    const __half* __restrict__ A1, const __half* __restrict__ A2,
    const __half* __restrict__ Wh, const __half* __restrict__ Wl,
    const float* __restrict__ bias,
    __half* __restrict__ Chf,
    const float* __restrict__ W2, float* __restrict__ Pout,
    int M, int K, int K1)
{
    extern __shared__ char smc[];
    __shared__ float sbias[128];

    const int tid = threadIdx.x;
    const int wid = tid >> 5, lane = tid & 31;
    const int g = lane >> 2, tg = lane & 3;
    const int wm = wid >> 1, wn = wid & 1;
    const int m0 = blockIdx.y * 128, n0 = blockIdx.x * 128;
    const uint32_t smc_u = s2u(smc);

    if (tid < 128) sbias[tid] = bias[n0 + tid];

    const int arow = tid >> 1;
    const int aks  = (tid & 1) * 16;
    const int gm   = m0 + arow;
    const int okA  = (gm < M) ? 16 : 0;

    const int q = lane >> 3, rr = lane & 7;
    const uint32_t aoff0 = (uint32_t)((wm * 32 + (q & 1) * 8 + rr) * 80 + (q >> 1) * 16);
    const uint32_t boff0 = (uint32_t)(10240 + (wn * 64 + (q >> 1) * 8 + rr) * 80 + (q & 1) * 16);

    float acc[2][8][4];
#pragma unroll
    for (int i = 0; i < 2; i++)
#pragma unroll
        for (int j = 0; j < 8; j++)
#pragma unroll
            for (int p = 0; p < 4; p++) acc[i][j][p] = 0.f;

    const int NC = K >> 5;

    auto STAGE = [&](int c) {
        const int ck = c * 32;
        const uint32_t sb = smc_u + (uint32_t)((c & 1) * STAGE_B);
        const uint32_t da = sb + (uint32_t)(arow * 80 + (tid & 1) * 32);
        const __half* pa = (ck < K1) ? (A1 + (size_t)gm * K1 + ck + aks)
                                     : (A2 + (size_t)gm * (K - K1) + (ck - K1) + aks);
        cp16(da, pa, okA);                cp16(da + 16, pa + 8, okA);
        const __half* pbh = Wh + (size_t)(n0 + arow) * K + ck + aks;
        const __half* pbl = Wl + (size_t)(n0 + arow) * K + ck + aks;
        cp16(da + 10240, pbh, 16);        cp16(da + 10240 + 16, pbh + 8, 16);
        cp16(da + 20480, pbl, 16);        cp16(da + 20480 + 16, pbl + 8, 16);
        CP_COMMIT();
    };

    STAGE(0);

    for (int c = 0; c < NC; c++) {
        if (c + 1 < NC) {
            STAGE(c + 1);
            asm volatile("cp.async.wait_group 1;" ::: "memory");
        } else {
            asm volatile("cp.async.wait_group 0;" ::: "memory");
        }
        __syncthreads();

        const uint32_t sb = smc_u + (uint32_t)((c & 1) * STAGE_B);
#pragma unroll
        for (int ks = 0; ks < 2; ks++) {
            const uint32_t ko = (uint32_t)(ks * 32);
            uint32_t ah[2][4], bb[8][2];
            ldsm4(ah[0][0], ah[0][1], ah[0][2], ah[0][3], sb + aoff0 + ko);
            ldsm4(ah[1][0], ah[1][1], ah[1][2], ah[1][3], sb + aoff0 + 1280 + ko);
#pragma unroll
            for (int jp = 0; jp < 4; jp++)
                ldsm4(bb[2 * jp][0], bb[2 * jp][1], bb[2 * jp + 1][0], bb[2 * jp + 1][1],
                      sb + boff0 + (uint32_t)(jp * 1280) + ko);
#pragma unroll
            for (int i = 0; i < 2; i++)
#pragma unroll
                for (int j = 0; j < 8; j++) MMA_F16(acc[i][j], ah[i], bb[j][0], bb[j][1]);

#pragma unroll
            for (int jp = 0; jp < 4; jp++)
                ldsm4(bb[2 * jp][0], bb[2 * jp][1], bb[2 * jp + 1][0], bb[2 * jp + 1][1],
                      sb + 10240 + boff0 + (uint32_t)(jp * 1280) + ko);
#pragma unroll
            for (int i = 0; i < 2; i++)
#pragma unroll
                for (int j = 0; j < 8; j++) MMA_F16(acc[i][j], ah[i], bb[j][0], bb[j][1]);
        }
        __syncthreads();
    }

    if (OUTMODE == 2) {
#pragma unroll
        for (int i = 0; i < 2; i++) {
            int r0 = m0 + wm * 32 + i * 16 + g;
#pragma unroll
            for (int j = 0; j < 8; j++) {
                int cl = wn * 64 + j * 8 + tg * 2;
                float b0 = sbias[cl], b1 = sbias[cl + 1];
                float v0 = acc[i][j][0] + b0, v1 = acc[i][j][1] + b1;
                float v2 = acc[i][j][2] + b0, v3 = acc[i][j][3] + b1;
                if (ACT == 1) {
                    v0 = fmaxf(v0, 0.f); v1 = fmaxf(v1, 0.f);
                    v2 = fmaxf(v2, 0.f); v3 = fmaxf(v3, 0.f);
                }
                if (r0 < M)
                    *(uint32_t*)(Chf + (size_t)r0 * 256 + n0 + cl) = pack_f16x2(v0, v1);
                if (r0 + 8 < M)
                    *(uint32_t*)(Chf + (size_t)(r0 + 8) * 256 + n0 + cl) = pack_f16x2(v2, v3);
            }
        }
    } else {
        // u path: park u-tile in smem (fp32, pitch 129), then fused out-projection
        float* ut = (float*)smc;
#pragma unroll
        for (int i = 0; i < 2; i++) {
            int rl = wm * 32 + i * 16 + g;
#pragma unroll
            for (int j = 0; j < 8; j++) {
                int cl = wn * 64 + j * 8 + tg * 2;
                float b0 = sbias[cl], b1 = sbias[cl + 1];
                float v0 = acc[i][j][0] + b0, v1 = acc[i][j][1] + b1;
                float v2 = acc[i][j][2] + b0, v3 = acc[i][j][3] + b1;
                if (ACT == 1) {
                    v0 = fmaxf(v0, 0.f); v1 = fmaxf(v1, 0.f);
                    v2 = fmaxf(v2, 0.f); v3 = fmaxf(v3, 0.f);
                }
                ut[rl * 129 + cl]       = v0;
                ut[rl * 129 + cl + 1]   = v1;
                ut[(rl + 8) * 129 + cl]     = v2;
                ut[(rl + 8) * 129 + cl + 1] = v3;
            }
        }
        __shared__ float w2s[128 * 16];
        for (int i = tid; i < 128 * 16 / 4; i += 256)
            ((float4*)w2s)[i] = ((const float4*)(W2 + (size_t)n0 * 16))[i];
        __syncthreads();

        const int row = tid >> 1;
        const int off = (tid & 1) * 8;
        const int gr = m0 + row;
        if (gr < M) {
            float o[8];
#pragma unroll
            for (int j = 0; j < 8; j++) o[j] = 0.f;
#pragma unroll 4
            for (int c = 0; c < 128; c++) {
                float uv = ut[row * 129 + c];
                const float* wr = &w2s[c * 16 + off];
#pragma unroll
                for (int j = 0; j < 8; j++) o[j] += uv * wr[j];
            }
            float* pp = Pout + (size_t)gr * 16 + off;
#pragma unroll
            for (int j = 0; j < 8; j++) atomicAdd(&pp[j], o[j]);
        }
    }
}

// ---------------- final: out = tanh(partial + b2) ----------------
__global__ __launch_bounds__(256) void tanh_kernel(const float* __restrict__ pout,
                                                   const float* __restrict__ b2,
                                                   float* __restrict__ out) {
    __shared__ float bs[16];
    if (threadIdx.x < 16) bs[threadIdx.x] = b2[threadIdx.x];
    __syncthreads();
    int idx = blockIdx.x * 256 + threadIdx.x;   // float4 index
    if (idx < NN * 4) {
        float4 v = ((const float4*)pout)[idx];
        int jb = (idx & 3) * 4;
        v.x = tanhf(v.x + bs[jb]);
        v.y = tanhf(v.y + bs[jb + 1]);
        v.z = tanhf(v.z + bs[jb + 2]);
        v.w = tanhf(v.w + bs[jb + 3]);
        ((float4*)out)[idx] = v;
    }
}

// ---------------- CSR build ----------------
__global__ void count_kernel(const int* __restrict__ dst, int* __restrict__ cnt) {
    int e = blockIdx.x * blockDim.x + threadIdx.x;
    if (e < NE) atomicAdd(&cnt[dst[e]], 1);
}

__global__ __launch_bounds__(1024) void scan_kernel(const int* __restrict__ cnt,
                                                    int* __restrict__ rowptr,
                                                    int* __restrict__ fill) {
    __shared__ int wsum[32];
    __shared__ int s_carry;
    const int tid = threadIdx.x, lane = tid & 31, wid = tid >> 5;
    if (tid == 0) { s_carry = 0; rowptr[0] = 0; }
    __syncthreads();
    for (int base = 0; base < NN; base += 1024) {
        int i = base + tid;
        int v = (i < NN) ? cnt[i] : 0;
        int s = v;
#pragma unroll
        for (int d = 1; d < 32; d <<= 1) {
            int y = __shfl_up_sync(0xffffffffu, s, d);
            if (lane >= d) s += y;
        }
        if (lane == 31) wsum[wid] = s;
        int carry_in = s_carry;
        __syncthreads();
        if (wid == 0) {
            int ws = wsum[lane];
#pragma unroll
            for (int d = 1; d < 32; d <<= 1) {
                int y = __shfl_up_sync(0xffffffffu, ws, d);
                if (lane >= d) ws += y;
            }
            wsum[lane] = ws;
        }
        __syncthreads();
        int off = (wid ? wsum[wid - 1] : 0) + carry_in;
        int inc = s + off;
        if (i < NN) {
            rowptr[i + 1] = inc;
            fill[i] = inc - v;
        }
        __syncthreads();
        if (tid == 1023) s_carry = inc;
        __syncthreads();
    }
}

__global__ void scatter_kernel(const int* __restrict__ src, const int* __restrict__ dst,
                               int* __restrict__ fill, int* __restrict__ col) {
    int e = blockIdx.x * blockDim.x + threadIdx.x;
    if (e < NE) {
        int slot = atomicAdd(&fill[dst[e]], 1);
        col[slot] = src[e];
    }
}

// ---------------- aggregation — fp16 in, fp16 out (4 nodes/block, 1 warp each) -------
__device__ __forceinline__ void acc8h(float* acc, uint4 hv) {
    const uint32_t* h = (const uint32_t*)&hv;
#pragma unroll
    for (int p = 0; p < 4; p++) {
        float2 f = __half22float2(*reinterpret_cast<const __half2*>(&h[p]));
        acc[2 * p]     += f.x;
        acc[2 * p + 1] += f.y;
    }
}

__global__ __launch_bounds__(128) void agg_kernel(
    const __half* __restrict__ t,
    const int* __restrict__ rowptr, const int* __restrict__ col,
    __half* __restrict__ agg)
{
    const int node = blockIdx.x * 4 + (threadIdx.x >> 5);
    if (node >= NN) return;
    const int tid = threadIdx.x & 31;
    const int s = rowptr[node];
    const int e = rowptr[node + 1];
    float acc[8];
#pragma unroll
    for (int p = 0; p < 8; p++) acc[p] = 0.f;

    int i = s;
    for (; i + 4 <= e; i += 4) {
        int c0 = __ldg(&col[i]),     c1 = __ldg(&col[i + 1]);
        int c2 = __ldg(&col[i + 2]), c3 = __ldg(&col[i + 3]);
        uint4 h0 = *(const uint4*)(t + (size_t)c0 * HID + tid * 8);
        uint4 h1 = *(const uint4*)(t + (size_t)c1 * HID + tid * 8);
        uint4 h2 = *(const uint4*)(t + (size_t)c2 * HID + tid * 8);
        uint4 h3 = *(const uint4*)(t + (size_t)c3 * HID + tid * 8);
        acc8h(acc, h0); acc8h(acc, h1);
        acc8h(acc, h2); acc8h(acc, h3);
    }
    for (; i < e; i++) {
        int c0 = __ldg(&col[i]);
        uint4 h0 = *(const uint4*)(t + (size_t)c0 * HID + tid * 8);
        acc8h(acc, h0);
    }

    uint32_t hw[4];
#pragma unroll
    for (int p = 0; p < 4; p++) hw[p] = pack_f16x2(acc[2 * p], acc[2 * p + 1]);
    *(uint4*)(agg + (size_t)node * HID + tid * 8) = *(uint4*)hw;
}

// ---------------- launcher ----------------
extern "C" void kernel_launch(void* const* d_in, const int* in_sizes, int n_in,
                              void* d_out, int out_size) {
    const float* x       = (const float*)d_in[0];
    const int*   ei      = (const int*)d_in[1];
    const float* pre_w1  = (const float*)d_in[2];
    const float* pre_b1  = (const float*)d_in[3];
    const float* pre_w2  = (const float*)d_in[4];
    const float* pre_b2  = (const float*)d_in[5];
    const float* conv_w  = (const float*)d_in[6];
    const float* conv_b  = (const float*)d_in[7];
    const float* post_w1 = (const float*)d_in[8];
    const float* post_b1 = (const float*)d_in[9];
    const float* post_w2 = (const float*)d_in[10];
    const float* post_b2 = (const float*)d_in[11];
    float* out = (float*)d_out;

    const int* src = ei;
    const int* dst = ei + NE;

    __half *a, *t, *gg;
    float* pout;
    int *cnt, *rowptr, *fill, *col;
    float *cbt, *cbu;
    __half *wth, *wtl, *wuh, *wul;
    cudaGetSymbolAddress((void**)&a, g_a);
    cudaGetSymbolAddress((void**)&t, g_t);     cudaGetSymbolAddress((void**)&gg, g_g);
    cudaGetSymbolAddress((void**)&pout, g_pout);
    cudaGetSymbolAddress((void**)&cnt, g_cnt);
    cudaGetSymbolAddress((void**)&rowptr, g_rowptr);
    cudaGetSymbolAddress((void**)&fill, g_fill);
    cudaGetSymbolAddress((void**)&col, g_col);
    cudaGetSymbolAddress((void**)&cbt, g_cbt); cudaGetSymbolAddress((void**)&cbu, g_cbu);
    cudaGetSymbolAddress((void**)&wth, g_wth); cudaGetSymbolAddress((void**)&wtl, g_wtl);
    cudaGetSymbolAddress((void**)&wuh, g_wuh); cudaGetSymbolAddress((void**)&wul, g_wul);

    const float* P1 = post_w1;                 // rows 0..255 of [512][256]
    const float* P2 = post_w1 + 256 * 256;     // rows 256..511

    // DSMEM must cover both the 2-stage pipeline (2*30720=61440) and the
    // u-tile park (128*129*4 = 66048).
    const int DSMEM = 66560;
    cudaFuncSetAttribute(mma_gemm<1, 2>, cudaFuncAttributeMaxDynamicSharedMemorySize, DSMEM);
    cudaFuncSetAttribute(mma_gemm<1, 3>, cudaFuncAttributeMaxDynamicSharedMemorySize, DSMEM);

    const int MT = (NN + 127) / 128;  // 391
    dim3 gg2(2, MT);

    // (1) t-weights + t-bias (fp16 hi/lo)
    compose_prep<<<dim3(4, 5), 256>>>(pre_w2, conv_w, wth, wtl, 256, 0,
                                      pre_b2, conv_b, cbt);
    // (2) pre-MLP layer 1 -> single fp16 a
    pre_kernel<<<(NN + 31) / 32, 256>>>(x, pre_w1, pre_b1, a);
    // (3) u-weights a-part (fp16 hi/lo) + u-bias
    compose_prep<<<dim3(4, 5), 256>>>(pre_w2, P1, wuh, wul, 512, 0,
                                      pre_b2, post_b1, cbu);
    // (4) u-weights agg-part (fp16 hi/lo)
    prep2h<<<dim3(8, 8), dim3(32, 8)>>>(P2, wuh, wul, 512, 256);
    // (5) t = relu(a@Wt + bt) -> single fp16
    mma_gemm<1, 2><<<gg2, 256, DSMEM>>>(a, nullptr, wth, wtl, cbt,
                                        t, nullptr, nullptr, NN, 256, 256);

    // ---- CSR build + atomic-free segment sum ----
    cudaMemsetAsync(cnt, 0, NN * sizeof(int), 0);
    cudaMemsetAsync(pout, 0, (size_t)NN * 16 * sizeof(float), 0);
    count_kernel<<<(NE + 255) / 256, 256>>>(dst, cnt);
    scan_kernel<<<1, 1024>>>(cnt, rowptr, fill);
    scatter_kernel<<<(NE + 255) / 256, 256>>>(src, dst, fill, col);
    agg_kernel<<<(NN + 3) / 4, 128>>>(t, rowptr, col, gg);

    // ---- u = relu(a@Wp + agg@P2 + bu), fused out-projection -> pout partials ----
    mma_gemm<1, 3><<<gg2, 256, DSMEM>>>(a, gg, wuh, wul, cbu,
                                        nullptr, post_w2, pout, NN, 512, 256);
    // ---- out = tanh(pout + b2) ----
    tanh_kernel<<<(NN * 4 + 255) / 256, 256>>>(pout, post_b2, out);
}

// round 16
// speedup vs baseline: 1.7961x; 1.1065x over previous
#include <cuda_runtime.h>
#include <cuda_bf16.h>
#include <cuda_fp16.h>
#include <cstdint>
#include <cstddef>

#define NN 50000
#define NE 800000
#define HID 256

// smem stage layout (bytes, pitch 80/row of 32 halfwords + pad):
// A[128x80]=10240 | B_hi[128x80]=10240 | B_lo[128x80]=10240
#define STAGE_B 30720

// ---------------- scratch (device globals: no allocation allowed) ----------------
__device__ __half g_a[(size_t)NN * HID];                        // single fp16 a
__device__ __half g_t[(size_t)NN * HID];                        // single fp16 t
__device__ __half g_g[(size_t)NN * HID];                        // single fp16 agg
__device__ float g_pout[(size_t)NN * 16];                       // fp32 out partials
__device__ int g_cnt[NN];
__device__ int g_rowptr[NN + 1];
__device__ int g_fill[NN];
__device__ int g_col[NE];
__device__ float g_cbt[256];         // b2@Wc + conv_b
__device__ float g_cbu[256];         // b2@P1 + post_b1
__device__ __half g_wth[256 * 256], g_wtl[256 * 256];           // t-GEMM weights fp16 hi/lo
__device__ __half g_wuh[256 * 512], g_wul[256 * 512];           // u-GEMM weights fp16 hi(/lo unused)

// ---------------- helpers ----------------
__device__ __forceinline__ uint32_t s2u(const void* p) {
    uint32_t a;
    asm("{ .reg .u64 t; cvta.to.shared.u64 t, %1; cvt.u32.u64 %0, t; }" : "=r"(a) : "l"(p));
    return a;
}
__device__ __forceinline__ void cp16(uint32_t dst, const void* src, int srcsz) {
    asm volatile("cp.async.cg.shared.global [%0], [%1], 16, %2;"
                 :: "r"(dst), "l"(src), "r"(srcsz) : "memory");
}
#define CP_COMMIT() asm volatile("cp.async.commit_group;" ::: "memory")

__device__ __forceinline__ void ldsm4(uint32_t& r0, uint32_t& r1, uint32_t& r2, uint32_t& r3,
                                      uint32_t addr) {
    asm volatile("ldmatrix.sync.aligned.m8n8.x4.shared.b16 {%0,%1,%2,%3}, [%4];"
                 : "=r"(r0), "=r"(r1), "=r"(r2), "=r"(r3) : "r"(addr));
}

#define MMA_F16(cc, aa, b0v, b1v)                                               \
    asm volatile(                                                               \
        "mma.sync.aligned.m16n8k16.row.col.f32.f16.f16.f32 "                    \
        "{%0,%1,%2,%3}, {%4,%5,%6,%7}, {%8,%9}, {%0,%1,%2,%3};"                 \
        : "+f"(cc[0]), "+f"(cc[1]), "+f"(cc[2]), "+f"(cc[3])                    \
        : "r"(aa[0]), "r"(aa[1]), "r"(aa[2]), "r"(aa[3]), "r"(b0v), "r"(b1v))

__device__ __forceinline__ uint32_t pack_f16x2(float a, float b) {
    __half2 p = __float22half2_rn(make_float2(a, b));
    return *reinterpret_cast<uint32_t*>(&p);
}

// ---------------- fused compose+prep+bias (fp16 hi/lo out) ----------------
__global__ __launch_bounds__(256) void compose_prep(
    const float* __restrict__ A, const float* __restrict__ B,
    __half* __restrict__ hi, __half* __restrict__ lo,
    int kpitch, int koff,
    const float* __restrict__ b2, const float* __restrict__ badd,
    float* __restrict__ bout)
{
    const int t = threadIdx.x;
    if (blockIdx.y == 4) {
        __shared__ float red[4][64];
        int j = blockIdx.x * 64 + (t & 63);
        int ks = t >> 6;
        float acc = 0.f;
#pragma unroll 8
        for (int k = ks * 64; k < ks * 64 + 64; k++)
            acc += b2[k] * B[(size_t)k * 256 + j];
        red[ks][t & 63] = acc;
        __syncthreads();
        if (t < 64) {
            int jj = blockIdx.x * 64 + t;
            bout[jj] = red[0][t] + red[1][t] + red[2][t] + red[3][t] + badd[jj];
        }
        return;
    }

    __shared__ float As[16][64];
    __shared__ float Bs[16][64];
    const int tx = t & 15, ty = t >> 4;
    const int m0 = blockIdx.y * 64, n0 = blockIdx.x * 64;
    float acc[4][4];
#pragma unroll
    for (int i = 0; i < 4; i++)
#pragma unroll
        for (int j = 0; j < 4; j++) acc[i][j] = 0.f;

    for (int k0 = 0; k0 < 256; k0 += 16) {
#pragma unroll
        for (int i = 0; i < 4; i++) {
            int idx = t + i * 256;
            int r = idx >> 4, c = idx & 15;
            As[c][r] = A[(size_t)(m0 + r) * 256 + k0 + c];
        }
#pragma unroll
        for (int i = 0; i < 4; i++) {
            int idx = t + i * 256;
            int r = idx >> 6, c = idx & 63;
            Bs[r][c] = B[(size_t)(k0 + r) * 256 + n0 + c];
        }
        __syncthreads();
#pragma unroll
        for (int k = 0; k < 16; k++) {
            float ra[4], rb[4];
#pragma unroll
            for (int i = 0; i < 4; i++) ra[i] = As[k][ty * 4 + i];
#pragma unroll
            for (int j = 0; j < 4; j++) rb[j] = Bs[k][tx * 4 + j];
#pragma unroll
            for (int i = 0; i < 4; i++)
#pragma unroll
                for (int j = 0; j < 4; j++) acc[i][j] += ra[i] * rb[j];
        }
        __syncthreads();
    }
#pragma unroll
    for (int i = 0; i < 4; i++) {
        int kk = m0 + ty * 4 + i;
#pragma unroll
        for (int j = 0; j < 4; j++) {
            int nn = n0 + tx * 4 + j;
            float v = acc[i][j];
            __half h = __float2half_rn(v);
            hi[(size_t)nn * kpitch + koff + kk] = h;
            lo[(size_t)nn * kpitch + koff + kk] = __float2half_rn(v - __half2float(h));
        }
    }
}

// ---------------- prep for P2: transpose + fp16 hi/lo split ----------------
__global__ void prep2h(const float* __restrict__ W, __half* __restrict__ hi,
                       __half* __restrict__ lo, int kpitch, int koff) {
    __shared__ float tile[32][33];
    int k0 = blockIdx.y * 32, n0 = blockIdx.x * 32;
    int tx = threadIdx.x, ty = threadIdx.y;  // 32 x 8
    for (int i = ty; i < 32; i += 8) tile[i][tx] = W[(size_t)(k0 + i) * 256 + n0 + tx];
    __syncthreads();
    for (int i = ty; i < 32; i += 8) {
        float v = tile[tx][i];
        __half h = __float2half_rn(v);
        hi[(size_t)(n0 + i) * kpitch + koff + k0 + tx] = h;
        lo[(size_t)(n0 + i) * kpitch + koff + k0 + tx] =
            __float2half_rn(v - __half2float(h));
    }
}

// ---------------- pre-MLP layer 1: a = relu(x@w1+b1), K=16, single fp16 out ----------
__global__ __launch_bounds__(256) void pre_kernel(
    const float* __restrict__ x, const float* __restrict__ w1, const float* __restrict__ b1,
    __half* __restrict__ C)
{
    __shared__ float ws[16 * 256];
    __shared__ float bs[256];
    const int tid = threadIdx.x;
    for (int i = tid; i < 1024; i += 256) ((float4*)ws)[i] = ((const float4*)w1)[i];
    bs[tid] = b1[tid];
    __syncthreads();

    const int warp = tid >> 5, lane = tid & 31;
#pragma unroll
    for (int r = 0; r < 4; r++) {
        int row = blockIdx.x * 32 + warp * 4 + r;
        if (row >= NN) break;
        float xv[16];
        const float4* xp = (const float4*)(x + (size_t)row * 16);
#pragma unroll
        for (int q = 0; q < 4; q++) *(float4*)&xv[q * 4] = xp[q];
        float acc[8];
#pragma unroll
        for (int j = 0; j < 8; j++) acc[j] = bs[lane + 32 * j];
#pragma unroll
        for (int k = 0; k < 16; k++) {
            float xk = xv[k];
            const float* wr = &ws[k * 256 + lane];
#pragma unroll
            for (int j = 0; j < 8; j++) acc[j] += xk * wr[32 * j];
        }
#pragma unroll
        for (int j = 0; j < 8; j++) {
            float v = fmaxf(acc[j], 0.f);
            C[(size_t)row * 256 + lane + 32 * j] = __float2half_rn(v);
        }
    }
}

// ---------------- tensor-core GEMM: all-fp16 ----------------
// WLO=1: 2-pass (W hi + W lo).  WLO=0: 1-pass (single fp16 W).
// OUTMODE 2: fp16 out (t).  OUTMODE 3: fused out-projection -> atomic fp32 partials.
template <int ACT, int OUTMODE, int WLO>
__global__ __launch_bounds__(256, 2) void mma_gemm(
    const __half* __restrict__ A1, const __half* __restrict__ A2,
    const __half* __restrict__ Wh, const __half* __restrict__ Wl,
    const float* __restrict__ bias,
    __half* __restrict__ Chf,
    const float* __restrict__ W2, float* __restrict__ Pout,
    int M, int K, int K1)
{
    extern __shared__ char smc[];
    __shared__ float sbias[128];

    const int tid = threadIdx.x;
    const int wid = tid >> 5, lane = tid & 31;
    const int g = lane >> 2, tg = lane & 3;
    const int wm = wid >> 1, wn = wid & 1;
    const int m0 = blockIdx.y * 128, n0 = blockIdx.x * 128;
    const uint32_t smc_u = s2u(smc);

    if (tid < 128) sbias[tid] = bias[n0 + tid];

    const int arow = tid >> 1;
    const int aks  = (tid & 1) * 16;
    const int gm   = m0 + arow;
    const int okA  = (gm < M) ? 16 : 0;

    const int q = lane >> 3, rr = lane & 7;
    const uint32_t aoff0 = (uint32_t)((wm * 32 + (q & 1) * 8 + rr) * 80 + (q >> 1) * 16);
    const uint32_t boff0 = (uint32_t)(10240 + (wn * 64 + (q >> 1) * 8 + rr) * 80 + (q & 1) * 16);

    float acc[2][8][4];
#pragma unroll
    for (int i = 0; i < 2; i++)
#pragma unroll
        for (int j = 0; j < 8; j++)
#pragma unroll
            for (int p = 0; p < 4; p++) acc[i][j][p] = 0.f;

    const int NC = K >> 5;

    auto STAGE = [&](int c) {
        const int ck = c * 32;
        const uint32_t sb = smc_u + (uint32_t)((c & 1) * STAGE_B);
        const uint32_t da = sb + (uint32_t)(arow * 80 + (tid & 1) * 32);
        const __half* pa = (ck < K1) ? (A1 + (size_t)gm * K1 + ck + aks)
                                     : (A2 + (size_t)gm * (K - K1) + (ck - K1) + aks);
        cp16(da, pa, okA);                cp16(da + 16, pa + 8, okA);
        const __half* pbh = Wh + (size_t)(n0 + arow) * K + ck + aks;
        cp16(da + 10240, pbh, 16);        cp16(da + 10240 + 16, pbh + 8, 16);
        if (WLO) {
            const __half* pbl = Wl + (size_t)(n0 + arow) * K + ck + aks;
            cp16(da + 20480, pbl, 16);    cp16(da + 20480 + 16, pbl + 8, 16);
        }
        CP_COMMIT();
    };

    STAGE(0);

    for (int c = 0; c < NC; c++) {
        if (c + 1 < NC) {
            STAGE(c + 1);
            asm volatile("cp.async.wait_group 1;" ::: "memory");
        } else {
            asm volatile("cp.async.wait_group 0;" ::: "memory");
        }
        __syncthreads();

        const uint32_t sb = smc_u + (uint32_t)((c & 1) * STAGE_B);
#pragma unroll
        for (int ks = 0; ks < 2; ks++) {
            const uint32_t ko = (uint32_t)(ks * 32);
            uint32_t ah[2][4], bb[8][2];
            ldsm4(ah[0][0], ah[0][1], ah[0][2], ah[0][3], sb + aoff0 + ko);
            ldsm4(ah[1][0], ah[1][1], ah[1][2], ah[1][3], sb + aoff0 + 1280 + ko);
#pragma unroll
            for (int jp = 0; jp < 4; jp++)
                ldsm4(bb[2 * jp][0], bb[2 * jp][1], bb[2 * jp + 1][0], bb[2 * jp + 1][1],
                      sb + boff0 + (uint32_t)(jp * 1280) + ko);
#pragma unroll
            for (int i = 0; i < 2; i++)
#pragma unroll
                for (int j = 0; j < 8; j++) MMA_F16(acc[i][j], ah[i], bb[j][0], bb[j][1]);

            if (WLO) {
#pragma unroll
                for (int jp = 0; jp < 4; jp++)
                    ldsm4(bb[2 * jp][0], bb[2 * jp][1], bb[2 * jp + 1][0], bb[2 * jp + 1][1],
                          sb + 10240 + boff0 + (uint32_t)(jp * 1280) + ko);
#pragma unroll
                for (int i = 0; i < 2; i++)
#pragma unroll
                    for (int j = 0; j < 8; j++) MMA_F16(acc[i][j], ah[i], bb[j][0], bb[j][1]);
            }
        }
        __syncthreads();
    }

    if (OUTMODE == 2) {
#pragma unroll
        for (int i = 0; i < 2; i++) {
            int r0 = m0 + wm * 32 + i * 16 + g;
#pragma unroll
            for (int j = 0; j < 8; j++) {
                int cl = wn * 64 + j * 8 + tg * 2;
                float b0 = sbias[cl], b1 = sbias[cl + 1];
                float v0 = acc[i][j][0] + b0, v1 = acc[i][j][1] + b1;
                float v2 = acc[i][j][2] + b0, v3 = acc[i][j][3] + b1;
                if (ACT == 1) {
                    v0 = fmaxf(v0, 0.f); v1 = fmaxf(v1, 0.f);
                    v2 = fmaxf(v2, 0.f); v3 = fmaxf(v3, 0.f);
                }
                if (r0 < M)
                    *(uint32_t*)(Chf + (size_t)r0 * 256 + n0 + cl) = pack_f16x2(v0, v1);
                if (r0 + 8 < M)
                    *(uint32_t*)(Chf + (size_t)(r0 + 8) * 256 + n0 + cl) = pack_f16x2(v2, v3);
            }
        }
    } else {
        // u path: park u-tile in smem (fp32, pitch 129), then fused out-projection
        float* ut = (float*)smc;
#pragma unroll
        for (int i = 0; i < 2; i++) {
            int rl = wm * 32 + i * 16 + g;
#pragma unroll
            for (int j = 0; j < 8; j++) {
                int cl = wn * 64 + j * 8 + tg * 2;
                float b0 = sbias[cl], b1 = sbias[cl + 1];
                float v0 = acc[i][j][0] + b0, v1 = acc[i][j][1] + b1;
                float v2 = acc[i][j][2] + b0, v3 = acc[i][j][3] + b1;
                if (ACT == 1) {
                    v0 = fmaxf(v0, 0.f); v1 = fmaxf(v1, 0.f);
                    v2 = fmaxf(v2, 0.f); v3 = fmaxf(v3, 0.f);
                }
                ut[rl * 129 + cl]       = v0;
                ut[rl * 129 + cl + 1]   = v1;
                ut[(rl + 8) * 129 + cl]     = v2;
                ut[(rl + 8) * 129 + cl + 1] = v3;
            }
        }
        __shared__ float w2s[128 * 16];
        for (int i = tid; i < 128 * 16 / 4; i += 256)
            ((float4*)w2s)[i] = ((const float4*)(W2 + (size_t)n0 * 16))[i];
        __syncthreads();

        const int row = tid >> 1;
        const int off = (tid & 1) * 8;
        const int gr = m0 + row;
        if (gr < M) {
            float o[8];
#pragma unroll
            for (int j = 0; j < 8; j++) o[j] = 0.f;
#pragma unroll 4
            for (int c = 0; c < 128; c++) {
                float uv = ut[row * 129 + c];
                const float* wr = &w2s[c * 16 + off];
#pragma unroll
                for (int j = 0; j < 8; j++) o[j] += uv * wr[j];
            }
            float* pp = Pout + (size_t)gr * 16 + off;
#pragma unroll
            for (int j = 0; j < 8; j++) atomicAdd(&pp[j], o[j]);
        }
    }
}

// ---------------- final: out = tanh(partial + b2) ----------------
__global__ __launch_bounds__(256) void tanh_kernel(const float* __restrict__ pout,
                                                   const float* __restrict__ b2,
                                                   float* __restrict__ out) {
    __shared__ float bs[16];
    if (threadIdx.x < 16) bs[threadIdx.x] = b2[threadIdx.x];
    __syncthreads();
    int idx = blockIdx.x * 256 + threadIdx.x;   // float4 index
    if (idx < NN * 4) {
        float4 v = ((const float4*)pout)[idx];
        int jb = (idx & 3) * 4;
        v.x = tanhf(v.x + bs[jb]);
        v.y = tanhf(v.y + bs[jb + 1]);
        v.z = tanhf(v.z + bs[jb + 2]);
        v.w = tanhf(v.w + bs[jb + 3]);
        ((float4*)out)[idx] = v;
    }
}

// ---------------- CSR build ----------------
__global__ void count_kernel(const int* __restrict__ dst, int* __restrict__ cnt) {
    int e = blockIdx.x * blockDim.x + threadIdx.x;
    if (e < NE) atomicAdd(&cnt[dst[e]], 1);
}

__global__ __launch_bounds__(1024) void scan_kernel(const int* __restrict__ cnt,
                                                    int* __restrict__ rowptr,
                                                    int* __restrict__ fill) {
    __shared__ int wsum[32];
    __shared__ int s_carry;
    const int tid = threadIdx.x, lane = tid & 31, wid = tid >> 5;
    if (tid == 0) { s_carry = 0; rowptr[0] = 0; }
    __syncthreads();
    for (int base = 0; base < NN; base += 1024) {
        int i = base + tid;
        int v = (i < NN) ? cnt[i] : 0;
        int s = v;
#pragma unroll
        for (int d = 1; d < 32; d <<= 1) {
            int y = __shfl_up_sync(0xffffffffu, s, d);
            if (lane >= d) s += y;
        }
        if (lane == 31) wsum[wid] = s;
        int carry_in = s_carry;
        __syncthreads();
        if (wid == 0) {
            int ws = wsum[lane];
#pragma unroll
            for (int d = 1; d < 32; d <<= 1) {
                int y = __shfl_up_sync(0xffffffffu, ws, d);
                if (lane >= d) ws += y;
            }
            wsum[lane] = ws;
        }
        __syncthreads();
        int off = (wid ? wsum[wid - 1] : 0) + carry_in;
        int inc = s + off;
        if (i < NN) {
            rowptr[i + 1] = inc;
            fill[i] = inc - v;
        }
        __syncthreads();
        if (tid == 1023) s_carry = inc;
        __syncthreads();
    }
}

__global__ void scatter_kernel(const int* __restrict__ src, const int* __restrict__ dst,
                               int* __restrict__ fill, int* __restrict__ col) {
    int e = blockIdx.x * blockDim.x + threadIdx.x;
    if (e < NE) {
        int slot = atomicAdd(&fill[dst[e]], 1);
        col[slot] = src[e];
    }
}

// ---------------- aggregation — fp16 in, fp16 out (4 nodes/block, 1 warp each) -------
__device__ __forceinline__ void acc8h(float* acc, uint4 hv) {
    const uint32_t* h = (const uint32_t*)&hv;
#pragma unroll
    for (int p = 0; p < 4; p++) {
        float2 f = __half22float2(*reinterpret_cast<const __half2*>(&h[p]));
        acc[2 * p]     += f.x;
        acc[2 * p + 1] += f.y;
    }
}

__global__ __launch_bounds__(128) void agg_kernel(
    const __half* __restrict__ t,
    const int* __restrict__ rowptr, const int* __restrict__ col,
    __half* __restrict__ agg)
{
    const int node = blockIdx.x * 4 + (threadIdx.x >> 5);
    if (node >= NN) return;
    const int tid = threadIdx.x & 31;
    const int s = rowptr[node];
    const int e = rowptr[node + 1];
    float acc[8];
#pragma unroll
    for (int p = 0; p < 8; p++) acc[p] = 0.f;

    int i = s;
    for (; i + 4 <= e; i += 4) {
        int c0 = __ldg(&col[i]),     c1 = __ldg(&col[i + 1]);
        int c2 = __ldg(&col[i + 2]), c3 = __ldg(&col[i + 3]);
        uint4 h0 = *(const uint4*)(t + (size_t)c0 * HID + tid * 8);
        uint4 h1 = *(const uint4*)(t + (size_t)c1 * HID + tid * 8);
        uint4 h2 = *(const uint4*)(t + (size_t)c2 * HID + tid * 8);
        uint4 h3 = *(const uint4*)(t + (size_t)c3 * HID + tid * 8);
        acc8h(acc, h0); acc8h(acc, h1);
        acc8h(acc, h2); acc8h(acc, h3);
    }
    for (; i < e; i++) {
        int c0 = __ldg(&col[i]);
        uint4 h0 = *(const uint4*)(t + (size_t)c0 * HID + tid * 8);
        acc8h(acc, h0);
    }

    uint32_t hw[4];
#pragma unroll
    for (int p = 0; p < 4; p++) hw[p] = pack_f16x2(acc[2 * p], acc[2 * p + 1]);
    *(uint4*)(agg + (size_t)node * HID + tid * 8) = *(uint4*)hw;
}

// ---------------- launcher ----------------
extern "C" void kernel_launch(void* const* d_in, const int* in_sizes, int n_in,
                              void* d_out, int out_size) {
    const float* x       = (const float*)d_in[0];
    const int*   ei      = (const int*)d_in[1];
    const float* pre_w1  = (const float*)d_in[2];
    const float* pre_b1  = (const float*)d_in[3];
    const float* pre_w2  = (const float*)d_in[4];
    const float* pre_b2  = (const float*)d_in[5];
    const float* conv_w  = (const float*)d_in[6];
    const float* conv_b  = (const float*)d_in[7];
    const float* post_w1 = (const float*)d_in[8];
    const float* post_b1 = (const float*)d_in[9];
    const float* post_w2 = (const float*)d_in[10];
    const float* post_b2 = (const float*)d_in[11];
    float* out = (float*)d_out;

    const int* src = ei;
    const int* dst = ei + NE;

    __half *a, *t, *gg;
    float* pout;
    int *cnt, *rowptr, *fill, *col;
    float *cbt, *cbu;
    __half *wth, *wtl, *wuh, *wul;
    cudaGetSymbolAddress((void**)&a, g_a);
    cudaGetSymbolAddress((void**)&t, g_t);     cudaGetSymbolAddress((void**)&gg, g_g);
    cudaGetSymbolAddress((void**)&pout, g_pout);
    cudaGetSymbolAddress((void**)&cnt, g_cnt);
    cudaGetSymbolAddress((void**)&rowptr, g_rowptr);
    cudaGetSymbolAddress((void**)&fill, g_fill);
    cudaGetSymbolAddress((void**)&col, g_col);
    cudaGetSymbolAddress((void**)&cbt, g_cbt); cudaGetSymbolAddress((void**)&cbu, g_cbu);
    cudaGetSymbolAddress((void**)&wth, g_wth); cudaGetSymbolAddress((void**)&wtl, g_wtl);
    cudaGetSymbolAddress((void**)&wuh, g_wuh); cudaGetSymbolAddress((void**)&wul, g_wul);

    const float* P1 = post_w1;                 // rows 0..255 of [512][256]
    const float* P2 = post_w1 + 256 * 256;     // rows 256..511

    // DSMEM must cover both the 2-stage pipeline (2*30720=61440) and the
    // u-tile park (128*129*4 = 66048).
    const int DSMEM = 66560;
    cudaFuncSetAttribute(mma_gemm<1, 2, 1>, cudaFuncAttributeMaxDynamicSharedMemorySize, DSMEM);
    cudaFuncSetAttribute(mma_gemm<1, 3, 0>, cudaFuncAttributeMaxDynamicSharedMemorySize, DSMEM);

    const int MT = (NN + 127) / 128;  // 391
    dim3 gg2(2, MT);

    // (1) t-weights + t-bias (fp16 hi/lo)
    compose_prep<<<dim3(4, 5), 256>>>(pre_w2, conv_w, wth, wtl, 256, 0,
                                      pre_b2, conv_b, cbt);
    // (2) pre-MLP layer 1 -> single fp16 a
    pre_kernel<<<(NN + 31) / 32, 256>>>(x, pre_w1, pre_b1, a);
    // (3) u-weights a-part + u-bias (hi plane = fp16-rounded weight)
    compose_prep<<<dim3(4, 5), 256>>>(pre_w2, P1, wuh, wul, 512, 0,
                                      pre_b2, post_b1, cbu);
    // (4) u-weights agg-part
    prep2h<<<dim3(8, 8), dim3(32, 8)>>>(P2, wuh, wul, 512, 256);
    // (5) t = relu(a@Wt + bt) -> single fp16   (2-pass exact weights)
    mma_gemm<1, 2, 1><<<gg2, 256, DSMEM>>>(a, nullptr, wth, wtl, cbt,
                                           t, nullptr, nullptr, NN, 256, 256);

    // ---- CSR build + atomic-free segment sum ----
    cudaMemsetAsync(cnt, 0, NN * sizeof(int), 0);
    cudaMemsetAsync(pout, 0, (size_t)NN * 16 * sizeof(float), 0);
    count_kernel<<<(NE + 255) / 256, 256>>>(dst, cnt);
    scan_kernel<<<1, 1024>>>(cnt, rowptr, fill);
    scatter_kernel<<<(NE + 255) / 256, 256>>>(src, dst, fill, col);
    agg_kernel<<<(NN + 3) / 4, 128>>>(t, rowptr, col, gg);

    // ---- u = relu(a@Wp + agg@P2 + bu), 1-pass fp16 weights, fused out-projection ----
    mma_gemm<1, 3, 0><<<gg2, 256, DSMEM>>>(a, gg, wuh, nullptr, cbu,
                                           nullptr, post_w2, pout, NN, 512, 256);
    // ---- out = tanh(pout + b2) ----
    tanh_kernel<<<(NN * 4 + 255) / 256, 256>>>(pout, post_b2, out);
}

// round 17
// speedup vs baseline: 1.9139x; 1.0656x over previous
#include <cuda_runtime.h>
#include <cuda_bf16.h>
#include <cuda_fp16.h>
#include <cstdint>
#include <cstddef>

#define NN 50000
#define NE 800000
#define HID 256

// smem stage layout (bytes, pitch 80/row of 32 halfwords + pad):
// A[128x80]=10240 | B_hi[128x80]=10240 | B_lo[128x80]=10240 (B_lo unused when WLO=0)
#define STAGE_B 30720

// ---------------- scratch (device globals: no allocation allowed) ----------------
__device__ __half g_a[(size_t)NN * HID];                        // single fp16 a
__device__ __half g_t[(size_t)NN * HID];                        // single fp16 t
__device__ __half g_g[(size_t)NN * HID];                        // single fp16 agg
__device__ float g_pout[(size_t)NN * 16];                       // fp32 out partials
__device__ int g_cnt[NN];
__device__ int g_rowptr[NN + 1];
__device__ int g_fill[NN];
__device__ int g_col[NE];
__device__ float g_cbt[256];         // b2@Wc + conv_b
__device__ float g_cbu[256];         // b2@P1 + post_b1
__device__ __half g_wth[256 * 256], g_wtl[256 * 256];           // t-GEMM weights fp16 hi(/lo unused)
__device__ __half g_wuh[256 * 512], g_wul[256 * 512];           // u-GEMM weights fp16 hi(/lo unused)

// ---------------- helpers ----------------
__device__ __forceinline__ uint32_t s2u(const void* p) {
    uint32_t a;
    asm("{ .reg .u64 t; cvta.to.shared.u64 t, %1; cvt.u32.u64 %0, t; }" : "=r"(a) : "l"(p));
    return a;
}
__device__ __forceinline__ void cp16(uint32_t dst, const void* src, int srcsz) {
    asm volatile("cp.async.cg.shared.global [%0], [%1], 16, %2;"
                 :: "r"(dst), "l"(src), "r"(srcsz) : "memory");
}
#define CP_COMMIT() asm volatile("cp.async.commit_group;" ::: "memory")

__device__ __forceinline__ void ldsm4(uint32_t& r0, uint32_t& r1, uint32_t& r2, uint32_t& r3,
                                      uint32_t addr) {
    asm volatile("ldmatrix.sync.aligned.m8n8.x4.shared.b16 {%0,%1,%2,%3}, [%4];"
                 : "=r"(r0), "=r"(r1), "=r"(r2), "=r"(r3) : "r"(addr));
}

#define MMA_F16(cc, aa, b0v, b1v)                                               \
    asm volatile(                                                               \
        "mma.sync.aligned.m16n8k16.row.col.f32.f16.f16.f32 "                    \
        "{%0,%1,%2,%3}, {%4,%5,%6,%7}, {%8,%9}, {%0,%1,%2,%3};"                 \
        : "+f"(cc[0]), "+f"(cc[1]), "+f"(cc[2]), "+f"(cc[3])                    \
        : "r"(aa[0]), "r"(aa[1]), "r"(aa[2]), "r"(aa[3]), "r"(b0v), "r"(b1v))

__device__ __forceinline__ uint32_t pack_f16x2(float a, float b) {
    __half2 p = __float22half2_rn(make_float2(a, b));
    return *reinterpret_cast<uint32_t*>(&p);
}

// ---------------- fused compose+prep+bias (fp16 hi/lo out) ----------------
__global__ __launch_bounds__(256) void compose_prep(
    const float* __restrict__ A, const float* __restrict__ B,
    __half* __restrict__ hi, __half* __restrict__ lo,
    int kpitch, int koff,
    const float* __restrict__ b2, const float* __restrict__ badd,
    float* __restrict__ bout)
{
    const int t = threadIdx.x;
    if (blockIdx.y == 4) {
        __shared__ float red[4][64];
        int j = blockIdx.x * 64 + (t & 63);
        int ks = t >> 6;
        float acc = 0.f;
#pragma unroll 8
        for (int k = ks * 64; k < ks * 64 + 64; k++)
            acc += b2[k] * B[(size_t)k * 256 + j];
        red[ks][t & 63] = acc;
        __syncthreads();
        if (t < 64) {
            int jj = blockIdx.x * 64 + t;
            bout[jj] = red[0][t] + red[1][t] + red[2][t] + red[3][t] + badd[jj];
        }
        return;
    }

    __shared__ float As[16][64];
    __shared__ float Bs[16][64];
    const int tx = t & 15, ty = t >> 4;
    const int m0 = blockIdx.y * 64, n0 = blockIdx.x * 64;
    float acc[4][4];
#pragma unroll
    for (int i = 0; i < 4; i++)
#pragma unroll
        for (int j = 0; j < 4; j++) acc[i][j] = 0.f;

    for (int k0 = 0; k0 < 256; k0 += 16) {
#pragma unroll
        for (int i = 0; i < 4; i++) {
            int idx = t + i * 256;
            int r = idx >> 4, c = idx & 15;
            As[c][r] = A[(size_t)(m0 + r) * 256 + k0 + c];
        }
#pragma unroll
        for (int i = 0; i < 4; i++) {
            int idx = t + i * 256;
            int r = idx >> 6, c = idx & 63;
            Bs[r][c] = B[(size_t)(k0 + r) * 256 + n0 + c];
        }
        __syncthreads();
#pragma unroll
        for (int k = 0; k < 16; k++) {
            float ra[4], rb[4];
#pragma unroll
            for (int i = 0; i < 4; i++) ra[i] = As[k][ty * 4 + i];
#pragma unroll
            for (int j = 0; j < 4; j++) rb[j] = Bs[k][tx * 4 + j];
#pragma unroll
            for (int i = 0; i < 4; i++)
#pragma unroll
                for (int j = 0; j < 4; j++) acc[i][j] += ra[i] * rb[j];
        }
        __syncthreads();
    }
#pragma unroll
    for (int i = 0; i < 4; i++) {
        int kk = m0 + ty * 4 + i;
#pragma unroll
        for (int j = 0; j < 4; j++) {
            int nn = n0 + tx * 4 + j;
            float v = acc[i][j];
            __half h = __float2half_rn(v);
            hi[(size_t)nn * kpitch + koff + kk] = h;
            lo[(size_t)nn * kpitch + koff + kk] = __float2half_rn(v - __half2float(h));
        }
    }
}

// ---------------- prep for P2: transpose + fp16 hi/lo split ----------------
__global__ void prep2h(const float* __restrict__ W, __half* __restrict__ hi,
                       __half* __restrict__ lo, int kpitch, int koff) {
    __shared__ float tile[32][33];
    int k0 = blockIdx.y * 32, n0 = blockIdx.x * 32;
    int tx = threadIdx.x, ty = threadIdx.y;  // 32 x 8
    for (int i = ty; i < 32; i += 8) tile[i][tx] = W[(size_t)(k0 + i) * 256 + n0 + tx];
    __syncthreads();
    for (int i = ty; i < 32; i += 8) {
        float v = tile[tx][i];
        __half h = __float2half_rn(v);
        hi[(size_t)(n0 + i) * kpitch + koff + k0 + tx] = h;
        lo[(size_t)(n0 + i) * kpitch + koff + k0 + tx] =
            __float2half_rn(v - __half2float(h));
    }
}

// ---------------- pre-MLP layer 1: a = relu(x@w1+b1), K=16, single fp16 out ----------
__global__ __launch_bounds__(256) void pre_kernel(
    const float* __restrict__ x, const float* __restrict__ w1, const float* __restrict__ b1,
    __half* __restrict__ C)
{
    __shared__ float ws[16 * 256];
    __shared__ float bs[256];
    const int tid = threadIdx.x;
    for (int i = tid; i < 1024; i += 256) ((float4*)ws)[i] = ((const float4*)w1)[i];
    bs[tid] = b1[tid];
    __syncthreads();

    const int warp = tid >> 5, lane = tid & 31;
#pragma unroll
    for (int r = 0; r < 4; r++) {
        int row = blockIdx.x * 32 + warp * 4 + r;
        if (row >= NN) break;
        float xv[16];
        const float4* xp = (const float4*)(x + (size_t)row * 16);
#pragma unroll
        for (int q = 0; q < 4; q++) *(float4*)&xv[q * 4] = xp[q];
        float acc[8];
#pragma unroll
        for (int j = 0; j < 8; j++) acc[j] = bs[lane + 32 * j];
#pragma unroll
        for (int k = 0; k < 16; k++) {
            float xk = xv[k];
            const float* wr = &ws[k * 256 + lane];
#pragma unroll
            for (int j = 0; j < 8; j++) acc[j] += xk * wr[32 * j];
        }
#pragma unroll
        for (int j = 0; j < 8; j++) {
            float v = fmaxf(acc[j], 0.f);
            C[(size_t)row * 256 + lane + 32 * j] = __float2half_rn(v);
        }
    }
}

// ---------------- tensor-core GEMM: all-fp16 ----------------
// WLO=1: 2-pass (W hi + W lo).  WLO=0: 1-pass (single fp16 W).
// OUTMODE 2: fp16 out (t).  OUTMODE 3: fused out-projection -> atomic fp32 partials.
template <int ACT, int OUTMODE, int WLO>
__global__ __launch_bounds__(256, 2) void mma_gemm(
    const __half* __restrict__ A1, const __half* __restrict__ A2,
    const __half* __restrict__ Wh, const __half* __restrict__ Wl,
    const float* __restrict__ bias,
    __half* __restrict__ Chf,
    const float* __restrict__ W2, float* __restrict__ Pout,
    int M, int K, int K1)
{
    extern __shared__ char smc[];
    __shared__ float sbias[128];

    const int tid = threadIdx.x;
    const int wid = tid >> 5, lane = tid & 31;
    const int g = lane >> 2, tg = lane & 3;
    const int wm = wid >> 1, wn = wid & 1;
    const int m0 = blockIdx.y * 128, n0 = blockIdx.x * 128;
    const uint32_t smc_u = s2u(smc);

    if (tid < 128) sbias[tid] = bias[n0 + tid];

    const int arow = tid >> 1;
    const int aks  = (tid & 1) * 16;
    const int gm   = m0 + arow;
    const int okA  = (gm < M) ? 16 : 0;

    const int q = lane >> 3, rr = lane & 7;
    const uint32_t aoff0 = (uint32_t)((wm * 32 + (q & 1) * 8 + rr) * 80 + (q >> 1) * 16);
    const uint32_t boff0 = (uint32_t)(10240 + (wn * 64 + (q >> 1) * 8 + rr) * 80 + (q & 1) * 16);

    float acc[2][8][4];
#pragma unroll
    for (int i = 0; i < 2; i++)
#pragma unroll
        for (int j = 0; j < 8; j++)
#pragma unroll
            for (int p = 0; p < 4; p++) acc[i][j][p] = 0.f;

    const int NC = K >> 5;

    auto STAGE = [&](int c) {
        const int ck = c * 32;
        const uint32_t sb = smc_u + (uint32_t)((c & 1) * STAGE_B);
        const uint32_t da = sb + (uint32_t)(arow * 80 + (tid & 1) * 32);
        const __half* pa = (ck < K1) ? (A1 + (size_t)gm * K1 + ck + aks)
                                     : (A2 + (size_t)gm * (K - K1) + (ck - K1) + aks);
        cp16(da, pa, okA);                cp16(da + 16, pa + 8, okA);
        const __half* pbh = Wh + (size_t)(n0 + arow) * K + ck + aks;
        cp16(da + 10240, pbh, 16);        cp16(da + 10240 + 16, pbh + 8, 16);
        if (WLO) {
            const __half* pbl = Wl + (size_t)(n0 + arow) * K + ck + aks;
            cp16(da + 20480, pbl, 16);    cp16(da + 20480 + 16, pbl + 8, 16);
        }
        CP_COMMIT();
    };

    STAGE(0);

    for (int c = 0; c < NC; c++) {
        if (c + 1 < NC) {
            STAGE(c + 1);
            asm volatile("cp.async.wait_group 1;" ::: "memory");
        } else {
            asm volatile("cp.async.wait_group 0;" ::: "memory");
        }
        __syncthreads();

        const uint32_t sb = smc_u + (uint32_t)((c & 1) * STAGE_B);
#pragma unroll
        for (int ks = 0; ks < 2; ks++) {
            const uint32_t ko = (uint32_t)(ks * 32);
            uint32_t ah[2][4], bb[8][2];
            ldsm4(ah[0][0], ah[0][1], ah[0][2], ah[0][3], sb + aoff0 + ko);
            ldsm4(ah[1][0], ah[1][1], ah[1][2], ah[1][3], sb + aoff0 + 1280 + ko);
#pragma unroll
            for (int jp = 0; jp < 4; jp++)
                ldsm4(bb[2 * jp][0], bb[2 * jp][1], bb[2 * jp + 1][0], bb[2 * jp + 1][1],
                      sb + boff0 + (uint32_t)(jp * 1280) + ko);
#pragma unroll
            for (int i = 0; i < 2; i++)
#pragma unroll
                for (int j = 0; j < 8; j++) MMA_F16(acc[i][j], ah[i], bb[j][0], bb[j][1]);

            if (WLO) {
#pragma unroll
                for (int jp = 0; jp < 4; jp++)
                    ldsm4(bb[2 * jp][0], bb[2 * jp][1], bb[2 * jp + 1][0], bb[2 * jp + 1][1],
                          sb + 10240 + boff0 + (uint32_t)(jp * 1280) + ko);
#pragma unroll
                for (int i = 0; i < 2; i++)
#pragma unroll
                    for (int j = 0; j < 8; j++) MMA_F16(acc[i][j], ah[i], bb[j][0], bb[j][1]);
            }
        }
        __syncthreads();
    }

    if (OUTMODE == 2) {
#pragma unroll
        for (int i = 0; i < 2; i++) {
            int r0 = m0 + wm * 32 + i * 16 + g;
#pragma unroll
            for (int j = 0; j < 8; j++) {
                int cl = wn * 64 + j * 8 + tg * 2;
                float b0 = sbias[cl], b1 = sbias[cl + 1];
                float v0 = acc[i][j][0] + b0, v1 = acc[i][j][1] + b1;
                float v2 = acc[i][j][2] + b0, v3 = acc[i][j][3] + b1;
                if (ACT == 1) {
                    v0 = fmaxf(v0, 0.f); v1 = fmaxf(v1, 0.f);
                    v2 = fmaxf(v2, 0.f); v3 = fmaxf(v3, 0.f);
                }
                if (r0 < M)
                    *(uint32_t*)(Chf + (size_t)r0 * 256 + n0 + cl) = pack_f16x2(v0, v1);
                if (r0 + 8 < M)
                    *(uint32_t*)(Chf + (size_t)(r0 + 8) * 256 + n0 + cl) = pack_f16x2(v2, v3);
            }
        }
    } else {
        // u path: park u-tile in smem (fp32, pitch 129), then fused out-projection
        float* ut = (float*)smc;
#pragma unroll
        for (int i = 0; i < 2; i++) {
            int rl = wm * 32 + i * 16 + g;
#pragma unroll
            for (int j = 0; j < 8; j++) {
                int cl = wn * 64 + j * 8 + tg * 2;
                float b0 = sbias[cl], b1 = sbias[cl + 1];
                float v0 = acc[i][j][0] + b0, v1 = acc[i][j][1] + b1;
                float v2 = acc[i][j][2] + b0, v3 = acc[i][j][3] + b1;
                if (ACT == 1) {
                    v0 = fmaxf(v0, 0.f); v1 = fmaxf(v1, 0.f);
                    v2 = fmaxf(v2, 0.f); v3 = fmaxf(v3, 0.f);
                }
                ut[rl * 129 + cl]       = v0;
                ut[rl * 129 + cl + 1]   = v1;
                ut[(rl + 8) * 129 + cl]     = v2;
                ut[(rl + 8) * 129 + cl + 1] = v3;
            }
        }
        __shared__ float w2s[128 * 16];
        for (int i = tid; i < 128 * 16 / 4; i += 256)
            ((float4*)w2s)[i] = ((const float4*)(W2 + (size_t)n0 * 16))[i];
        __syncthreads();

        const int row = tid >> 1;
        const int off = (tid & 1) * 8;
        const int gr = m0 + row;
        if (gr < M) {
            float o[8];
#pragma unroll
            for (int j = 0; j < 8; j++) o[j] = 0.f;
#pragma unroll 4
            for (int c = 0; c < 128; c++) {
                float uv = ut[row * 129 + c];
                const float* wr = &w2s[c * 16 + off];
#pragma unroll
                for (int j = 0; j < 8; j++) o[j] += uv * wr[j];
            }
            float* pp = Pout + (size_t)gr * 16 + off;
#pragma unroll
            for (int j = 0; j < 8; j++) atomicAdd(&pp[j], o[j]);
        }
    }
}

// ---------------- final: out = tanh(partial + b2) ----------------
__global__ __launch_bounds__(256) void tanh_kernel(const float* __restrict__ pout,
                                                   const float* __restrict__ b2,
                                                   float* __restrict__ out) {
    __shared__ float bs[16];
    if (threadIdx.x < 16) bs[threadIdx.x] = b2[threadIdx.x];
    __syncthreads();
    int idx = blockIdx.x * 256 + threadIdx.x;   // float4 index
    if (idx < NN * 4) {
        float4 v = ((const float4*)pout)[idx];
        int jb = (idx & 3) * 4;
        v.x = tanhf(v.x + bs[jb]);
        v.y = tanhf(v.y + bs[jb + 1]);
        v.z = tanhf(v.z + bs[jb + 2]);
        v.w = tanhf(v.w + bs[jb + 3]);
        ((float4*)out)[idx] = v;
    }
}

// ---------------- CSR build ----------------
__global__ void count_kernel(const int* __restrict__ dst, int* __restrict__ cnt) {
    int e = blockIdx.x * blockDim.x + threadIdx.x;
    if (e < NE) atomicAdd(&cnt[dst[e]], 1);
}

__global__ __launch_bounds__(1024) void scan_kernel(const int* __restrict__ cnt,
                                                    int* __restrict__ rowptr,
                                                    int* __restrict__ fill) {
    __shared__ int wsum[32];
    __shared__ int s_carry;
    const int tid = threadIdx.x, lane = tid & 31, wid = tid >> 5;
    if (tid == 0) { s_carry = 0; rowptr[0] = 0; }
    __syncthreads();
    for (int base = 0; base < NN; base += 1024) {
        int i = base + tid;
        int v = (i < NN) ? cnt[i] : 0;
        int s = v;
#pragma unroll
        for (int d = 1; d < 32; d <<= 1) {
            int y = __shfl_up_sync(0xffffffffu, s, d);
            if (lane >= d) s += y;
        }
        if (lane == 31) wsum[wid] = s;
        int carry_in = s_carry;
        __syncthreads();
        if (wid == 0) {
            int ws = wsum[lane];
#pragma unroll
            for (int d = 1; d < 32; d <<= 1) {
                int y = __shfl_up_sync(0xffffffffu, ws, d);
                if (lane >= d) ws += y;
            }
            wsum[lane] = ws;
        }
        __syncthreads();
        int off = (wid ? wsum[wid - 1] : 0) + carry_in;
        int inc = s + off;
        if (i < NN) {
            rowptr[i + 1] = inc;
            fill[i] = inc - v;
        }
        __syncthreads();
        if (tid == 1023) s_carry = inc;
        __syncthreads();
    }
}

__global__ void scatter_kernel(const int* __restrict__ src, const int* __restrict__ dst,
                               int* __restrict__ fill, int* __restrict__ col) {
    int e = blockIdx.x * blockDim.x + threadIdx.x;
    if (e < NE) {
        int slot = atomicAdd(&fill[dst[e]], 1);
        col[slot] = src[e];
    }
}

// ---------------- aggregation — fp16 in, fp16 out (4 nodes/block, 1 warp each) -------
__device__ __forceinline__ void acc8h(float* acc, uint4 hv) {
    const uint32_t* h = (const uint32_t*)&hv;
#pragma unroll
    for (int p = 0; p < 4; p++) {
        float2 f = __half22float2(*reinterpret_cast<const __half2*>(&h[p]));
        acc[2 * p]     += f.x;
        acc[2 * p + 1] += f.y;
    }
}

__global__ __launch_bounds__(128) void agg_kernel(
    const __half* __restrict__ t,
    const int* __restrict__ rowptr, const int* __restrict__ col,
    __half* __restrict__ agg)
{
    const int node = blockIdx.x * 4 + (threadIdx.x >> 5);
    if (node >= NN) return;
    const int tid = threadIdx.x & 31;
    const int s = rowptr[node];
    const int e = rowptr[node + 1];
    float acc[8];
#pragma unroll
    for (int p = 0; p < 8; p++) acc[p] = 0.f;

    int i = s;
    for (; i + 4 <= e; i += 4) {
        int c0 = __ldg(&col[i]),     c1 = __ldg(&col[i + 1]);
        int c2 = __ldg(&col[i + 2]), c3 = __ldg(&col[i + 3]);
        uint4 h0 = *(const uint4*)(t + (size_t)c0 * HID + tid * 8);
        uint4 h1 = *(const uint4*)(t + (size_t)c1 * HID + tid * 8);
        uint4 h2 = *(const uint4*)(t + (size_t)c2 * HID + tid * 8);
        uint4 h3 = *(const uint4*)(t + (size_t)c3 * HID + tid * 8);
        acc8h(acc, h0); acc8h(acc, h1);
        acc8h(acc, h2); acc8h(acc, h3);
    }
    for (; i < e; i++) {
        int c0 = __ldg(&col[i]);
        uint4 h0 = *(const uint4*)(t + (size_t)c0 * HID + tid * 8);
        acc8h(acc, h0);
    }

    uint32_t hw[4];
#pragma unroll
    for (int p = 0; p < 4; p++) hw[p] = pack_f16x2(acc[2 * p], acc[2 * p + 1]);
    *(uint4*)(agg + (size_t)node * HID + tid * 8) = *(uint4*)hw;
}

// ---------------- launcher ----------------
extern "C" void kernel_launch(void* const* d_in, const int* in_sizes, int n_in,
                              void* d_out, int out_size) {
    const float* x       = (const float*)d_in[0];
    const int*   ei      = (const int*)d_in[1];
    const float* pre_w1  = (const float*)d_in[2];
    const float* pre_b1  = (const float*)d_in[3];
    const float* pre_w2  = (const float*)d_in[4];
    const float* pre_b2  = (const float*)d_in[5];
    const float* conv_w  = (const float*)d_in[6];
    const float* conv_b  = (const float*)d_in[7];
    const float* post_w1 = (const float*)d_in[8];
    const float* post_b1 = (const float*)d_in[9];
    const float* post_w2 = (const float*)d_in[10];
    const float* post_b2 = (const float*)d_in[11];
    float* out = (float*)d_out;

    const int* src = ei;
    const int* dst = ei + NE;

    __half *a, *t, *gg;
    float* pout;
    int *cnt, *rowptr, *fill, *col;
    float *cbt, *cbu;
    __half *wth, *wtl, *wuh, *wul;
    cudaGetSymbolAddress((void**)&a, g_a);
    cudaGetSymbolAddress((void**)&t, g_t);     cudaGetSymbolAddress((void**)&gg, g_g);
    cudaGetSymbolAddress((void**)&pout, g_pout);
    cudaGetSymbolAddress((void**)&cnt, g_cnt);
    cudaGetSymbolAddress((void**)&rowptr, g_rowptr);
    cudaGetSymbolAddress((void**)&fill, g_fill);
    cudaGetSymbolAddress((void**)&col, g_col);
    cudaGetSymbolAddress((void**)&cbt, g_cbt); cudaGetSymbolAddress((void**)&cbu, g_cbu);
    cudaGetSymbolAddress((void**)&wth, g_wth); cudaGetSymbolAddress((void**)&wtl, g_wtl);
    cudaGetSymbolAddress((void**)&wuh, g_wuh); cudaGetSymbolAddress((void**)&wul, g_wul);

    const float* P1 = post_w1;                 // rows 0..255 of [512][256]
    const float* P2 = post_w1 + 256 * 256;     // rows 256..511

    // DSMEM must cover both the 2-stage pipeline (2*30720=61440) and the
    // u-tile park (128*129*4 = 66048).
    const int DSMEM = 66560;
    cudaFuncSetAttribute(mma_gemm<1, 2, 0>, cudaFuncAttributeMaxDynamicSharedMemorySize, DSMEM);
    cudaFuncSetAttribute(mma_gemm<1, 3, 0>, cudaFuncAttributeMaxDynamicSharedMemorySize, DSMEM);

    const int MT = (NN + 127) / 128;  // 391
    dim3 gg2(2, MT);

    // (1) t-weights + t-bias (hi plane = fp16-rounded weight)
    compose_prep<<<dim3(4, 5), 256>>>(pre_w2, conv_w, wth, wtl, 256, 0,
                                      pre_b2, conv_b, cbt);
    // (2) pre-MLP layer 1 -> single fp16 a
    pre_kernel<<<(NN + 31) / 32, 256>>>(x, pre_w1, pre_b1, a);
    // (3) u-weights a-part + u-bias
    compose_prep<<<dim3(4, 5), 256>>>(pre_w2, P1, wuh, wul, 512, 0,
                                      pre_b2, post_b1, cbu);
    // (4) u-weights agg-part
    prep2h<<<dim3(8, 8), dim3(32, 8)>>>(P2, wuh, wul, 512, 256);
    // (5) t = relu(a@Wt + bt) -> single fp16   (1-pass fp16 weights)
    mma_gemm<1, 2, 0><<<gg2, 256, DSMEM>>>(a, nullptr, wth, nullptr, cbt,
                                           t, nullptr, nullptr, NN, 256, 256);

    // ---- CSR build + atomic-free segment sum ----
    cudaMemsetAsync(cnt, 0, NN * sizeof(int), 0);
    cudaMemsetAsync(pout, 0, (size_t)NN * 16 * sizeof(float), 0);
    count_kernel<<<(NE + 255) / 256, 256>>>(dst, cnt);
    scan_kernel<<<1, 1024>>>(cnt, rowptr, fill);
    scatter_kernel<<<(NE + 255) / 256, 256>>>(src, dst, fill, col);
    agg_kernel<<<(NN + 3) / 4, 128>>>(t, rowptr, col, gg);

    // ---- u = relu(a@Wp + agg@P2 + bu), 1-pass fp16 weights, fused out-projection ----
    mma_gemm<1, 3, 0><<<gg2, 256, DSMEM>>>(a, gg, wuh, nullptr, cbu,
                                           nullptr, post_w2, pout, NN, 512, 256);
    // ---- out = tanh(pout + b2) ----
    tanh_kernel<<<(NN * 4 + 255) / 256, 256>>>(pout, post_b2, out);
}